// round 1
// baseline (speedup 1.0000x reference)
#include <cuda_runtime.h>
#include <math.h>

// ---------------------------------------------------------------------------
// CrossViewSwapAttention — fp32 baseline, full fusion into 16 kernels.
// B=2 N=6 H=W=64 FH=32 FW=88 DIM=128 HEADS=4 DH=32
// Stage1: q-win 8x8 (384 q tokens), kv-win 4x11 (264 kv tokens), 64 windows
// Stage2: q broadcast over cameras -> only 64 unique q tokens (mean over n of
//         identical outputs == output), kv grid-windows (dilated).
// ---------------------------------------------------------------------------

#define B_   2
#define N_   6
#define H_   64
#define W_   64
#define FH_  32
#define FW_  88
#define D_   128
#define NKV  264
#define NQ1  384

// scratch (device globals: no runtime allocation allowed)
__device__ float g_cembed[B_*N_*D_];
__device__ float g_kim[B_*N_*FH_*FW_*D_];   // (b,n,fh,fw,c)
__device__ float g_vim[B_*N_*FH_*FW_*D_];
__device__ float g_qim[B_*N_*H_*W_*D_];     // (b,n,h,w,c)
__device__ float g_qtok[B_*64*NQ1*D_];      // (b,l,t,c)
__device__ float g_ktok[B_*64*NKV*D_];
__device__ float g_vtok[B_*64*NKV*D_];
__device__ float g_otok[B_*64*NQ1*D_];
__device__ float g_q1[B_*H_*W_*D_];         // (b,h,w,c)
__device__ float g_q2[B_*H_*W_*D_];

__device__ __forceinline__ float blkSum128(float v, float* red) {
#pragma unroll
    for (int o = 16; o; o >>= 1) v += __shfl_xor_sync(0xffffffffu, v, o);
    if ((threadIdx.x & 31) == 0) red[threadIdx.x >> 5] = v;
    __syncthreads();
    float s = red[0] + red[1] + red[2] + red[3];
    __syncthreads();
    return s;
}

// ---------------- camera embedding:  c_embed = W_cam @ E_inv[...,-1] --------
__global__ void k_cembed(const float* __restrict__ E_inv,
                         const float* __restrict__ W_cam) {
    int bn = blockIdx.x, o = threadIdx.x;
    float acc = 0.f;
#pragma unroll
    for (int i = 0; i < 4; i++) acc += W_cam[o*4+i] * E_inv[bn*16 + i*4 + 3];
    g_cembed[bn*D_ + o] = acc;
}

// ---------------- key/val image features ------------------------------------
// key_im = normalize(W_img@(E_inv@[I_inv@plane;1]) - c_embed) + conv_fp(relu(bn(feat)))
// val_im = conv_fl(relu(bn(feat)))
__global__ void k_keyval(const float* __restrict__ feat,
                         const float* __restrict__ I_inv,
                         const float* __restrict__ E_inv,
                         const float* __restrict__ W_img,
                         const float* __restrict__ fp_g, const float* __restrict__ fp_b,
                         const float* __restrict__ W_fp,
                         const float* __restrict__ fl_g, const float* __restrict__ fl_b,
                         const float* __restrict__ W_fl) {
    int blk = blockIdx.x;
    int bn = blk / (FH_*FW_), p = blk % (FH_*FW_);
    int fh = p / FW_, fw = p % FW_;
    int tid = threadIdx.x;
    __shared__ float dd[4];
    __shared__ float sfp[D_], sfl[D_];
    __shared__ float red[4];
    if (tid == 0) {
        float px = (float)fw * (480.0f / 87.0f);
        float py = (float)fh * (224.0f / 31.0f);
        float cam[4];
#pragma unroll
        for (int i = 0; i < 3; i++)
            cam[i] = I_inv[bn*9+i*3+0]*px + I_inv[bn*9+i*3+1]*py + I_inv[bn*9+i*3+2];
        cam[3] = 1.0f;
#pragma unroll
        for (int i = 0; i < 4; i++) {
            float s = 0.f;
#pragma unroll
            for (int j = 0; j < 4; j++) s += E_inv[bn*16+i*4+j]*cam[j];
            dd[i] = s;
        }
    }
    float f = feat[(bn*D_ + tid)*(FH_*FW_) + p];
    const float invs = rsqrtf(1.0f + 1e-5f);
    sfp[tid] = fmaxf(f * invs * fp_g[tid] + fp_b[tid], 0.f);
    sfl[tid] = fmaxf(f * invs * fl_g[tid] + fl_b[tid], 0.f);
    __syncthreads();
    float de = W_img[tid*4+0]*dd[0] + W_img[tid*4+1]*dd[1]
             + W_img[tid*4+2]*dd[2] + W_img[tid*4+3]*dd[3];
    float t = de - g_cembed[bn*D_+tid];
    float ss = blkSum128(t*t, red);
    float img = t / fmaxf(sqrtf(ss), 1e-12f);
    const float4* wp4 = reinterpret_cast<const float4*>(W_fp + tid*D_);
    const float4* wl4 = reinterpret_cast<const float4*>(W_fl + tid*D_);
    float accp = 0.f, accl = 0.f;
#pragma unroll 8
    for (int c4 = 0; c4 < D_/4; c4++) {
        float4 wp = wp4[c4], wl = wl4[c4];
        accp += wp.x*sfp[c4*4+0] + wp.y*sfp[c4*4+1] + wp.z*sfp[c4*4+2] + wp.w*sfp[c4*4+3];
        accl += wl.x*sfl[c4*4+0] + wl.y*sfl[c4*4+1] + wl.z*sfl[c4*4+2] + wl.w*sfl[c4*4+3];
    }
    g_kim[blk*D_ + tid] = img + accp;
    g_vim[blk*D_ + tid] = accl;
}

// ---------------- query: normalize(W_bev@grid + b_bev - c_embed) + x --------
__global__ void k_query(const float* __restrict__ grid,
                        const float* __restrict__ x,
                        const float* __restrict__ W_bev,
                        const float* __restrict__ b_bev) {
    int blk = blockIdx.x;
    int bn = blk / (H_*W_), p = blk % (H_*W_);
    int b = bn / N_;
    int tid = threadIdx.x;
    __shared__ float red[4];
    float we = W_bev[tid*2+0]*grid[p] + W_bev[tid*2+1]*grid[H_*W_ + p] + b_bev[tid];
    float t = we - g_cembed[bn*D_+tid];
    float ss = blkSum128(t*t, red);
    float bev = t / fmaxf(sqrtf(ss), 1e-12f);
    g_qim[blk*D_+tid] = bev + x[(b*D_+tid)*(H_*W_) + p];
}

// ---------------- gather + LayerNorm + QKV projection ------------------------
// modes: 0=Q stage1 (win8x8, per camera), 1=K stage1 (win4x11), 2=V stage1,
//        3=Q stage2 (from q1, 64 tokens), 4=K stage2 (gridwin), 5=V stage2
__global__ void k_lnproj(int mode, int dst_sel,
                         const float* __restrict__ lg, const float* __restrict__ lb,
                         const float* __restrict__ W, const float* __restrict__ bias) {
    int idx = blockIdx.x, tid = threadIdx.x;
    const float* src;
    if (mode == 0) {
        int b = idx / (64*NQ1); int r = idx % (64*NQ1);
        int l = r / NQ1; int t = r % NQ1;
        int n = t >> 6; int ij = t & 63; int i = ij >> 3, j = ij & 7;
        int h = (l >> 3)*8 + i, w = (l & 7)*8 + j;
        src = g_qim + (((b*N_+n)*H_ + h)*W_ + w)*D_;
    } else if (mode == 3) {
        int b = idx / (64*64); int r = idx % (64*64);
        int l = r >> 6; int t = r & 63; int i = t >> 3, j = t & 7;
        int h = (l >> 3)*8 + i, w = (l & 7)*8 + j;
        src = g_q1 + ((b*H_+h)*W_+w)*D_;
    } else {
        int b = idx / (64*NKV); int r = idx % (64*NKV);
        int l = r / NKV; int t = r % NKV;
        int n = t / 44; int f = t % 44; int f1 = f / 11, f2 = f % 11;
        int h, w;
        if (mode <= 2) { h = (l >> 3)*4 + f1;  w = (l & 7)*11 + f2; }   // contiguous win
        else           { h = f1*8 + (l >> 3);  w = f2*8 + (l & 7); }    // grid (dilated) win
        const float* base = (mode == 1 || mode == 4) ? g_kim : g_vim;
        src = base + (((b*N_+n)*FH_ + h)*FW_ + w)*D_;
    }
    __shared__ float lnx[D_];
    __shared__ float red[4];
    float v = src[tid];
    float mean = blkSum128(v, red) * (1.0f/128.0f);
    float dv = v - mean;
    float var = blkSum128(dv*dv, red) * (1.0f/128.0f);
    lnx[tid] = dv * rsqrtf(var + 1e-5f) * lg[tid] + lb[tid];
    __syncthreads();
    float acc = bias[tid];
#pragma unroll 8
    for (int c = 0; c < D_; c++) acc += lnx[c]*W[c*D_+tid];    // coalesced over tid
    float* dst = (dst_sel == 0) ? g_qtok : ((dst_sel == 1) ? g_ktok : g_vtok);
    dst[idx*D_+tid] = acc;
}

// ---------------- flash attention per (b*L, head) ----------------------------
__global__ void k_attn(int NQ) {
    extern __shared__ float sh[];
    float* ks = sh;
    float* vs = sh + NKV*32;
    int bl = blockIdx.x;
    int hh = blockIdx.y;
    int tid = threadIdx.x;
    const float* kbase = g_ktok + bl*NKV*D_ + hh*32;
    const float* vbase = g_vtok + bl*NKV*D_ + hh*32;
    for (int idx = tid; idx < NKV*32; idx += blockDim.x) {
        int kk = idx >> 5, c = idx & 31;
        ks[idx] = kbase[kk*D_ + c];
        vs[idx] = vbase[kk*D_ + c];
    }
    __syncthreads();
    const float scale = 0.17677669529663687f;  // 32^-0.5
    for (int t = tid; t < NQ; t += blockDim.x) {
        const float* qp = g_qtok + (bl*NQ + t)*D_ + hh*32;
        float q[32];
#pragma unroll
        for (int c = 0; c < 32; c++) q[c] = qp[c]*scale;
        float m = -1e30f, ssum = 0.f;
        float acc[32];
#pragma unroll
        for (int c = 0; c < 32; c++) acc[c] = 0.f;
        for (int kk = 0; kk < NKV; kk++) {
            const float* kp = ks + kk*32;
            float s = 0.f;
#pragma unroll
            for (int c = 0; c < 32; c++) s += q[c]*kp[c];
            float mn = fmaxf(m, s);
            float corr = __expf(m - mn);
            float p = __expf(s - mn);
            ssum = ssum*corr + p;
            const float* vp = vs + kk*32;
#pragma unroll
            for (int c = 0; c < 32; c++) acc[c] = acc[c]*corr + p*vp[c];
            m = mn;
        }
        float inv = 1.0f / ssum;
        float* op = g_otok + (bl*NQ + t)*D_ + hh*32;
#pragma unroll
        for (int c = 0; c < 32; c++) op[c] = acc[c]*inv;
    }
}

// ---------------- output proj + camera mean + skip ---------------------------
// mean over n commutes with the linear Wp projection -> average first.
__global__ void k_projout(int stage, const float* __restrict__ Wp,
                          const float* __restrict__ bp,
                          const float* __restrict__ x) {
    int blk = blockIdx.x, tid = threadIdx.x;
    int b = blk / (H_*W_), p = blk % (H_*W_);
    int hh = p / W_, ww = p % W_;
    int i = hh & 7, j = ww & 7;
    int l = (hh >> 3)*8 + (ww >> 3);
    __shared__ float mvec[D_];
    if (stage == 0) {
        float a = 0.f;
#pragma unroll
        for (int n = 0; n < N_; n++)
            a += g_otok[((b*64+l)*NQ1 + n*64 + i*8 + j)*D_ + tid];
        mvec[tid] = a * (1.0f/6.0f);
    } else {
        mvec[tid] = g_otok[((b*64+l)*64 + i*8 + j)*D_ + tid];
    }
    __syncthreads();
    float acc = bp[tid];
#pragma unroll 8
    for (int c = 0; c < D_; c++) acc += mvec[c]*Wp[c*D_+tid];
    float sk = (stage == 0) ? x[(b*D_+tid)*(H_*W_) + p] : g_q1[blk*D_+tid];
    float* dst = (stage == 0) ? g_q1 : g_q2;
    dst[blk*D_+tid] = acc + sk;
}

// ---------------- MLP: x + gelu(ln(x)@Wa + ba)@Wb + bb (in-place) ------------
__global__ void k_mlp(int which,
                      const float* __restrict__ lg, const float* __restrict__ lb,
                      const float* __restrict__ Wa, const float* __restrict__ ba,
                      const float* __restrict__ Wb, const float* __restrict__ bb) {
    float* buf = (which == 0) ? g_q1 : g_q2;
    int blk = blockIdx.x, tid = threadIdx.x;
    __shared__ float lnx[D_];
    __shared__ float gh[256];
    __shared__ float red[4];
    float v = buf[blk*D_+tid];
    float mean = blkSum128(v, red)*(1.0f/128.0f);
    float dv = v - mean;
    float var = blkSum128(dv*dv, red)*(1.0f/128.0f);
    lnx[tid] = dv*rsqrtf(var+1e-5f)*lg[tid]+lb[tid];
    __syncthreads();
#pragma unroll
    for (int half = 0; half < 2; half++) {
        int j = tid + half*128;
        float hv = ba[j];
#pragma unroll 8
        for (int c = 0; c < D_; c++) hv += lnx[c]*Wa[c*256+j];
        gh[j] = hv * 0.5f * (1.0f + erff(hv*0.70710678118654752f));  // exact gelu
    }
    __syncthreads();
    float acc = v + bb[tid];
#pragma unroll 8
    for (int jj = 0; jj < 256; jj++) acc += gh[jj]*Wb[jj*D_+tid];
    buf[blk*D_+tid] = acc;
}

// ---------------- final LN + transpose to (b, c, h, w) -----------------------
__global__ void k_final(const float* __restrict__ pg, const float* __restrict__ pb,
                        float* __restrict__ out) {
    int blk = blockIdx.x, tid = threadIdx.x;
    int b = blk / (H_*W_), p = blk % (H_*W_);
    __shared__ float red[4];
    float v = g_q2[blk*D_+tid];
    float mean = blkSum128(v, red)*(1.0f/128.0f);
    float dv = v - mean;
    float var = blkSum128(dv*dv, red)*(1.0f/128.0f);
    out[(b*D_+tid)*(H_*W_) + p] = dv*rsqrtf(var+1e-5f)*pg[tid]+pb[tid];
}

// ---------------------------------------------------------------------------
extern "C" void kernel_launch(void* const* d_in, const int* in_sizes, int n_in,
                              void* d_out, int out_size) {
    (void)in_sizes; (void)n_in; (void)out_size;
    const float* x        = (const float*)d_in[1];
    const float* grid     = (const float*)d_in[2];
    const float* feature  = (const float*)d_in[3];
    const float* I_inv    = (const float*)d_in[4];
    const float* E_inv    = (const float*)d_in[5];
    const float* bn_fl_g  = (const float*)d_in[6];
    const float* bn_fl_b  = (const float*)d_in[7];
    const float* W_fl     = (const float*)d_in[8];
    const float* bn_fp_g  = (const float*)d_in[9];
    const float* bn_fp_b  = (const float*)d_in[10];
    const float* W_fp     = (const float*)d_in[11];
    const float* W_bev    = (const float*)d_in[12];
    const float* b_bev    = (const float*)d_in[13];
    const float* W_img    = (const float*)d_in[14];
    const float* W_cam    = (const float*)d_in[15];
    const float* aln_g    = (const float*)d_in[16];
    const float* aln_b    = (const float*)d_in[17];
    const float* aWqkv    = (const float*)d_in[18];
    const float* abqkv    = (const float*)d_in[19];
    const float* aWp      = (const float*)d_in[20];
    const float* abp      = (const float*)d_in[21];
    const float* pn_g     = (const float*)d_in[22];
    const float* pn_b     = (const float*)d_in[23];
    const float* Wma      = (const float*)d_in[24];
    const float* bma      = (const float*)d_in[25];
    const float* Wmb      = (const float*)d_in[26];
    const float* bmb      = (const float*)d_in[27];
    const float* post_g   = (const float*)d_in[28];
    const float* post_b   = (const float*)d_in[29];
    float* out = (float*)d_out;

    cudaFuncSetAttribute(k_attn, cudaFuncAttributeMaxDynamicSharedMemorySize,
                         NKV*32*2*(int)sizeof(float));

    k_cembed<<<B_*N_, 128>>>(E_inv, W_cam);
    k_keyval<<<B_*N_*FH_*FW_, 128>>>(feature, I_inv, E_inv, W_img,
                                     bn_fp_g, bn_fp_b, W_fp,
                                     bn_fl_g, bn_fl_b, W_fl);
    k_query<<<B_*N_*H_*W_, 128>>>(grid, x, W_bev, b_bev);

    for (int s = 0; s < 2; s++) {
        int NQ = (s == 0) ? NQ1 : 64;
        int qmode = (s == 0) ? 0 : 3;
        int kmode = (s == 0) ? 1 : 4;
        int vmode = (s == 0) ? 2 : 5;
        k_lnproj<<<B_*64*NQ, 128>>>(qmode, 0,
                                    aln_g + (s*3+0)*128, aln_b + (s*3+0)*128,
                                    aWqkv + (s*3+0)*128*128, abqkv + (s*3+0)*128);
        k_lnproj<<<B_*64*NKV, 128>>>(kmode, 1,
                                     aln_g + (s*3+1)*128, aln_b + (s*3+1)*128,
                                     aWqkv + (s*3+1)*128*128, abqkv + (s*3+1)*128);
        k_lnproj<<<B_*64*NKV, 128>>>(vmode, 2,
                                     aln_g + (s*3+2)*128, aln_b + (s*3+2)*128,
                                     aWqkv + (s*3+2)*128*128, abqkv + (s*3+2)*128);
        k_attn<<<dim3(B_*64, 4), 256, NKV*32*2*sizeof(float)>>>(NQ);
        k_projout<<<B_*H_*W_, 128>>>(s, aWp + s*128*128, abp + s*128, x);
        k_mlp<<<B_*H_*W_, 128>>>(s, pn_g + s*128, pn_b + s*128,
                                 Wma + s*128*256, bma + s*256,
                                 Wmb + s*256*128, bmb + s*128);
    }
    k_final<<<B_*H_*W_, 128>>>(post_g, post_b, out);
}

// round 2
// speedup vs baseline: 2.0808x; 2.0808x over previous
#include <cuda_runtime.h>
#include <math.h>

#define B_   2
#define N_   6
#define H_   64
#define W_   64
#define FH_  32
#define FW_  88
#define PIX  (FH_*FW_)     // 2816
#define D_   128
#define NKV  264
#define NQ1  384

// scratch (device globals: no runtime allocation allowed)
__device__ float g_cembed[B_*N_*D_];
__device__ float g_kim[B_*N_*PIX*D_];
__device__ float g_vim[B_*N_*PIX*D_];
__device__ float g_qim[B_*N_*H_*W_*D_];
__device__ float g_qtok[B_*64*NQ1*D_];
__device__ float g_ktok[B_*64*NKV*D_];
__device__ float g_vtok[B_*64*NKV*D_];
__device__ float g_otok[B_*64*NQ1*D_];
__device__ float g_q1[B_*H_*W_*D_];
__device__ float g_q2[B_*H_*W_*D_];

__device__ __forceinline__ float blkSum128(float v, float* red) {
#pragma unroll
    for (int o = 16; o; o >>= 1) v += __shfl_xor_sync(0xffffffffu, v, o);
    if ((threadIdx.x & 31) == 0) red[threadIdx.x >> 5] = v;
    __syncthreads();
    float s = red[0] + red[1] + red[2] + red[3];
    __syncthreads();
    return s;
}

__device__ __forceinline__ void warpRed2(float& s, float& q) {
#pragma unroll
    for (int o = 16; o; o >>= 1) {
        s += __shfl_xor_sync(0xffffffffu, s, o);
        q += __shfl_xor_sync(0xffffffffu, q, o);
    }
}

// ---------------- camera embedding ------------------------------------------
__global__ void k_cembed(const float* __restrict__ E_inv,
                         const float* __restrict__ W_cam) {
    int bn = blockIdx.x, o = threadIdx.x;
    float acc = 0.f;
#pragma unroll
    for (int i = 0; i < 4; i++) acc += W_cam[o*4+i] * E_inv[bn*16 + i*4 + 3];
    g_cembed[bn*D_ + o] = acc;
}

// ---------------- key/val image features, tiled 32 pixels/block --------------
__global__ void __launch_bounds__(128) k_keyval(
        const float* __restrict__ feat,
        const float* __restrict__ I_inv, const float* __restrict__ E_inv,
        const float* __restrict__ W_img,
        const float* __restrict__ fp_g, const float* __restrict__ fp_b,
        const float* __restrict__ W_fp,
        const float* __restrict__ fl_g, const float* __restrict__ fl_b,
        const float* __restrict__ W_fl) {
    extern __shared__ float sh[];
    float* sfp  = sh;            // [128 ch][32 px] channel-major
    float* sfl  = sh + 4096;
    float* kimg = sh + 8192;     // [32 px][128 ch]
    int blk = blockIdx.x, tid = threadIdx.x;
    int bn = blk / 88, p0 = (blk % 88) * 32;
    int warp = tid >> 5, lane = tid & 31;

    const float invs = rsqrtf(1.0f + 1e-5f);
    // P0: BN-ReLU into channel-major smem (coalesced)
    for (int k = tid; k < 4096; k += 128) {
        int c = k >> 5, pp = k & 31;
        float f = feat[(bn*D_ + c)*PIX + p0 + pp];
        sfp[k] = fmaxf(f * invs * fp_g[c] + fp_b[c], 0.f);
        sfl[k] = fmaxf(f * invs * fl_g[c] + fl_b[c], 0.f);
    }
    // P1: image embedding, warp-per-pixel
    for (int it = 0; it < 8; it++) {
        int tt = it*4 + warp;
        int p = p0 + tt, fh = p / FW_, fw = p % FW_;
        float px = (float)fw * (480.0f / 87.0f);
        float py = (float)fh * (224.0f / 31.0f);
        float cam[4];
#pragma unroll
        for (int i = 0; i < 3; i++)
            cam[i] = I_inv[bn*9+i*3+0]*px + I_inv[bn*9+i*3+1]*py + I_inv[bn*9+i*3+2];
        cam[3] = 1.0f;
        float dd[4];
#pragma unroll
        for (int i = 0; i < 4; i++)
            dd[i] = E_inv[bn*16+i*4+0]*cam[0] + E_inv[bn*16+i*4+1]*cam[1]
                  + E_inv[bn*16+i*4+2]*cam[2] + E_inv[bn*16+i*4+3]*cam[3];
        int c0 = lane*4;
        float t[4]; float ssum = 0.f, dum = 0.f;
#pragma unroll
        for (int i = 0; i < 4; i++) {
            int c = c0+i;
            float de = W_img[c*4+0]*dd[0] + W_img[c*4+1]*dd[1]
                     + W_img[c*4+2]*dd[2] + W_img[c*4+3]*dd[3];
            t[i] = de - g_cembed[bn*D_+c];
            ssum += t[i]*t[i];
        }
        warpRed2(ssum, dum);
        float inv = 1.0f / fmaxf(sqrtf(ssum), 1e-12f);
#pragma unroll
        for (int i = 0; i < 4; i++) kimg[tt*D_ + c0 + i] = t[i]*inv;
    }
    __syncthreads();
    // P2: conv_fp -> k ; P3: conv_fl -> v. thread owns output channel tid.
    for (int pass = 0; pass < 2; pass++) {
        const float* Wc = pass ? W_fl : W_fp;
        const float* sx = pass ? sfl : sfp;
        float wreg[128];
        const float4* w4 = reinterpret_cast<const float4*>(Wc + tid*D_);
#pragma unroll
        for (int c4 = 0; c4 < 32; c4++) {
            float4 w = w4[c4];
            wreg[c4*4+0]=w.x; wreg[c4*4+1]=w.y; wreg[c4*4+2]=w.z; wreg[c4*4+3]=w.w;
        }
        const float4* sx4 = reinterpret_cast<const float4*>(sx);
#pragma unroll
        for (int pg = 0; pg < 4; pg++) {
            float acc[8];
#pragma unroll
            for (int j = 0; j < 8; j++) acc[j] = 0.f;
            for (int c = 0; c < 128; c++) {
                float w = wreg[c];
                float4 a = sx4[c*8 + pg*2];
                float4 b = sx4[c*8 + pg*2 + 1];
                acc[0] += w*a.x; acc[1] += w*a.y; acc[2] += w*a.z; acc[3] += w*a.w;
                acc[4] += w*b.x; acc[5] += w*b.y; acc[6] += w*b.z; acc[7] += w*b.w;
            }
#pragma unroll
            for (int j = 0; j < 8; j++) {
                int pp = pg*8 + j;
                if (pass == 0)
                    g_kim[(bn*PIX + p0 + pp)*D_ + tid] = kimg[pp*D_+tid] + acc[j];
                else
                    g_vim[(bn*PIX + p0 + pp)*D_ + tid] = acc[j];
            }
        }
    }
}

// ---------------- query -----------------------------------------------------
__global__ void k_query(const float* __restrict__ grid,
                        const float* __restrict__ x,
                        const float* __restrict__ W_bev,
                        const float* __restrict__ b_bev) {
    int blk = blockIdx.x;
    int bn = blk / (H_*W_), p = blk % (H_*W_);
    int b = bn / N_;
    int tid = threadIdx.x;
    __shared__ float red[4];
    float we = W_bev[tid*2+0]*grid[p] + W_bev[tid*2+1]*grid[H_*W_ + p] + b_bev[tid];
    float t = we - g_cembed[bn*D_+tid];
    float ss = blkSum128(t*t, red);
    float bev = t / fmaxf(sqrtf(ss), 1e-12f);
    g_qim[blk*D_+tid] = bev + x[(b*D_+tid)*(H_*W_) + p];
}

// ---------------- gather + LN + QKV projection, tiled 32 tokens/block --------
// modes: 0=Q1 1=K1 2=V1 3=Q2 4=K2 5=V2
__device__ __forceinline__ const float* lnproj_src(int mode, int u) {
    if (mode == 0) {
        int b = u / 24576; int r = u % 24576;
        int l = r / NQ1; int t = r % NQ1;
        int n = t >> 6; int ij = t & 63; int i = ij >> 3, j = ij & 7;
        int h = (l >> 3)*8 + i, w = (l & 7)*8 + j;
        return g_qim + (((b*N_+n)*H_ + h)*W_ + w)*D_;
    } else if (mode == 3) {
        int b = u >> 12; int r = u & 4095;
        int l = r >> 6; int t = r & 63; int i = t >> 3, j = t & 7;
        int h = (l >> 3)*8 + i, w = (l & 7)*8 + j;
        return g_q1 + ((b*H_+h)*W_+w)*D_;
    } else {
        int b = u / 16896; int r = u % 16896;
        int l = r / NKV; int t = r % NKV;
        int n = t / 44; int f = t % 44; int f1 = f / 11, f2 = f % 11;
        int h, w;
        if (mode <= 2) { h = (l >> 3)*4 + f1;  w = (l & 7)*11 + f2; }
        else           { h = f1*8 + (l >> 3);  w = f2*8 + (l & 7); }
        const float* base = (mode == 1 || mode == 4) ? g_kim : g_vim;
        return base + (((b*N_+n)*FH_ + h)*FW_ + w)*D_;
    }
}

__global__ void __launch_bounds__(128) k_lnproj(
        int mode, int dst_sel,
        const float* __restrict__ lg, const float* __restrict__ lb,
        const float* __restrict__ W, const float* __restrict__ bias) {
    __shared__ __align__(16) float lnx[32][D_];
    __shared__ float sg[D_], sb[D_];
    int blk = blockIdx.x, tid = threadIdx.x;
    int warp = tid >> 5, lane = tid & 31;
    sg[tid] = lg[tid]; sb[tid] = lb[tid];
    float bias_r = bias[tid];
    float wreg[128];
#pragma unroll
    for (int c = 0; c < 128; c++) wreg[c] = W[c*D_ + tid];
    __syncthreads();
    // LN: warp per token
    for (int it = 0; it < 8; it++) {
        int tt = it*4 + warp;
        int u = blk*32 + tt;
        const float* src = lnproj_src(mode, u);
        float4 v = reinterpret_cast<const float4*>(src)[lane];
        float s = v.x+v.y+v.z+v.w;
        float q = v.x*v.x+v.y*v.y+v.z*v.z+v.w*v.w;
        warpRed2(s, q);
        float mean = s*(1.0f/128.0f);
        float var = fmaxf(q*(1.0f/128.0f) - mean*mean, 0.f);
        float rstd = rsqrtf(var + 1e-5f);
        int c0 = lane*4;
        lnx[tt][c0+0] = (v.x-mean)*rstd*sg[c0+0]+sb[c0+0];
        lnx[tt][c0+1] = (v.y-mean)*rstd*sg[c0+1]+sb[c0+1];
        lnx[tt][c0+2] = (v.z-mean)*rstd*sg[c0+2]+sb[c0+2];
        lnx[tt][c0+3] = (v.w-mean)*rstd*sg[c0+3]+sb[c0+3];
    }
    __syncthreads();
    float* dst = (dst_sel == 0) ? g_qtok : ((dst_sel == 1) ? g_ktok : g_vtok);
    for (int tt = 0; tt < 32; tt++) {
        const float4* xr = reinterpret_cast<const float4*>(lnx[tt]);
        float acc = bias_r;
#pragma unroll
        for (int c4 = 0; c4 < 32; c4++) {
            float4 xv = xr[c4];
            acc += xv.x*wreg[c4*4+0] + xv.y*wreg[c4*4+1]
                 + xv.z*wreg[c4*4+2] + xv.w*wreg[c4*4+3];
        }
        dst[(blk*32 + tt)*D_ + tid] = acc;
    }
}

// ---------------- flash attention stage 1: 384 threads, 1 q/thread -----------
__global__ void __launch_bounds__(384) k_attn1() {
    extern __shared__ float sh[];
    float* ks = sh;
    float* vs = sh + NKV*32;
    int bl = blockIdx.x, hh = blockIdx.y, tid = threadIdx.x;
    const float* kbase = g_ktok + bl*NKV*D_ + hh*32;
    const float* vbase = g_vtok + bl*NKV*D_ + hh*32;
    for (int t = tid; t < NKV*8; t += 384) {
        int kk = t >> 3, c4 = t & 7;
        reinterpret_cast<float4*>(ks)[t] = reinterpret_cast<const float4*>(kbase)[kk*32 + c4];
        reinterpret_cast<float4*>(vs)[t] = reinterpret_cast<const float4*>(vbase)[kk*32 + c4];
    }
    __syncthreads();
    const float scale = 0.17677669529663687f;
    const float* qp = g_qtok + (bl*NQ1 + tid)*D_ + hh*32;
    float q[32];
#pragma unroll
    for (int c4 = 0; c4 < 8; c4++) {
        float4 v = reinterpret_cast<const float4*>(qp)[c4];
        q[c4*4+0]=v.x*scale; q[c4*4+1]=v.y*scale; q[c4*4+2]=v.z*scale; q[c4*4+3]=v.w*scale;
    }
    float m = -1e30f, ssum = 0.f;
    float acc[32];
#pragma unroll
    for (int c = 0; c < 32; c++) acc[c] = 0.f;
    for (int kk = 0; kk < NKV; kk++) {
        const float4* kp = reinterpret_cast<const float4*>(ks + kk*32);
        float s = 0.f;
#pragma unroll
        for (int c4 = 0; c4 < 8; c4++) {
            float4 kv = kp[c4];
            s += q[c4*4+0]*kv.x + q[c4*4+1]*kv.y + q[c4*4+2]*kv.z + q[c4*4+3]*kv.w;
        }
        float mn = fmaxf(m, s);
        float corr = __expf(m - mn);
        float p = __expf(s - mn);
        ssum = ssum*corr + p;
        const float4* vp = reinterpret_cast<const float4*>(vs + kk*32);
#pragma unroll
        for (int c4 = 0; c4 < 8; c4++) {
            float4 vv = vp[c4];
            acc[c4*4+0] = acc[c4*4+0]*corr + p*vv.x;
            acc[c4*4+1] = acc[c4*4+1]*corr + p*vv.y;
            acc[c4*4+2] = acc[c4*4+2]*corr + p*vv.z;
            acc[c4*4+3] = acc[c4*4+3]*corr + p*vv.w;
        }
        m = mn;
    }
    float inv = 1.0f / ssum;
    float* op = g_otok + (bl*NQ1 + tid)*D_ + hh*32;
#pragma unroll
    for (int c4 = 0; c4 < 8; c4++) {
        float4 o;
        o.x = acc[c4*4+0]*inv; o.y = acc[c4*4+1]*inv;
        o.z = acc[c4*4+2]*inv; o.w = acc[c4*4+3]*inv;
        reinterpret_cast<float4*>(op)[c4] = o;
    }
}

// ---------------- flash attention stage 2: 64 q, split-KV x4 -----------------
__global__ void __launch_bounds__(256) k_attn2() {
    extern __shared__ float sh[];
    float* ks = sh;                       // 8448
    float* vs = sh + NKV*32;              // 8448
    float* pacc = sh + NKV*64;            // 4*64*32 = 8192
    float* pm = pacc + 8192;              // 256
    float* psum = pm + 256;               // 256
    int bl = blockIdx.x, hh = blockIdx.y, tid = threadIdx.x;
    int part = tid >> 6, q = tid & 63;
    const float* kbase = g_ktok + bl*NKV*D_ + hh*32;
    const float* vbase = g_vtok + bl*NKV*D_ + hh*32;
    for (int t = tid; t < NKV*8; t += 256) {
        int kk = t >> 3, c4 = t & 7;
        reinterpret_cast<float4*>(ks)[t] = reinterpret_cast<const float4*>(kbase)[kk*32 + c4];
        reinterpret_cast<float4*>(vs)[t] = reinterpret_cast<const float4*>(vbase)[kk*32 + c4];
    }
    __syncthreads();
    const float scale = 0.17677669529663687f;
    const float* qp = g_qtok + (bl*64 + q)*D_ + hh*32;
    float qr[32];
#pragma unroll
    for (int c4 = 0; c4 < 8; c4++) {
        float4 v = reinterpret_cast<const float4*>(qp)[c4];
        qr[c4*4+0]=v.x*scale; qr[c4*4+1]=v.y*scale; qr[c4*4+2]=v.z*scale; qr[c4*4+3]=v.w*scale;
    }
    float m = -1e30f, ssum = 0.f;
    float acc[32];
#pragma unroll
    for (int c = 0; c < 32; c++) acc[c] = 0.f;
    for (int kk = part*66; kk < part*66 + 66; kk++) {
        const float4* kp = reinterpret_cast<const float4*>(ks + kk*32);
        float s = 0.f;
#pragma unroll
        for (int c4 = 0; c4 < 8; c4++) {
            float4 kv = kp[c4];
            s += qr[c4*4+0]*kv.x + qr[c4*4+1]*kv.y + qr[c4*4+2]*kv.z + qr[c4*4+3]*kv.w;
        }
        float mn = fmaxf(m, s);
        float corr = __expf(m - mn);
        float p = __expf(s - mn);
        ssum = ssum*corr + p;
        const float4* vp = reinterpret_cast<const float4*>(vs + kk*32);
#pragma unroll
        for (int c4 = 0; c4 < 8; c4++) {
            float4 vv = vp[c4];
            acc[c4*4+0] = acc[c4*4+0]*corr + p*vv.x;
            acc[c4*4+1] = acc[c4*4+1]*corr + p*vv.y;
            acc[c4*4+2] = acc[c4*4+2]*corr + p*vv.z;
            acc[c4*4+3] = acc[c4*4+3]*corr + p*vv.w;
        }
        m = mn;
    }
    pm[part*64+q] = m;
    psum[part*64+q] = ssum;
    float* pa = pacc + (part*64+q)*32;
#pragma unroll
    for (int c4 = 0; c4 < 8; c4++) {
        float4 o; o.x=acc[c4*4]; o.y=acc[c4*4+1]; o.z=acc[c4*4+2]; o.w=acc[c4*4+3];
        reinterpret_cast<float4*>(pa)[c4] = o;
    }
    __syncthreads();
    // merge: thread -> (q = tid&63, channel group cg = tid>>6 -> 8 channels)
    {
        int qq = tid & 63, cg = tid >> 6;
        float M = fmaxf(fmaxf(pm[qq], pm[64+qq]), fmaxf(pm[128+qq], pm[192+qq]));
        float w0 = __expf(pm[qq]-M),      w1 = __expf(pm[64+qq]-M);
        float w2 = __expf(pm[128+qq]-M),  w3 = __expf(pm[192+qq]-M);
        float S = w0*psum[qq] + w1*psum[64+qq] + w2*psum[128+qq] + w3*psum[192+qq];
        float inv = 1.0f / S;
        float* op = g_otok + (bl*64 + qq)*D_ + hh*32 + cg*8;
#pragma unroll
        for (int c = 0; c < 8; c++) {
            float o = w0*pacc[(qq)*32 + cg*8 + c]
                    + w1*pacc[(64+qq)*32 + cg*8 + c]
                    + w2*pacc[(128+qq)*32 + cg*8 + c]
                    + w3*pacc[(192+qq)*32 + cg*8 + c];
            op[c] = o*inv;
        }
    }
}

// ---------------- output proj + camera mean + skip, tiled --------------------
__global__ void __launch_bounds__(128) k_projout(
        int stage, const float* __restrict__ Wp,
        const float* __restrict__ bp, const float* __restrict__ x) {
    __shared__ __align__(16) float mvec[32][D_];
    int blk = blockIdx.x, tid = threadIdx.x;
    float bp_r = bp[tid];
    float wreg[128];
#pragma unroll
    for (int c = 0; c < 128; c++) wreg[c] = Wp[c*D_ + tid];
    for (int tt = 0; tt < 32; tt++) {
        int u = blk*32 + tt;
        int b = u >> 12, p = u & 4095;
        int hh = p >> 6, ww = p & 63;
        int i = hh & 7, j = ww & 7;
        int l = (hh >> 3)*8 + (ww >> 3);
        if (stage == 0) {
            float a = 0.f;
#pragma unroll
            for (int n = 0; n < N_; n++)
                a += g_otok[((b*64+l)*NQ1 + n*64 + i*8 + j)*D_ + tid];
            mvec[tt][tid] = a * (1.0f/6.0f);
        } else {
            mvec[tt][tid] = g_otok[((b*64+l)*64 + i*8 + j)*D_ + tid];
        }
    }
    __syncthreads();
    for (int tt = 0; tt < 32; tt++) {
        int u = blk*32 + tt;
        int b = u >> 12, p = u & 4095;
        const float4* xr = reinterpret_cast<const float4*>(mvec[tt]);
        float acc = bp_r;
#pragma unroll
        for (int c4 = 0; c4 < 32; c4++) {
            float4 xv = xr[c4];
            acc += xv.x*wreg[c4*4+0] + xv.y*wreg[c4*4+1]
                 + xv.z*wreg[c4*4+2] + xv.w*wreg[c4*4+3];
        }
        float sk = (stage == 0) ? x[(b*D_+tid)*4096 + p] : g_q1[u*D_ + tid];
        float* dst = (stage == 0) ? g_q1 : g_q2;
        dst[u*D_ + tid] = acc + sk;
    }
}

// ---------------- MLP, tiled 16 tokens/block, 256 threads --------------------
__global__ void __launch_bounds__(256) k_mlp(
        int which,
        const float* __restrict__ lg, const float* __restrict__ lb,
        const float* __restrict__ Wa, const float* __restrict__ ba,
        const float* __restrict__ Wb, const float* __restrict__ bb) {
    __shared__ __align__(16) float lnx[16][D_];      // reused as pbuf in phase B
    __shared__ __align__(16) float gh[16][256];
    float* buf = (which == 0) ? g_q1 : g_q2;
    int blk = blockIdx.x, tid = threadIdx.x;
    int warp = tid >> 5, lane = tid & 31;
    // LN: warp per token (8 warps x 2)
    for (int it = 0; it < 2; it++) {
        int tt = it*8 + warp;
        int u = blk*16 + tt;
        float4 v = reinterpret_cast<const float4*>(buf + u*D_)[lane];
        float s = v.x+v.y+v.z+v.w;
        float q = v.x*v.x+v.y*v.y+v.z*v.z+v.w*v.w;
        warpRed2(s, q);
        float mean = s*(1.0f/128.0f);
        float var = fmaxf(q*(1.0f/128.0f) - mean*mean, 0.f);
        float rstd = rsqrtf(var + 1e-5f);
        int c0 = lane*4;
        lnx[tt][c0+0] = (v.x-mean)*rstd*lg[c0+0]+lb[c0+0];
        lnx[tt][c0+1] = (v.y-mean)*rstd*lg[c0+1]+lb[c0+1];
        lnx[tt][c0+2] = (v.z-mean)*rstd*lg[c0+2]+lb[c0+2];
        lnx[tt][c0+3] = (v.w-mean)*rstd*lg[c0+3]+lb[c0+3];
    }
    __syncthreads();
    // Phase A: h = gelu(lnx @ Wa + ba); thread owns hidden col j = tid
    {
        float wa[128];
#pragma unroll
        for (int c = 0; c < 128; c++) wa[c] = Wa[c*256 + tid];
        float ba_r = ba[tid];
        for (int tt = 0; tt < 16; tt++) {
            const float4* xr = reinterpret_cast<const float4*>(lnx[tt]);
            float h = ba_r;
#pragma unroll
            for (int c4 = 0; c4 < 32; c4++) {
                float4 xv = xr[c4];
                h += xv.x*wa[c4*4+0] + xv.y*wa[c4*4+1] + xv.z*wa[c4*4+2] + xv.w*wa[c4*4+3];
            }
            gh[tt][tid] = h * 0.5f * (1.0f + erff(h*0.70710678118654752f));
        }
    }
    __syncthreads();
    // Phase B: out = x + gh @ Wb + bb; thread (o = tid&127, half = tid>>7)
    {
        int o = tid & 127, half = tid >> 7;
        float wb[128];
#pragma unroll
        for (int c = 0; c < 128; c++) wb[c] = Wb[(half*128 + c)*D_ + o];
        float accs[16];
        for (int tt = 0; tt < 16; tt++) {
            const float4* hr = reinterpret_cast<const float4*>(&gh[tt][half*128]);
            float acc = 0.f;
#pragma unroll
            for (int c4 = 0; c4 < 32; c4++) {
                float4 hv = hr[c4];
                acc += hv.x*wb[c4*4+0] + hv.y*wb[c4*4+1] + hv.z*wb[c4*4+2] + hv.w*wb[c4*4+3];
            }
            accs[tt] = acc;
        }
        __syncthreads();
        float* pbuf = &lnx[0][0];     // reuse
        if (half == 1) {
            for (int tt = 0; tt < 16; tt++) pbuf[tt*D_ + o] = accs[tt];
        }
        __syncthreads();
        if (half == 0) {
            float bb_r = bb[o];
            for (int tt = 0; tt < 16; tt++) {
                int u = blk*16 + tt;
                buf[u*D_ + o] = buf[u*D_ + o] + bb_r + accs[tt] + pbuf[tt*D_ + o];
            }
        }
    }
}

// ---------------- final LN + transpose ---------------------------------------
__global__ void k_final(const float* __restrict__ pg, const float* __restrict__ pb,
                        float* __restrict__ out) {
    int blk = blockIdx.x, tid = threadIdx.x;
    int b = blk / (H_*W_), p = blk % (H_*W_);
    __shared__ float red[4];
    float v = g_q2[blk*D_+tid];
    float mean = blkSum128(v, red)*(1.0f/128.0f);
    float dv = v - mean;
    float var = blkSum128(dv*dv, red)*(1.0f/128.0f);
    out[(b*D_+tid)*(H_*W_) + p] = dv*rsqrtf(var+1e-5f)*pg[tid]+pb[tid];
}

// ---------------------------------------------------------------------------
extern "C" void kernel_launch(void* const* d_in, const int* in_sizes, int n_in,
                              void* d_out, int out_size) {
    (void)in_sizes; (void)n_in; (void)out_size;
    const float* x        = (const float*)d_in[1];
    const float* grid     = (const float*)d_in[2];
    const float* feature  = (const float*)d_in[3];
    const float* I_inv    = (const float*)d_in[4];
    const float* E_inv    = (const float*)d_in[5];
    const float* bn_fl_g  = (const float*)d_in[6];
    const float* bn_fl_b  = (const float*)d_in[7];
    const float* W_fl     = (const float*)d_in[8];
    const float* bn_fp_g  = (const float*)d_in[9];
    const float* bn_fp_b  = (const float*)d_in[10];
    const float* W_fp     = (const float*)d_in[11];
    const float* W_bev    = (const float*)d_in[12];
    const float* b_bev    = (const float*)d_in[13];
    const float* W_img    = (const float*)d_in[14];
    const float* W_cam    = (const float*)d_in[15];
    const float* aln_g    = (const float*)d_in[16];
    const float* aln_b    = (const float*)d_in[17];
    const float* aWqkv    = (const float*)d_in[18];
    const float* abqkv    = (const float*)d_in[19];
    const float* aWp      = (const float*)d_in[20];
    const float* abp      = (const float*)d_in[21];
    const float* pn_g     = (const float*)d_in[22];
    const float* pn_b     = (const float*)d_in[23];
    const float* Wma      = (const float*)d_in[24];
    const float* bma      = (const float*)d_in[25];
    const float* Wmb      = (const float*)d_in[26];
    const float* bmb      = (const float*)d_in[27];
    const float* post_g   = (const float*)d_in[28];
    const float* post_b   = (const float*)d_in[29];
    float* out = (float*)d_out;

    cudaFuncSetAttribute(k_keyval, cudaFuncAttributeMaxDynamicSharedMemorySize, 49152);
    cudaFuncSetAttribute(k_attn1, cudaFuncAttributeMaxDynamicSharedMemorySize, NKV*32*2*(int)sizeof(float));
    cudaFuncSetAttribute(k_attn2, cudaFuncAttributeMaxDynamicSharedMemorySize, 102400);

    k_cembed<<<B_*N_, 128>>>(E_inv, W_cam);
    k_keyval<<<B_*N_*88, 128, 49152>>>(feature, I_inv, E_inv, W_img,
                                       bn_fp_g, bn_fp_b, W_fp,
                                       bn_fl_g, bn_fl_b, W_fl);
    k_query<<<B_*N_*H_*W_, 128>>>(grid, x, W_bev, b_bev);

    for (int s = 0; s < 2; s++) {
        int qmode = (s == 0) ? 0 : 3;
        int kmode = (s == 0) ? 1 : 4;
        int vmode = (s == 0) ? 2 : 5;
        int nqtok = (s == 0) ? B_*64*NQ1 : B_*64*64;
        k_lnproj<<<nqtok/32, 128>>>(qmode, 0,
                                    aln_g + (s*3+0)*128, aln_b + (s*3+0)*128,
                                    aWqkv + (s*3+0)*128*128, abqkv + (s*3+0)*128);
        k_lnproj<<<B_*64*NKV/32, 128>>>(kmode, 1,
                                        aln_g + (s*3+1)*128, aln_b + (s*3+1)*128,
                                        aWqkv + (s*3+1)*128*128, abqkv + (s*3+1)*128);
        k_lnproj<<<B_*64*NKV/32, 128>>>(vmode, 2,
                                        aln_g + (s*3+2)*128, aln_b + (s*3+2)*128,
                                        aWqkv + (s*3+2)*128*128, abqkv + (s*3+2)*128);
        if (s == 0)
            k_attn1<<<dim3(B_*64, 4), 384, NKV*32*2*sizeof(float)>>>();
        else
            k_attn2<<<dim3(B_*64, 4), 256, 102400>>>();
        k_projout<<<B_*H_*W_/32, 128>>>(s, aWp + s*128*128, abp + s*128, x);
        k_mlp<<<B_*H_*W_/16, 256>>>(s, pn_g + s*128, pn_b + s*128,
                                    Wma + s*128*256, bma + s*256,
                                    Wmb + s*256*128, bmb + s*128);
    }
    k_final<<<B_*H_*W_, 128>>>(post_g, post_b, out);
}

// round 3
// speedup vs baseline: 2.1360x; 1.0265x over previous
#include <cuda_runtime.h>
#include <math.h>

#define B_   2
#define N_   6
#define H_   64
#define W_   64
#define FH_  32
#define FW_  88
#define PIX  (FH_*FW_)     // 2816
#define D_   128
#define NKV  264
#define NQ1  384

// scratch (device globals: no runtime allocation allowed)
__device__ float g_cembed[B_*N_*D_];
__device__ float g_kim[B_*N_*PIX*D_];
__device__ float g_vim[B_*N_*PIX*D_];
__device__ float g_qim[B_*N_*H_*W_*D_];
__device__ float g_qtok[B_*64*NQ1*D_];
__device__ float g_ktok[B_*64*NKV*D_];
__device__ float g_vtok[B_*64*NKV*D_];
__device__ float g_otok[B_*64*NQ1*D_];
__device__ float g_q1[B_*H_*W_*D_];
__device__ float g_q2[B_*H_*W_*D_];

__device__ __forceinline__ float blkSum128(float v, float* red) {
#pragma unroll
    for (int o = 16; o; o >>= 1) v += __shfl_xor_sync(0xffffffffu, v, o);
    if ((threadIdx.x & 31) == 0) red[threadIdx.x >> 5] = v;
    __syncthreads();
    float s = red[0] + red[1] + red[2] + red[3];
    __syncthreads();
    return s;
}

__device__ __forceinline__ void warpRed2(float& s, float& q) {
#pragma unroll
    for (int o = 16; o; o >>= 1) {
        s += __shfl_xor_sync(0xffffffffu, s, o);
        q += __shfl_xor_sync(0xffffffffu, q, o);
    }
}

// ---------------- camera embedding ------------------------------------------
__global__ void k_cembed(const float* __restrict__ E_inv,
                         const float* __restrict__ W_cam) {
    int bn = blockIdx.x, o = threadIdx.x;
    float acc = 0.f;
#pragma unroll
    for (int i = 0; i < 4; i++) acc += W_cam[o*4+i] * E_inv[bn*16 + i*4 + 3];
    g_cembed[bn*D_ + o] = acc;
}

// ---------------- key/val image features, tiled 32 pixels/block --------------
__global__ void __launch_bounds__(128) k_keyval(
        const float* __restrict__ feat,
        const float* __restrict__ I_inv, const float* __restrict__ E_inv,
        const float* __restrict__ W_img,
        const float* __restrict__ fp_g, const float* __restrict__ fp_b,
        const float* __restrict__ W_fp,
        const float* __restrict__ fl_g, const float* __restrict__ fl_b,
        const float* __restrict__ W_fl) {
    extern __shared__ float sh[];
    float* sfp  = sh;            // [128 ch][32 px] channel-major
    float* sfl  = sh + 4096;
    float* kimg = sh + 8192;     // [32 px][128 ch]
    int blk = blockIdx.x, tid = threadIdx.x;
    int bn = blk / 88, p0 = (blk % 88) * 32;
    int warp = tid >> 5, lane = tid & 31;

    const float invs = rsqrtf(1.0f + 1e-5f);
    for (int k = tid; k < 4096; k += 128) {
        int c = k >> 5, pp = k & 31;
        float f = feat[(bn*D_ + c)*PIX + p0 + pp];
        sfp[k] = fmaxf(f * invs * fp_g[c] + fp_b[c], 0.f);
        sfl[k] = fmaxf(f * invs * fl_g[c] + fl_b[c], 0.f);
    }
    for (int it = 0; it < 8; it++) {
        int tt = it*4 + warp;
        int p = p0 + tt, fh = p / FW_, fw = p % FW_;
        float px = (float)fw * (480.0f / 87.0f);
        float py = (float)fh * (224.0f / 31.0f);
        float cam[4];
#pragma unroll
        for (int i = 0; i < 3; i++)
            cam[i] = I_inv[bn*9+i*3+0]*px + I_inv[bn*9+i*3+1]*py + I_inv[bn*9+i*3+2];
        cam[3] = 1.0f;
        float dd[4];
#pragma unroll
        for (int i = 0; i < 4; i++)
            dd[i] = E_inv[bn*16+i*4+0]*cam[0] + E_inv[bn*16+i*4+1]*cam[1]
                  + E_inv[bn*16+i*4+2]*cam[2] + E_inv[bn*16+i*4+3]*cam[3];
        int c0 = lane*4;
        float t[4]; float ssum = 0.f, dum = 0.f;
#pragma unroll
        for (int i = 0; i < 4; i++) {
            int c = c0+i;
            float de = W_img[c*4+0]*dd[0] + W_img[c*4+1]*dd[1]
                     + W_img[c*4+2]*dd[2] + W_img[c*4+3]*dd[3];
            t[i] = de - g_cembed[bn*D_+c];
            ssum += t[i]*t[i];
        }
        warpRed2(ssum, dum);
        float inv = 1.0f / fmaxf(sqrtf(ssum), 1e-12f);
#pragma unroll
        for (int i = 0; i < 4; i++) kimg[tt*D_ + c0 + i] = t[i]*inv;
    }
    __syncthreads();
    for (int pass = 0; pass < 2; pass++) {
        const float* Wc = pass ? W_fl : W_fp;
        const float* sx = pass ? sfl : sfp;
        float wreg[128];
        const float4* w4 = reinterpret_cast<const float4*>(Wc + tid*D_);
#pragma unroll
        for (int c4 = 0; c4 < 32; c4++) {
            float4 w = w4[c4];
            wreg[c4*4+0]=w.x; wreg[c4*4+1]=w.y; wreg[c4*4+2]=w.z; wreg[c4*4+3]=w.w;
        }
        const float4* sx4 = reinterpret_cast<const float4*>(sx);
#pragma unroll
        for (int pg = 0; pg < 4; pg++) {
            float acc[8];
#pragma unroll
            for (int j = 0; j < 8; j++) acc[j] = 0.f;
            for (int c = 0; c < 128; c++) {
                float w = wreg[c];
                float4 a = sx4[c*8 + pg*2];
                float4 b = sx4[c*8 + pg*2 + 1];
                acc[0] += w*a.x; acc[1] += w*a.y; acc[2] += w*a.z; acc[3] += w*a.w;
                acc[4] += w*b.x; acc[5] += w*b.y; acc[6] += w*b.z; acc[7] += w*b.w;
            }
#pragma unroll
            for (int j = 0; j < 8; j++) {
                int pp = pg*8 + j;
                if (pass == 0)
                    g_kim[(bn*PIX + p0 + pp)*D_ + tid] = kimg[pp*D_+tid] + acc[j];
                else
                    g_vim[(bn*PIX + p0 + pp)*D_ + tid] = acc[j];
            }
        }
    }
}

// ---------------- query -----------------------------------------------------
__global__ void k_query(const float* __restrict__ grid,
                        const float* __restrict__ x,
                        const float* __restrict__ W_bev,
                        const float* __restrict__ b_bev) {
    int blk = blockIdx.x;
    int bn = blk / (H_*W_), p = blk % (H_*W_);
    int b = bn / N_;
    int tid = threadIdx.x;
    __shared__ float red[4];
    float we = W_bev[tid*2+0]*grid[p] + W_bev[tid*2+1]*grid[H_*W_ + p] + b_bev[tid];
    float t = we - g_cembed[bn*D_+tid];
    float ss = blkSum128(t*t, red);
    float bev = t / fmaxf(sqrtf(ss), 1e-12f);
    g_qim[blk*D_+tid] = bev + x[(b*D_+tid)*(H_*W_) + p];
}

// ---------------- gather + LN + QKV projection, tiled 32 tokens/block --------
__device__ __forceinline__ const float* lnproj_src(int mode, int u) {
    if (mode == 0) {
        int b = u / 24576; int r = u % 24576;
        int l = r / NQ1; int t = r % NQ1;
        int n = t >> 6; int ij = t & 63; int i = ij >> 3, j = ij & 7;
        int h = (l >> 3)*8 + i, w = (l & 7)*8 + j;
        return g_qim + (((b*N_+n)*H_ + h)*W_ + w)*D_;
    } else if (mode == 3) {
        int b = u >> 12; int r = u & 4095;
        int l = r >> 6; int t = r & 63; int i = t >> 3, j = t & 7;
        int h = (l >> 3)*8 + i, w = (l & 7)*8 + j;
        return g_q1 + ((b*H_+h)*W_+w)*D_;
    } else {
        int b = u / 16896; int r = u % 16896;
        int l = r / NKV; int t = r % NKV;
        int n = t / 44; int f = t % 44; int f1 = f / 11, f2 = f % 11;
        int h, w;
        if (mode <= 2) { h = (l >> 3)*4 + f1;  w = (l & 7)*11 + f2; }
        else           { h = f1*8 + (l >> 3);  w = f2*8 + (l & 7); }
        const float* base = (mode == 1 || mode == 4) ? g_kim : g_vim;
        return base + (((b*N_+n)*FH_ + h)*FW_ + w)*D_;
    }
}

__global__ void __launch_bounds__(128) k_lnproj(
        int mode, int dst_sel,
        const float* __restrict__ lg, const float* __restrict__ lb,
        const float* __restrict__ W, const float* __restrict__ bias) {
    __shared__ __align__(16) float lnx[32][D_];
    __shared__ float sg[D_], sb[D_];
    int blk = blockIdx.x, tid = threadIdx.x;
    int warp = tid >> 5, lane = tid & 31;
    sg[tid] = lg[tid]; sb[tid] = lb[tid];
    float bias_r = bias[tid];
    float4 wv[32];
#pragma unroll
    for (int c4 = 0; c4 < 32; c4++) {
        wv[c4].x = W[(c4*4+0)*D_ + tid];
        wv[c4].y = W[(c4*4+1)*D_ + tid];
        wv[c4].z = W[(c4*4+2)*D_ + tid];
        wv[c4].w = W[(c4*4+3)*D_ + tid];
    }
    __syncthreads();
    for (int it = 0; it < 8; it++) {
        int tt = it*4 + warp;
        int u = blk*32 + tt;
        const float* src = lnproj_src(mode, u);
        float4 v = reinterpret_cast<const float4*>(src)[lane];
        float s = v.x+v.y+v.z+v.w;
        float q = v.x*v.x+v.y*v.y+v.z*v.z+v.w*v.w;
        warpRed2(s, q);
        float mean = s*(1.0f/128.0f);
        float var = fmaxf(q*(1.0f/128.0f) - mean*mean, 0.f);
        float rstd = rsqrtf(var + 1e-5f);
        int c0 = lane*4;
        lnx[tt][c0+0] = (v.x-mean)*rstd*sg[c0+0]+sb[c0+0];
        lnx[tt][c0+1] = (v.y-mean)*rstd*sg[c0+1]+sb[c0+1];
        lnx[tt][c0+2] = (v.z-mean)*rstd*sg[c0+2]+sb[c0+2];
        lnx[tt][c0+3] = (v.w-mean)*rstd*sg[c0+3]+sb[c0+3];
    }
    __syncthreads();
    float* dst = (dst_sel == 0) ? g_qtok : ((dst_sel == 1) ? g_ktok : g_vtok);
    // 4 tokens in flight -> 4 independent FMA chains
    for (int tt0 = 0; tt0 < 32; tt0 += 4) {
        const float4* x0 = reinterpret_cast<const float4*>(lnx[tt0+0]);
        const float4* x1 = reinterpret_cast<const float4*>(lnx[tt0+1]);
        const float4* x2 = reinterpret_cast<const float4*>(lnx[tt0+2]);
        const float4* x3 = reinterpret_cast<const float4*>(lnx[tt0+3]);
        float a0 = bias_r, a1 = bias_r, a2 = bias_r, a3 = bias_r;
#pragma unroll
        for (int c4 = 0; c4 < 32; c4++) {
            float4 w = wv[c4];
            float4 v0 = x0[c4], v1 = x1[c4], v2 = x2[c4], v3 = x3[c4];
            a0 += v0.x*w.x + v0.y*w.y + v0.z*w.z + v0.w*w.w;
            a1 += v1.x*w.x + v1.y*w.y + v1.z*w.z + v1.w*w.w;
            a2 += v2.x*w.x + v2.y*w.y + v2.z*w.z + v2.w*w.w;
            a3 += v3.x*w.x + v3.y*w.y + v3.z*w.z + v3.w*w.w;
        }
        int u0 = (blk*32 + tt0)*D_ + tid;
        dst[u0      ] = a0;
        dst[u0 + D_ ] = a1;
        dst[u0 + 2*D_] = a2;
        dst[u0 + 3*D_] = a3;
    }
}

// ---------------- flash attention stage 1: 384 threads, 1 q/thread -----------
__global__ void __launch_bounds__(384) k_attn1() {
    extern __shared__ float sh[];
    float* ks = sh;
    float* vs = sh + NKV*32;
    int bl = blockIdx.x, hh = blockIdx.y, tid = threadIdx.x;
    const float* kbase = g_ktok + bl*NKV*D_ + hh*32;
    const float* vbase = g_vtok + bl*NKV*D_ + hh*32;
    for (int t = tid; t < NKV*8; t += 384) {
        int kk = t >> 3, c4 = t & 7;
        reinterpret_cast<float4*>(ks)[t] = reinterpret_cast<const float4*>(kbase)[kk*32 + c4];
        reinterpret_cast<float4*>(vs)[t] = reinterpret_cast<const float4*>(vbase)[kk*32 + c4];
    }
    __syncthreads();
    const float scale = 0.17677669529663687f;
    const float* qp = g_qtok + (bl*NQ1 + tid)*D_ + hh*32;
    float q[32];
#pragma unroll
    for (int c4 = 0; c4 < 8; c4++) {
        float4 v = reinterpret_cast<const float4*>(qp)[c4];
        q[c4*4+0]=v.x*scale; q[c4*4+1]=v.y*scale; q[c4*4+2]=v.z*scale; q[c4*4+3]=v.w*scale;
    }
    float m, ssum;
    float acc[32];
    {   // seed with key 0
        const float4* kp = reinterpret_cast<const float4*>(ks);
        float s0=0.f,s1=0.f,s2=0.f,s3=0.f;
#pragma unroll
        for (int c4 = 0; c4 < 8; c4 += 4) {
            float4 k0=kp[c4], k1=kp[c4+1], k2=kp[c4+2], k3=kp[c4+3];
            s0 += q[c4*4+0]*k0.x + q[c4*4+1]*k0.y + q[c4*4+2]*k0.z + q[c4*4+3]*k0.w;
            s1 += q[c4*4+4]*k1.x + q[c4*4+5]*k1.y + q[c4*4+6]*k1.z + q[c4*4+7]*k1.w;
            s2 += q[c4*4+8]*k2.x + q[c4*4+9]*k2.y + q[c4*4+10]*k2.z + q[c4*4+11]*k2.w;
            s3 += q[c4*4+12]*k3.x + q[c4*4+13]*k3.y + q[c4*4+14]*k3.z + q[c4*4+15]*k3.w;
        }
        m = (s0+s1)+(s2+s3);
        ssum = 1.f;
        const float4* vp = reinterpret_cast<const float4*>(vs);
#pragma unroll
        for (int c4 = 0; c4 < 8; c4++) {
            float4 vv = vp[c4];
            acc[c4*4+0]=vv.x; acc[c4*4+1]=vv.y; acc[c4*4+2]=vv.z; acc[c4*4+3]=vv.w;
        }
    }
    for (int kk = 1; kk < NKV; kk++) {
        const float4* kp = reinterpret_cast<const float4*>(ks + kk*32);
        float s0=0.f,s1=0.f,s2=0.f,s3=0.f;
#pragma unroll
        for (int c4 = 0; c4 < 8; c4 += 4) {
            float4 k0=kp[c4], k1=kp[c4+1], k2=kp[c4+2], k3=kp[c4+3];
            s0 += q[c4*4+0]*k0.x + q[c4*4+1]*k0.y + q[c4*4+2]*k0.z + q[c4*4+3]*k0.w;
            s1 += q[c4*4+4]*k1.x + q[c4*4+5]*k1.y + q[c4*4+6]*k1.z + q[c4*4+7]*k1.w;
            s2 += q[c4*4+8]*k2.x + q[c4*4+9]*k2.y + q[c4*4+10]*k2.z + q[c4*4+11]*k2.w;
            s3 += q[c4*4+12]*k3.x + q[c4*4+13]*k3.y + q[c4*4+14]*k3.z + q[c4*4+15]*k3.w;
        }
        float s = (s0+s1)+(s2+s3);
        const float4* vp = reinterpret_cast<const float4*>(vs + kk*32);
        if (s <= m) {
            float p = __expf(s - m);
            ssum += p;
#pragma unroll
            for (int c4 = 0; c4 < 8; c4++) {
                float4 vv = vp[c4];
                acc[c4*4+0] += p*vv.x; acc[c4*4+1] += p*vv.y;
                acc[c4*4+2] += p*vv.z; acc[c4*4+3] += p*vv.w;
            }
        } else {
            float corr = __expf(m - s);
            m = s;
            ssum = ssum*corr + 1.f;
#pragma unroll
            for (int c4 = 0; c4 < 8; c4++) {
                float4 vv = vp[c4];
                acc[c4*4+0] = acc[c4*4+0]*corr + vv.x;
                acc[c4*4+1] = acc[c4*4+1]*corr + vv.y;
                acc[c4*4+2] = acc[c4*4+2]*corr + vv.z;
                acc[c4*4+3] = acc[c4*4+3]*corr + vv.w;
            }
        }
    }
    float inv = 1.0f / ssum;
    float* op = g_otok + (bl*NQ1 + tid)*D_ + hh*32;
#pragma unroll
    for (int c4 = 0; c4 < 8; c4++) {
        float4 o;
        o.x = acc[c4*4+0]*inv; o.y = acc[c4*4+1]*inv;
        o.z = acc[c4*4+2]*inv; o.w = acc[c4*4+3]*inv;
        reinterpret_cast<float4*>(op)[c4] = o;
    }
}

// ---------------- flash attention stage 2: 64 q, split-KV x4 -----------------
__global__ void __launch_bounds__(256) k_attn2() {
    extern __shared__ float sh[];
    float* ks = sh;                       // 8448
    float* vs = sh + NKV*32;              // 8448
    float* pacc = sh + NKV*64;            // 4*64*32 = 8192
    float* pm = pacc + 8192;              // 256
    float* psum = pm + 256;               // 256
    int bl = blockIdx.x, hh = blockIdx.y, tid = threadIdx.x;
    int part = tid >> 6, q = tid & 63;
    const float* kbase = g_ktok + bl*NKV*D_ + hh*32;
    const float* vbase = g_vtok + bl*NKV*D_ + hh*32;
    for (int t = tid; t < NKV*8; t += 256) {
        int kk = t >> 3, c4 = t & 7;
        reinterpret_cast<float4*>(ks)[t] = reinterpret_cast<const float4*>(kbase)[kk*32 + c4];
        reinterpret_cast<float4*>(vs)[t] = reinterpret_cast<const float4*>(vbase)[kk*32 + c4];
    }
    __syncthreads();
    const float scale = 0.17677669529663687f;
    const float* qp = g_qtok + (bl*64 + q)*D_ + hh*32;
    float qr[32];
#pragma unroll
    for (int c4 = 0; c4 < 8; c4++) {
        float4 v = reinterpret_cast<const float4*>(qp)[c4];
        qr[c4*4+0]=v.x*scale; qr[c4*4+1]=v.y*scale; qr[c4*4+2]=v.z*scale; qr[c4*4+3]=v.w*scale;
    }
    float m, ssum;
    float acc[32];
    int kk0 = part*66;
    {
        const float4* kp = reinterpret_cast<const float4*>(ks + kk0*32);
        float s0=0.f,s1=0.f,s2=0.f,s3=0.f;
#pragma unroll
        for (int c4 = 0; c4 < 8; c4 += 4) {
            float4 k0=kp[c4], k1=kp[c4+1], k2=kp[c4+2], k3=kp[c4+3];
            s0 += qr[c4*4+0]*k0.x + qr[c4*4+1]*k0.y + qr[c4*4+2]*k0.z + qr[c4*4+3]*k0.w;
            s1 += qr[c4*4+4]*k1.x + qr[c4*4+5]*k1.y + qr[c4*4+6]*k1.z + qr[c4*4+7]*k1.w;
            s2 += qr[c4*4+8]*k2.x + qr[c4*4+9]*k2.y + qr[c4*4+10]*k2.z + qr[c4*4+11]*k2.w;
            s3 += qr[c4*4+12]*k3.x + qr[c4*4+13]*k3.y + qr[c4*4+14]*k3.z + qr[c4*4+15]*k3.w;
        }
        m = (s0+s1)+(s2+s3);
        ssum = 1.f;
        const float4* vp = reinterpret_cast<const float4*>(vs + kk0*32);
#pragma unroll
        for (int c4 = 0; c4 < 8; c4++) {
            float4 vv = vp[c4];
            acc[c4*4+0]=vv.x; acc[c4*4+1]=vv.y; acc[c4*4+2]=vv.z; acc[c4*4+3]=vv.w;
        }
    }
    for (int kk = kk0+1; kk < kk0 + 66; kk++) {
        const float4* kp = reinterpret_cast<const float4*>(ks + kk*32);
        float s0=0.f,s1=0.f,s2=0.f,s3=0.f;
#pragma unroll
        for (int c4 = 0; c4 < 8; c4 += 4) {
            float4 k0=kp[c4], k1=kp[c4+1], k2=kp[c4+2], k3=kp[c4+3];
            s0 += qr[c4*4+0]*k0.x + qr[c4*4+1]*k0.y + qr[c4*4+2]*k0.z + qr[c4*4+3]*k0.w;
            s1 += qr[c4*4+4]*k1.x + qr[c4*4+5]*k1.y + qr[c4*4+6]*k1.z + qr[c4*4+7]*k1.w;
            s2 += qr[c4*4+8]*k2.x + qr[c4*4+9]*k2.y + qr[c4*4+10]*k2.z + qr[c4*4+11]*k2.w;
            s3 += qr[c4*4+12]*k3.x + qr[c4*4+13]*k3.y + qr[c4*4+14]*k3.z + qr[c4*4+15]*k3.w;
        }
        float s = (s0+s1)+(s2+s3);
        const float4* vp = reinterpret_cast<const float4*>(vs + kk*32);
        if (s <= m) {
            float p = __expf(s - m);
            ssum += p;
#pragma unroll
            for (int c4 = 0; c4 < 8; c4++) {
                float4 vv = vp[c4];
                acc[c4*4+0] += p*vv.x; acc[c4*4+1] += p*vv.y;
                acc[c4*4+2] += p*vv.z; acc[c4*4+3] += p*vv.w;
            }
        } else {
            float corr = __expf(m - s);
            m = s;
            ssum = ssum*corr + 1.f;
#pragma unroll
            for (int c4 = 0; c4 < 8; c4++) {
                float4 vv = vp[c4];
                acc[c4*4+0] = acc[c4*4+0]*corr + vv.x;
                acc[c4*4+1] = acc[c4*4+1]*corr + vv.y;
                acc[c4*4+2] = acc[c4*4+2]*corr + vv.z;
                acc[c4*4+3] = acc[c4*4+3]*corr + vv.w;
            }
        }
    }
    pm[part*64+q] = m;
    psum[part*64+q] = ssum;
    float* pa = pacc + (part*64+q)*32;
#pragma unroll
    for (int c4 = 0; c4 < 8; c4++) {
        float4 o; o.x=acc[c4*4]; o.y=acc[c4*4+1]; o.z=acc[c4*4+2]; o.w=acc[c4*4+3];
        reinterpret_cast<float4*>(pa)[c4] = o;
    }
    __syncthreads();
    {
        int qq = tid & 63, cg = tid >> 6;
        float M = fmaxf(fmaxf(pm[qq], pm[64+qq]), fmaxf(pm[128+qq], pm[192+qq]));
        float w0 = __expf(pm[qq]-M),      w1 = __expf(pm[64+qq]-M);
        float w2 = __expf(pm[128+qq]-M),  w3 = __expf(pm[192+qq]-M);
        float S = w0*psum[qq] + w1*psum[64+qq] + w2*psum[128+qq] + w3*psum[192+qq];
        float inv = 1.0f / S;
        float* op = g_otok + (bl*64 + qq)*D_ + hh*32 + cg*8;
#pragma unroll
        for (int c = 0; c < 8; c++) {
            float o = w0*pacc[(qq)*32 + cg*8 + c]
                    + w1*pacc[(64+qq)*32 + cg*8 + c]
                    + w2*pacc[(128+qq)*32 + cg*8 + c]
                    + w3*pacc[(192+qq)*32 + cg*8 + c];
            op[c] = o*inv;
        }
    }
}

// ---------------- output proj + camera mean + skip, tiled --------------------
__global__ void __launch_bounds__(128) k_projout(
        int stage, const float* __restrict__ Wp,
        const float* __restrict__ bp, const float* __restrict__ x) {
    __shared__ __align__(16) float mvec[32][D_];
    int blk = blockIdx.x, tid = threadIdx.x;
    float bp_r = bp[tid];
    float4 wv[32];
#pragma unroll
    for (int c4 = 0; c4 < 32; c4++) {
        wv[c4].x = Wp[(c4*4+0)*D_ + tid];
        wv[c4].y = Wp[(c4*4+1)*D_ + tid];
        wv[c4].z = Wp[(c4*4+2)*D_ + tid];
        wv[c4].w = Wp[(c4*4+3)*D_ + tid];
    }
    for (int tt = 0; tt < 32; tt++) {
        int u = blk*32 + tt;
        int b = u >> 12, p = u & 4095;
        int hh = p >> 6, ww = p & 63;
        int i = hh & 7, j = ww & 7;
        int l = (hh >> 3)*8 + (ww >> 3);
        if (stage == 0) {
            float a = 0.f;
#pragma unroll
            for (int n = 0; n < N_; n++)
                a += g_otok[((b*64+l)*NQ1 + n*64 + i*8 + j)*D_ + tid];
            mvec[tt][tid] = a * (1.0f/6.0f);
        } else {
            mvec[tt][tid] = g_otok[((b*64+l)*64 + i*8 + j)*D_ + tid];
        }
    }
    __syncthreads();
    for (int tt0 = 0; tt0 < 32; tt0 += 4) {
        const float4* x0 = reinterpret_cast<const float4*>(mvec[tt0+0]);
        const float4* x1 = reinterpret_cast<const float4*>(mvec[tt0+1]);
        const float4* x2 = reinterpret_cast<const float4*>(mvec[tt0+2]);
        const float4* x3 = reinterpret_cast<const float4*>(mvec[tt0+3]);
        float a0 = bp_r, a1 = bp_r, a2 = bp_r, a3 = bp_r;
#pragma unroll
        for (int c4 = 0; c4 < 32; c4++) {
            float4 w = wv[c4];
            float4 v0 = x0[c4], v1 = x1[c4], v2 = x2[c4], v3 = x3[c4];
            a0 += v0.x*w.x + v0.y*w.y + v0.z*w.z + v0.w*w.w;
            a1 += v1.x*w.x + v1.y*w.y + v1.z*w.z + v1.w*w.w;
            a2 += v2.x*w.x + v2.y*w.y + v2.z*w.z + v2.w*w.w;
            a3 += v3.x*w.x + v3.y*w.y + v3.z*w.z + v3.w*w.w;
        }
        float accs[4] = {a0, a1, a2, a3};
#pragma unroll
        for (int i = 0; i < 4; i++) {
            int u = blk*32 + tt0 + i;
            int b = u >> 12, p = u & 4095;
            float sk = (stage == 0) ? x[(b*D_+tid)*4096 + p] : g_q1[u*D_ + tid];
            float* dst = (stage == 0) ? g_q1 : g_q2;
            dst[u*D_ + tid] = accs[i] + sk;
        }
    }
}

// ---------------- MLP, tiled 16 tokens/block, 256 threads --------------------
__global__ void __launch_bounds__(256) k_mlp(
        int which,
        const float* __restrict__ lg, const float* __restrict__ lb,
        const float* __restrict__ Wa, const float* __restrict__ ba,
        const float* __restrict__ Wb, const float* __restrict__ bb) {
    __shared__ __align__(16) float lnx[16][D_];      // reused as pbuf in phase B
    __shared__ __align__(16) float gh[16][256];
    float* buf = (which == 0) ? g_q1 : g_q2;
    int blk = blockIdx.x, tid = threadIdx.x;
    int warp = tid >> 5, lane = tid & 31;
    for (int it = 0; it < 2; it++) {
        int tt = it*8 + warp;
        int u = blk*16 + tt;
        float4 v = reinterpret_cast<const float4*>(buf + u*D_)[lane];
        float s = v.x+v.y+v.z+v.w;
        float q = v.x*v.x+v.y*v.y+v.z*v.z+v.w*v.w;
        warpRed2(s, q);
        float mean = s*(1.0f/128.0f);
        float var = fmaxf(q*(1.0f/128.0f) - mean*mean, 0.f);
        float rstd = rsqrtf(var + 1e-5f);
        int c0 = lane*4;
        lnx[tt][c0+0] = (v.x-mean)*rstd*lg[c0+0]+lb[c0+0];
        lnx[tt][c0+1] = (v.y-mean)*rstd*lg[c0+1]+lb[c0+1];
        lnx[tt][c0+2] = (v.z-mean)*rstd*lg[c0+2]+lb[c0+2];
        lnx[tt][c0+3] = (v.w-mean)*rstd*lg[c0+3]+lb[c0+3];
    }
    __syncthreads();
    // Phase A: h = gelu(lnx @ Wa + ba); thread owns hidden col tid, 4-token ILP
    {
        float4 wa[32];
#pragma unroll
        for (int c4 = 0; c4 < 32; c4++) {
            wa[c4].x = Wa[(c4*4+0)*256 + tid];
            wa[c4].y = Wa[(c4*4+1)*256 + tid];
            wa[c4].z = Wa[(c4*4+2)*256 + tid];
            wa[c4].w = Wa[(c4*4+3)*256 + tid];
        }
        float ba_r = ba[tid];
        for (int tt0 = 0; tt0 < 16; tt0 += 4) {
            const float4* x0 = reinterpret_cast<const float4*>(lnx[tt0+0]);
            const float4* x1 = reinterpret_cast<const float4*>(lnx[tt0+1]);
            const float4* x2 = reinterpret_cast<const float4*>(lnx[tt0+2]);
            const float4* x3 = reinterpret_cast<const float4*>(lnx[tt0+3]);
            float a0 = ba_r, a1 = ba_r, a2 = ba_r, a3 = ba_r;
#pragma unroll
            for (int c4 = 0; c4 < 32; c4++) {
                float4 w = wa[c4];
                float4 v0 = x0[c4], v1 = x1[c4], v2 = x2[c4], v3 = x3[c4];
                a0 += v0.x*w.x + v0.y*w.y + v0.z*w.z + v0.w*w.w;
                a1 += v1.x*w.x + v1.y*w.y + v1.z*w.z + v1.w*w.w;
                a2 += v2.x*w.x + v2.y*w.y + v2.z*w.z + v2.w*w.w;
                a3 += v3.x*w.x + v3.y*w.y + v3.z*w.z + v3.w*w.w;
            }
            gh[tt0+0][tid] = a0 * 0.5f * (1.0f + erff(a0*0.70710678118654752f));
            gh[tt0+1][tid] = a1 * 0.5f * (1.0f + erff(a1*0.70710678118654752f));
            gh[tt0+2][tid] = a2 * 0.5f * (1.0f + erff(a2*0.70710678118654752f));
            gh[tt0+3][tid] = a3 * 0.5f * (1.0f + erff(a3*0.70710678118654752f));
        }
    }
    __syncthreads();
    // Phase B: out = x + gh @ Wb + bb; thread (o = tid&127, half = tid>>7)
    {
        int o = tid & 127, half = tid >> 7;
        float4 wb[32];
#pragma unroll
        for (int c4 = 0; c4 < 32; c4++) {
            wb[c4].x = Wb[(half*128 + c4*4+0)*D_ + o];
            wb[c4].y = Wb[(half*128 + c4*4+1)*D_ + o];
            wb[c4].z = Wb[(half*128 + c4*4+2)*D_ + o];
            wb[c4].w = Wb[(half*128 + c4*4+3)*D_ + o];
        }
        float accs[16];
        for (int tt0 = 0; tt0 < 16; tt0 += 4) {
            const float4* h0 = reinterpret_cast<const float4*>(&gh[tt0+0][half*128]);
            const float4* h1 = reinterpret_cast<const float4*>(&gh[tt0+1][half*128]);
            const float4* h2 = reinterpret_cast<const float4*>(&gh[tt0+2][half*128]);
            const float4* h3 = reinterpret_cast<const float4*>(&gh[tt0+3][half*128]);
            float a0 = 0.f, a1 = 0.f, a2 = 0.f, a3 = 0.f;
#pragma unroll
            for (int c4 = 0; c4 < 32; c4++) {
                float4 w = wb[c4];
                float4 v0 = h0[c4], v1 = h1[c4], v2 = h2[c4], v3 = h3[c4];
                a0 += v0.x*w.x + v0.y*w.y + v0.z*w.z + v0.w*w.w;
                a1 += v1.x*w.x + v1.y*w.y + v1.z*w.z + v1.w*w.w;
                a2 += v2.x*w.x + v2.y*w.y + v2.z*w.z + v2.w*w.w;
                a3 += v3.x*w.x + v3.y*w.y + v3.z*w.z + v3.w*w.w;
            }
            accs[tt0+0]=a0; accs[tt0+1]=a1; accs[tt0+2]=a2; accs[tt0+3]=a3;
        }
        __syncthreads();
        float* pbuf = &lnx[0][0];     // reuse
        if (half == 1) {
            for (int tt = 0; tt < 16; tt++) pbuf[tt*D_ + o] = accs[tt];
        }
        __syncthreads();
        if (half == 0) {
            float bb_r = bb[o];
            for (int tt = 0; tt < 16; tt++) {
                int u = blk*16 + tt;
                buf[u*D_ + o] = buf[u*D_ + o] + bb_r + accs[tt] + pbuf[tt*D_ + o];
            }
        }
    }
}

// ---------------- final LN + transpose ---------------------------------------
__global__ void k_final(const float* __restrict__ pg, const float* __restrict__ pb,
                        float* __restrict__ out) {
    int blk = blockIdx.x, tid = threadIdx.x;
    int b = blk / (H_*W_), p = blk % (H_*W_);
    __shared__ float red[4];
    float v = g_q2[blk*D_+tid];
    float mean = blkSum128(v, red)*(1.0f/128.0f);
    float dv = v - mean;
    float var = blkSum128(dv*dv, red)*(1.0f/128.0f);
    out[(b*D_+tid)*(H_*W_) + p] = dv*rsqrtf(var+1e-5f)*pg[tid]+pb[tid];
}

// ---------------------------------------------------------------------------
extern "C" void kernel_launch(void* const* d_in, const int* in_sizes, int n_in,
                              void* d_out, int out_size) {
    (void)in_sizes; (void)n_in; (void)out_size;
    const float* x        = (const float*)d_in[1];
    const float* grid     = (const float*)d_in[2];
    const float* feature  = (const float*)d_in[3];
    const float* I_inv    = (const float*)d_in[4];
    const float* E_inv    = (const float*)d_in[5];
    const float* bn_fl_g  = (const float*)d_in[6];
    const float* bn_fl_b  = (const float*)d_in[7];
    const float* W_fl     = (const float*)d_in[8];
    const float* bn_fp_g  = (const float*)d_in[9];
    const float* bn_fp_b  = (const float*)d_in[10];
    const float* W_fp     = (const float*)d_in[11];
    const float* W_bev    = (const float*)d_in[12];
    const float* b_bev    = (const float*)d_in[13];
    const float* W_img    = (const float*)d_in[14];
    const float* W_cam    = (const float*)d_in[15];
    const float* aln_g    = (const float*)d_in[16];
    const float* aln_b    = (const float*)d_in[17];
    const float* aWqkv    = (const float*)d_in[18];
    const float* abqkv    = (const float*)d_in[19];
    const float* aWp      = (const float*)d_in[20];
    const float* abp      = (const float*)d_in[21];
    const float* pn_g     = (const float*)d_in[22];
    const float* pn_b     = (const float*)d_in[23];
    const float* Wma      = (const float*)d_in[24];
    const float* bma      = (const float*)d_in[25];
    const float* Wmb      = (const float*)d_in[26];
    const float* bmb      = (const float*)d_in[27];
    const float* post_g   = (const float*)d_in[28];
    const float* post_b   = (const float*)d_in[29];
    float* out = (float*)d_out;

    cudaFuncSetAttribute(k_keyval, cudaFuncAttributeMaxDynamicSharedMemorySize, 49152);
    cudaFuncSetAttribute(k_attn1, cudaFuncAttributeMaxDynamicSharedMemorySize, NKV*32*2*(int)sizeof(float));
    cudaFuncSetAttribute(k_attn2, cudaFuncAttributeMaxDynamicSharedMemorySize, 102400);

    k_cembed<<<B_*N_, 128>>>(E_inv, W_cam);
    k_keyval<<<B_*N_*88, 128, 49152>>>(feature, I_inv, E_inv, W_img,
                                       bn_fp_g, bn_fp_b, W_fp,
                                       bn_fl_g, bn_fl_b, W_fl);
    k_query<<<B_*N_*H_*W_, 128>>>(grid, x, W_bev, b_bev);

    for (int s = 0; s < 2; s++) {
        int qmode = (s == 0) ? 0 : 3;
        int kmode = (s == 0) ? 1 : 4;
        int vmode = (s == 0) ? 2 : 5;
        int nqtok = (s == 0) ? B_*64*NQ1 : B_*64*64;
        k_lnproj<<<nqtok/32, 128>>>(qmode, 0,
                                    aln_g + (s*3+0)*128, aln_b + (s*3+0)*128,
                                    aWqkv + (s*3+0)*128*128, abqkv + (s*3+0)*128);
        k_lnproj<<<B_*64*NKV/32, 128>>>(kmode, 1,
                                        aln_g + (s*3+1)*128, aln_b + (s*3+1)*128,
                                        aWqkv + (s*3+1)*128*128, abqkv + (s*3+1)*128);
        k_lnproj<<<B_*64*NKV/32, 128>>>(vmode, 2,
                                        aln_g + (s*3+2)*128, aln_b + (s*3+2)*128,
                                        aWqkv + (s*3+2)*128*128, abqkv + (s*3+2)*128);
        if (s == 0)
            k_attn1<<<dim3(B_*64, 4), 384, NKV*32*2*sizeof(float)>>>();
        else
            k_attn2<<<dim3(B_*64, 4), 256, 102400>>>();
        k_projout<<<B_*H_*W_/32, 128>>>(s, aWp + s*128*128, abp + s*128, x);
        k_mlp<<<B_*H_*W_/16, 256>>>(s, pn_g + s*128, pn_b + s*128,
                                    Wma + s*128*256, bma + s*256,
                                    Wmb + s*256*128, bmb + s*128);
    }
    k_final<<<B_*H_*W_, 128>>>(post_g, post_b, out);
}

// round 4
// speedup vs baseline: 2.7870x; 1.3048x over previous
#include <cuda_runtime.h>
#include <cuda_fp16.h>
#include <math.h>
#include <stdint.h>

#define B_   2
#define N_   6
#define H_   64
#define W_   64
#define FH_  32
#define FW_  88
#define PIX  (FH_*FW_)     // 2816
#define D_   128
#define NKV  264
#define NQ1  384

// ---------------- scratch globals (no runtime allocation) -------------------
__device__ float  g_cembed[B_*N_*D_];
__device__ __half g_xq [B_*N_*4096*D_];    // LN'd (un-gamma'd) query, dense pixel order
__device__ __half g_xk [B_*N_*PIX*D_];
__device__ __half g_xv [B_*N_*PIX*D_];
__device__ __half g_xq1[B_*4096*D_];
__device__ __half g_wfold[6*D_*D_];        // folded weights, [o][c] (B^T)
__device__ float  g_bfold[6*D_];
__device__ float  g_qp1[B_*N_*4096*D_];
__device__ float  g_kp1[B_*N_*PIX*D_];
__device__ float  g_vp1[B_*N_*PIX*D_];
__device__ float  g_qp2[B_*4096*D_];
__device__ float  g_kp2[B_*N_*PIX*D_];
__device__ float  g_vp2[B_*N_*PIX*D_];
__device__ float  g_otok[B_*64*NQ1*D_];
__device__ float  g_q1[B_*H_*W_*D_];
__device__ float  g_q2[B_*H_*W_*D_];

__device__ __forceinline__ float blkSum128(float v, float* red) {
#pragma unroll
    for (int o = 16; o; o >>= 1) v += __shfl_xor_sync(0xffffffffu, v, o);
    if ((threadIdx.x & 31) == 0) red[threadIdx.x >> 5] = v;
    __syncthreads();
    float s = red[0] + red[1] + red[2] + red[3];
    __syncthreads();
    return s;
}

__device__ __forceinline__ void warpRed2(float& s, float& q) {
#pragma unroll
    for (int o = 16; o; o >>= 1) {
        s += __shfl_xor_sync(0xffffffffu, s, o);
        q += __shfl_xor_sync(0xffffffffu, q, o);
    }
}

__device__ __forceinline__ void st_half4(__half* dst, float a, float b, float c, float d) {
    __half2* p = reinterpret_cast<__half2*>(dst);
    p[0] = __floats2half2_rn(a, b);
    p[1] = __floats2half2_rn(c, d);
}

__device__ __forceinline__ void mma16816(float* c, const uint32_t* a,
                                         uint32_t b0, uint32_t b1) {
    asm volatile(
        "mma.sync.aligned.m16n8k16.row.col.f32.f16.f16.f32 "
        "{%0,%1,%2,%3}, {%4,%5,%6,%7}, {%8,%9}, {%0,%1,%2,%3};\n"
        : "+f"(c[0]), "+f"(c[1]), "+f"(c[2]), "+f"(c[3])
        : "r"(a[0]), "r"(a[1]), "r"(a[2]), "r"(a[3]), "r"(b0), "r"(b1));
}

// ---------------- camera embedding ------------------------------------------
__global__ void k_cembed(const float* __restrict__ E_inv,
                         const float* __restrict__ W_cam) {
    int bn = blockIdx.x, o = threadIdx.x;
    float acc = 0.f;
#pragma unroll
    for (int i = 0; i < 4; i++) acc += W_cam[o*4+i] * E_inv[bn*16 + i*4 + 3];
    g_cembed[bn*D_ + o] = acc;
}

// ---------------- key/val image features -> LN'd fp16 xhat ------------------
__global__ void __launch_bounds__(128) k_keyval(
        const float* __restrict__ feat,
        const float* __restrict__ I_inv, const float* __restrict__ E_inv,
        const float* __restrict__ W_img,
        const float* __restrict__ fp_g, const float* __restrict__ fp_b,
        const float* __restrict__ W_fp,
        const float* __restrict__ fl_g, const float* __restrict__ fl_b,
        const float* __restrict__ W_fl) {
    extern __shared__ float sh[];
    float* sfp  = sh;            // [128 ch][32 px]
    float* sfl  = sh + 4096;
    float* kbuf = sh + 8192;     // [32 px][128 ch]
    int blk = blockIdx.x, tid = threadIdx.x;
    int bn = blk / 88, p0 = (blk % 88) * 32;
    int warp = tid >> 5, lane = tid & 31;

    const float invs = rsqrtf(1.0f + 1e-5f);
    for (int k = tid; k < 4096; k += 128) {
        int c = k >> 5, pp = k & 31;
        float f = feat[(bn*D_ + c)*PIX + p0 + pp];
        sfp[k] = fmaxf(f * invs * fp_g[c] + fp_b[c], 0.f);
        sfl[k] = fmaxf(f * invs * fl_g[c] + fl_b[c], 0.f);
    }
    // img embed per pixel -> kbuf
    for (int it = 0; it < 8; it++) {
        int tt = it*4 + warp;
        int p = p0 + tt, fh = p / FW_, fw = p % FW_;
        float px = (float)fw * (480.0f / 87.0f);
        float py = (float)fh * (224.0f / 31.0f);
        float cam[4];
#pragma unroll
        for (int i = 0; i < 3; i++)
            cam[i] = I_inv[bn*9+i*3+0]*px + I_inv[bn*9+i*3+1]*py + I_inv[bn*9+i*3+2];
        cam[3] = 1.0f;
        float dd[4];
#pragma unroll
        for (int i = 0; i < 4; i++)
            dd[i] = E_inv[bn*16+i*4+0]*cam[0] + E_inv[bn*16+i*4+1]*cam[1]
                  + E_inv[bn*16+i*4+2]*cam[2] + E_inv[bn*16+i*4+3]*cam[3];
        int c0 = lane*4;
        float t[4]; float ssum = 0.f, dum = 0.f;
#pragma unroll
        for (int i = 0; i < 4; i++) {
            int c = c0+i;
            float de = W_img[c*4+0]*dd[0] + W_img[c*4+1]*dd[1]
                     + W_img[c*4+2]*dd[2] + W_img[c*4+3]*dd[3];
            t[i] = de - g_cembed[bn*D_+c];
            ssum += t[i]*t[i];
        }
        warpRed2(ssum, dum);
        float inv = 1.0f / fmaxf(sqrtf(ssum), 1e-12f);
#pragma unroll
        for (int i = 0; i < 4; i++) kbuf[tt*D_ + c0 + i] = t[i]*inv;
    }
    __syncthreads();
    // K conv accumulate into kbuf
    {
        float wreg[128];
        const float4* w4 = reinterpret_cast<const float4*>(W_fp + tid*D_);
#pragma unroll
        for (int c4 = 0; c4 < 32; c4++) {
            float4 w = w4[c4];
            wreg[c4*4+0]=w.x; wreg[c4*4+1]=w.y; wreg[c4*4+2]=w.z; wreg[c4*4+3]=w.w;
        }
        const float4* sx4 = reinterpret_cast<const float4*>(sfp);
#pragma unroll
        for (int pg = 0; pg < 4; pg++) {
            float acc[8];
#pragma unroll
            for (int j = 0; j < 8; j++) acc[j] = 0.f;
            for (int c = 0; c < 128; c++) {
                float w = wreg[c];
                float4 a = sx4[c*8 + pg*2];
                float4 b = sx4[c*8 + pg*2 + 1];
                acc[0] += w*a.x; acc[1] += w*a.y; acc[2] += w*a.z; acc[3] += w*a.w;
                acc[4] += w*b.x; acc[5] += w*b.y; acc[6] += w*b.z; acc[7] += w*b.w;
            }
#pragma unroll
            for (int j = 0; j < 8; j++)
                kbuf[(pg*8+j)*D_ + tid] += acc[j];
        }
    }
    __syncthreads();
    // LN K -> g_xk (fp16, no gamma/beta: folded into weights)
    for (int it = 0; it < 8; it++) {
        int tt = it*4 + warp;
        float4 v = reinterpret_cast<const float4*>(&kbuf[tt*D_])[lane];
        float s = v.x+v.y+v.z+v.w;
        float q = v.x*v.x+v.y*v.y+v.z*v.z+v.w*v.w;
        warpRed2(s, q);
        float mean = s*(1.0f/128.0f);
        float var = fmaxf(q*(1.0f/128.0f) - mean*mean, 0.f);
        float rstd = rsqrtf(var + 1e-5f);
        st_half4(&g_xk[(bn*PIX + p0 + tt)*D_ + lane*4],
                 (v.x-mean)*rstd, (v.y-mean)*rstd, (v.z-mean)*rstd, (v.w-mean)*rstd);
    }
    __syncthreads();
    // V conv -> kbuf
    {
        float wreg[128];
        const float4* w4 = reinterpret_cast<const float4*>(W_fl + tid*D_);
#pragma unroll
        for (int c4 = 0; c4 < 32; c4++) {
            float4 w = w4[c4];
            wreg[c4*4+0]=w.x; wreg[c4*4+1]=w.y; wreg[c4*4+2]=w.z; wreg[c4*4+3]=w.w;
        }
        const float4* sx4 = reinterpret_cast<const float4*>(sfl);
#pragma unroll
        for (int pg = 0; pg < 4; pg++) {
            float acc[8];
#pragma unroll
            for (int j = 0; j < 8; j++) acc[j] = 0.f;
            for (int c = 0; c < 128; c++) {
                float w = wreg[c];
                float4 a = sx4[c*8 + pg*2];
                float4 b = sx4[c*8 + pg*2 + 1];
                acc[0] += w*a.x; acc[1] += w*a.y; acc[2] += w*a.z; acc[3] += w*a.w;
                acc[4] += w*b.x; acc[5] += w*b.y; acc[6] += w*b.z; acc[7] += w*b.w;
            }
#pragma unroll
            for (int j = 0; j < 8; j++)
                kbuf[(pg*8+j)*D_ + tid] = acc[j];
        }
    }
    __syncthreads();
    // LN V -> g_xv
    for (int it = 0; it < 8; it++) {
        int tt = it*4 + warp;
        float4 v = reinterpret_cast<const float4*>(&kbuf[tt*D_])[lane];
        float s = v.x+v.y+v.z+v.w;
        float q = v.x*v.x+v.y*v.y+v.z*v.z+v.w*v.w;
        warpRed2(s, q);
        float mean = s*(1.0f/128.0f);
        float var = fmaxf(q*(1.0f/128.0f) - mean*mean, 0.f);
        float rstd = rsqrtf(var + 1e-5f);
        st_half4(&g_xv[(bn*PIX + p0 + tt)*D_ + lane*4],
                 (v.x-mean)*rstd, (v.y-mean)*rstd, (v.z-mean)*rstd, (v.w-mean)*rstd);
    }
}

// ---------------- query -> LN'd fp16 xhat ------------------------------------
__global__ void k_query(const float* __restrict__ grid,
                        const float* __restrict__ x,
                        const float* __restrict__ W_bev,
                        const float* __restrict__ b_bev) {
    int blk = blockIdx.x;
    int bn = blk / (H_*W_), p = blk % (H_*W_);
    int b = bn / N_;
    int tid = threadIdx.x;
    __shared__ float red[4];
    float we = W_bev[tid*2+0]*grid[p] + W_bev[tid*2+1]*grid[H_*W_ + p] + b_bev[tid];
    float t = we - g_cembed[bn*D_+tid];
    float ss = blkSum128(t*t, red);
    float bev = t / fmaxf(sqrtf(ss), 1e-12f);
    float q = bev + x[(b*D_+tid)*(H_*W_) + p];
    float mean = blkSum128(q, red)*(1.0f/128.0f);
    float dv = q - mean;
    float var = blkSum128(dv*dv, red)*(1.0f/128.0f);
    g_xq[(bn*4096 + p)*D_ + tid] = __float2half(dv * rsqrtf(var + 1e-5f));
}

// ---------------- fold LN gamma/beta into projection weights -----------------
__global__ void __launch_bounds__(128) k_foldw(
        const float* __restrict__ aln_g, const float* __restrict__ aln_b,
        const float* __restrict__ aWqkv, const float* __restrict__ abqkv) {
    __shared__ __half sw[128][129];
    int idx = blockIdx.x, tid = threadIdx.x;
    const float* W = aWqkv + idx*16384;
    const float* g = aln_g + idx*128;
    const float* b = aln_b + idx*128;
    float bacc = abqkv[idx*128 + tid];
    for (int c = 0; c < 128; c++) {
        float w = W[c*128 + tid];
        sw[c][tid] = __float2half(g[c] * w);
        bacc += b[c] * w;
    }
    g_bfold[idx*128 + tid] = bacc;
    __syncthreads();
    for (int o = 0; o < 128; o++)
        g_wfold[idx*16384 + o*128 + tid] = sw[tid][o];   // Wt[o][c]
}

// ---------------- prenorm q1 -> fp16 xhat ------------------------------------
__global__ void __launch_bounds__(256) k_prenorm() {
    int blk = blockIdx.x, tid = threadIdx.x;
    int warp = tid >> 5, lane = tid & 31;
    int u = blk*8 + warp;
    float4 v = reinterpret_cast<const float4*>(g_q1 + u*D_)[lane];
    float s = v.x+v.y+v.z+v.w;
    float q = v.x*v.x+v.y*v.y+v.z*v.z+v.w*v.w;
    warpRed2(s, q);
    float mean = s*(1.0f/128.0f);
    float var = fmaxf(q*(1.0f/128.0f) - mean*mean, 0.f);
    float rstd = rsqrtf(var + 1e-5f);
    st_half4(&g_xq1[u*D_ + lane*4],
             (v.x-mean)*rstd, (v.y-mean)*rstd, (v.z-mean)*rstd, (v.w-mean)*rstd);
}

// ---------------- HMMA GEMM: C[T][128] = A[T][128] @ Wt^T + bias -------------
__global__ void __launch_bounds__(256) k_gemm(int job) {
    const __half* A; const __half* Wt; const float* bias; float* C;
    switch (job) {
        case 0: A=g_xq;  Wt=g_wfold+0*16384; bias=g_bfold+0*128; C=g_qp1; break;
        case 1: A=g_xk;  Wt=g_wfold+1*16384; bias=g_bfold+1*128; C=g_kp1; break;
        case 2: A=g_xv;  Wt=g_wfold+2*16384; bias=g_bfold+2*128; C=g_vp1; break;
        case 3: A=g_xq1; Wt=g_wfold+3*16384; bias=g_bfold+3*128; C=g_qp2; break;
        case 4: A=g_xk;  Wt=g_wfold+4*16384; bias=g_bfold+4*128; C=g_kp2; break;
        default:A=g_xv;  Wt=g_wfold+5*16384; bias=g_bfold+5*128; C=g_vp2; break;
    }
    extern __shared__ __half shh[];
    __half* As = shh;                 // [128][136]
    __half* Ws = shh + 128*136;       // [128][136]
    float* sbias = reinterpret_cast<float*>(shh + 2*128*136);
    int tid = threadIdx.x;
    int m0 = blockIdx.x * 128;
    {
        int r = tid >> 4, q = tid & 15;
        for (int rr = r; rr < 128; rr += 16) {
            *reinterpret_cast<int4*>(&As[rr*136 + q*8]) =
                *reinterpret_cast<const int4*>(&A[(m0+rr)*128 + q*8]);
            *reinterpret_cast<int4*>(&Ws[rr*136 + q*8]) =
                *reinterpret_cast<const int4*>(&Wt[rr*128 + q*8]);
        }
        if (tid < 128) sbias[tid] = bias[tid];
    }
    __syncthreads();
    int warp = tid >> 5, lane = tid & 31;
    int wm = (warp & 3) * 32;
    int wn = (warp >> 2) * 64;
    int g = lane >> 2, tg = (lane & 3) * 2;
    float acc[2][8][4];
#pragma unroll
    for (int i = 0; i < 2; i++)
#pragma unroll
        for (int j = 0; j < 8; j++)
#pragma unroll
            for (int r = 0; r < 4; r++) acc[i][j][r] = 0.f;
#pragma unroll
    for (int ks = 0; ks < 8; ks++) {
        int k0 = ks*16;
        uint32_t a[2][4];
#pragma unroll
        for (int i = 0; i < 2; i++) {
            int mb = wm + i*16;
            a[i][0] = *reinterpret_cast<const uint32_t*>(&As[(mb+g  )*136 + k0+tg  ]);
            a[i][1] = *reinterpret_cast<const uint32_t*>(&As[(mb+8+g)*136 + k0+tg  ]);
            a[i][2] = *reinterpret_cast<const uint32_t*>(&As[(mb+g  )*136 + k0+8+tg]);
            a[i][3] = *reinterpret_cast<const uint32_t*>(&As[(mb+8+g)*136 + k0+8+tg]);
        }
#pragma unroll
        for (int j = 0; j < 8; j++) {
            uint32_t b0 = *reinterpret_cast<const uint32_t*>(&Ws[(wn+j*8+g)*136 + k0+tg  ]);
            uint32_t b1 = *reinterpret_cast<const uint32_t*>(&Ws[(wn+j*8+g)*136 + k0+8+tg]);
            mma16816(acc[0][j], a[0], b0, b1);
            mma16816(acc[1][j], a[1], b0, b1);
        }
    }
#pragma unroll
    for (int i = 0; i < 2; i++) {
#pragma unroll
        for (int j = 0; j < 8; j++) {
            int m = m0 + wm + i*16 + g;
            int n = wn + j*8 + tg;
            C[m*128 + n]       = acc[i][j][0] + sbias[n];
            C[m*128 + n+1]     = acc[i][j][1] + sbias[n+1];
            C[(m+8)*128 + n]   = acc[i][j][2] + sbias[n];
            C[(m+8)*128 + n+1] = acc[i][j][3] + sbias[n+1];
        }
    }
}

// ---------------- flash attention stage 1 ------------------------------------
__global__ void __launch_bounds__(384) k_attn1() {
    extern __shared__ float sh[];
    float* ks = sh;
    float* vs = sh + NKV*32;
    int bl = blockIdx.x, hh = blockIdx.y, tid = threadIdx.x;
    int b = bl >> 6, l = bl & 63;
    for (int t = tid; t < NKV*8; t += 384) {
        int kk = t >> 3, c4 = t & 7;
        int n = kk/44, f = kk%44, f1 = f/11, f2 = f%11;
        int h = (l >> 3)*4 + f1, w = (l & 7)*11 + f2;
        int pix = (b*N_+n)*PIX + h*FW_ + w;
        reinterpret_cast<float4*>(ks)[t] =
            *reinterpret_cast<const float4*>(&g_kp1[pix*D_ + hh*32 + c4*4]);
        reinterpret_cast<float4*>(vs)[t] =
            *reinterpret_cast<const float4*>(&g_vp1[pix*D_ + hh*32 + c4*4]);
    }
    __syncthreads();
    const float scale = 0.17677669529663687f;
    int n = tid >> 6, ij = tid & 63, i = ij >> 3, j = ij & 7;
    int qpix = (b*N_+n)*4096 + ((l >> 3)*8 + i)*64 + (l & 7)*8 + j;
    const float* qp = g_qp1 + qpix*D_ + hh*32;
    float q[32];
#pragma unroll
    for (int c4 = 0; c4 < 8; c4++) {
        float4 v = reinterpret_cast<const float4*>(qp)[c4];
        q[c4*4+0]=v.x*scale; q[c4*4+1]=v.y*scale; q[c4*4+2]=v.z*scale; q[c4*4+3]=v.w*scale;
    }
    float m, ssum;
    float acc[32];
    {
        const float4* kp = reinterpret_cast<const float4*>(ks);
        float s0=0.f,s1=0.f,s2=0.f,s3=0.f;
#pragma unroll
        for (int c4 = 0; c4 < 8; c4 += 4) {
            float4 k0=kp[c4], k1=kp[c4+1], k2=kp[c4+2], k3=kp[c4+3];
            s0 += q[c4*4+0]*k0.x + q[c4*4+1]*k0.y + q[c4*4+2]*k0.z + q[c4*4+3]*k0.w;
            s1 += q[c4*4+4]*k1.x + q[c4*4+5]*k1.y + q[c4*4+6]*k1.z + q[c4*4+7]*k1.w;
            s2 += q[c4*4+8]*k2.x + q[c4*4+9]*k2.y + q[c4*4+10]*k2.z + q[c4*4+11]*k2.w;
            s3 += q[c4*4+12]*k3.x + q[c4*4+13]*k3.y + q[c4*4+14]*k3.z + q[c4*4+15]*k3.w;
        }
        m = (s0+s1)+(s2+s3);
        ssum = 1.f;
        const float4* vp = reinterpret_cast<const float4*>(vs);
#pragma unroll
        for (int c4 = 0; c4 < 8; c4++) {
            float4 vv = vp[c4];
            acc[c4*4+0]=vv.x; acc[c4*4+1]=vv.y; acc[c4*4+2]=vv.z; acc[c4*4+3]=vv.w;
        }
    }
    for (int kk = 1; kk < NKV; kk++) {
        const float4* kp = reinterpret_cast<const float4*>(ks + kk*32);
        float s0=0.f,s1=0.f,s2=0.f,s3=0.f;
#pragma unroll
        for (int c4 = 0; c4 < 8; c4 += 4) {
            float4 k0=kp[c4], k1=kp[c4+1], k2=kp[c4+2], k3=kp[c4+3];
            s0 += q[c4*4+0]*k0.x + q[c4*4+1]*k0.y + q[c4*4+2]*k0.z + q[c4*4+3]*k0.w;
            s1 += q[c4*4+4]*k1.x + q[c4*4+5]*k1.y + q[c4*4+6]*k1.z + q[c4*4+7]*k1.w;
            s2 += q[c4*4+8]*k2.x + q[c4*4+9]*k2.y + q[c4*4+10]*k2.z + q[c4*4+11]*k2.w;
            s3 += q[c4*4+12]*k3.x + q[c4*4+13]*k3.y + q[c4*4+14]*k3.z + q[c4*4+15]*k3.w;
        }
        float s = (s0+s1)+(s2+s3);
        const float4* vp = reinterpret_cast<const float4*>(vs + kk*32);
        if (s <= m) {
            float p = __expf(s - m);
            ssum += p;
#pragma unroll
            for (int c4 = 0; c4 < 8; c4++) {
                float4 vv = vp[c4];
                acc[c4*4+0] += p*vv.x; acc[c4*4+1] += p*vv.y;
                acc[c4*4+2] += p*vv.z; acc[c4*4+3] += p*vv.w;
            }
        } else {
            float corr = __expf(m - s);
            m = s;
            ssum = ssum*corr + 1.f;
#pragma unroll
            for (int c4 = 0; c4 < 8; c4++) {
                float4 vv = vp[c4];
                acc[c4*4+0] = acc[c4*4+0]*corr + vv.x;
                acc[c4*4+1] = acc[c4*4+1]*corr + vv.y;
                acc[c4*4+2] = acc[c4*4+2]*corr + vv.z;
                acc[c4*4+3] = acc[c4*4+3]*corr + vv.w;
            }
        }
    }
    float inv = 1.0f / ssum;
    float* op = g_otok + (bl*NQ1 + tid)*D_ + hh*32;
#pragma unroll
    for (int c4 = 0; c4 < 8; c4++) {
        float4 o;
        o.x = acc[c4*4+0]*inv; o.y = acc[c4*4+1]*inv;
        o.z = acc[c4*4+2]*inv; o.w = acc[c4*4+3]*inv;
        reinterpret_cast<float4*>(op)[c4] = o;
    }
}

// ---------------- flash attention stage 2: split-KV x4 -----------------------
__global__ void __launch_bounds__(256) k_attn2() {
    extern __shared__ float sh[];
    float* ks = sh;
    float* vs = sh + NKV*32;
    float* pacc = sh + NKV*64;
    float* pm = pacc + 8192;
    float* psum = pm + 256;
    int bl = blockIdx.x, hh = blockIdx.y, tid = threadIdx.x;
    int b = bl >> 6, l = bl & 63;
    int part = tid >> 6, q = tid & 63;
    for (int t = tid; t < NKV*8; t += 256) {
        int kk = t >> 3, c4 = t & 7;
        int n = kk/44, f = kk%44, f1 = f/11, f2 = f%11;
        int h = f1*8 + (l >> 3), w = f2*8 + (l & 7);
        int pix = (b*N_+n)*PIX + h*FW_ + w;
        reinterpret_cast<float4*>(ks)[t] =
            *reinterpret_cast<const float4*>(&g_kp2[pix*D_ + hh*32 + c4*4]);
        reinterpret_cast<float4*>(vs)[t] =
            *reinterpret_cast<const float4*>(&g_vp2[pix*D_ + hh*32 + c4*4]);
    }
    __syncthreads();
    const float scale = 0.17677669529663687f;
    int i = q >> 3, j = q & 7;
    int qrow = b*4096 + ((l >> 3)*8 + i)*64 + (l & 7)*8 + j;
    const float* qp = g_qp2 + qrow*D_ + hh*32;
    float qr[32];
#pragma unroll
    for (int c4 = 0; c4 < 8; c4++) {
        float4 v = reinterpret_cast<const float4*>(qp)[c4];
        qr[c4*4+0]=v.x*scale; qr[c4*4+1]=v.y*scale; qr[c4*4+2]=v.z*scale; qr[c4*4+3]=v.w*scale;
    }
    float m, ssum;
    float acc[32];
    int kk0 = part*66;
    {
        const float4* kp = reinterpret_cast<const float4*>(ks + kk0*32);
        float s0=0.f,s1=0.f,s2=0.f,s3=0.f;
#pragma unroll
        for (int c4 = 0; c4 < 8; c4 += 4) {
            float4 k0=kp[c4], k1=kp[c4+1], k2=kp[c4+2], k3=kp[c4+3];
            s0 += qr[c4*4+0]*k0.x + qr[c4*4+1]*k0.y + qr[c4*4+2]*k0.z + qr[c4*4+3]*k0.w;
            s1 += qr[c4*4+4]*k1.x + qr[c4*4+5]*k1.y + qr[c4*4+6]*k1.z + qr[c4*4+7]*k1.w;
            s2 += qr[c4*4+8]*k2.x + qr[c4*4+9]*k2.y + qr[c4*4+10]*k2.z + qr[c4*4+11]*k2.w;
            s3 += qr[c4*4+12]*k3.x + qr[c4*4+13]*k3.y + qr[c4*4+14]*k3.z + qr[c4*4+15]*k3.w;
        }
        m = (s0+s1)+(s2+s3);
        ssum = 1.f;
        const float4* vp = reinterpret_cast<const float4*>(vs + kk0*32);
#pragma unroll
        for (int c4 = 0; c4 < 8; c4++) {
            float4 vv = vp[c4];
            acc[c4*4+0]=vv.x; acc[c4*4+1]=vv.y; acc[c4*4+2]=vv.z; acc[c4*4+3]=vv.w;
        }
    }
    for (int kk = kk0+1; kk < kk0 + 66; kk++) {
        const float4* kp = reinterpret_cast<const float4*>(ks + kk*32);
        float s0=0.f,s1=0.f,s2=0.f,s3=0.f;
#pragma unroll
        for (int c4 = 0; c4 < 8; c4 += 4) {
            float4 k0=kp[c4], k1=kp[c4+1], k2=kp[c4+2], k3=kp[c4+3];
            s0 += qr[c4*4+0]*k0.x + qr[c4*4+1]*k0.y + qr[c4*4+2]*k0.z + qr[c4*4+3]*k0.w;
            s1 += qr[c4*4+4]*k1.x + qr[c4*4+5]*k1.y + qr[c4*4+6]*k1.z + qr[c4*4+7]*k1.w;
            s2 += qr[c4*4+8]*k2.x + qr[c4*4+9]*k2.y + qr[c4*4+10]*k2.z + qr[c4*4+11]*k2.w;
            s3 += qr[c4*4+12]*k3.x + qr[c4*4+13]*k3.y + qr[c4*4+14]*k3.z + qr[c4*4+15]*k3.w;
        }
        float s = (s0+s1)+(s2+s3);
        const float4* vp = reinterpret_cast<const float4*>(vs + kk*32);
        if (s <= m) {
            float p = __expf(s - m);
            ssum += p;
#pragma unroll
            for (int c4 = 0; c4 < 8; c4++) {
                float4 vv = vp[c4];
                acc[c4*4+0] += p*vv.x; acc[c4*4+1] += p*vv.y;
                acc[c4*4+2] += p*vv.z; acc[c4*4+3] += p*vv.w;
            }
        } else {
            float corr = __expf(m - s);
            m = s;
            ssum = ssum*corr + 1.f;
#pragma unroll
            for (int c4 = 0; c4 < 8; c4++) {
                float4 vv = vp[c4];
                acc[c4*4+0] = acc[c4*4+0]*corr + vv.x;
                acc[c4*4+1] = acc[c4*4+1]*corr + vv.y;
                acc[c4*4+2] = acc[c4*4+2]*corr + vv.z;
                acc[c4*4+3] = acc[c4*4+3]*corr + vv.w;
            }
        }
    }
    pm[part*64+q] = m;
    psum[part*64+q] = ssum;
    float* pa = pacc + (part*64+q)*32;
#pragma unroll
    for (int c4 = 0; c4 < 8; c4++) {
        float4 o; o.x=acc[c4*4]; o.y=acc[c4*4+1]; o.z=acc[c4*4+2]; o.w=acc[c4*4+3];
        reinterpret_cast<float4*>(pa)[c4] = o;
    }
    __syncthreads();
    {
        int qq = tid & 63, cg = tid >> 6;
        float M = fmaxf(fmaxf(pm[qq], pm[64+qq]), fmaxf(pm[128+qq], pm[192+qq]));
        float w0 = __expf(pm[qq]-M),      w1 = __expf(pm[64+qq]-M);
        float w2 = __expf(pm[128+qq]-M),  w3 = __expf(pm[192+qq]-M);
        float S = w0*psum[qq] + w1*psum[64+qq] + w2*psum[128+qq] + w3*psum[192+qq];
        float inv = 1.0f / S;
        float* op = g_otok + (bl*64 + qq)*D_ + hh*32 + cg*8;
#pragma unroll
        for (int c = 0; c < 8; c++) {
            float o = w0*pacc[(qq)*32 + cg*8 + c]
                    + w1*pacc[(64+qq)*32 + cg*8 + c]
                    + w2*pacc[(128+qq)*32 + cg*8 + c]
                    + w3*pacc[(192+qq)*32 + cg*8 + c];
            op[c] = o*inv;
        }
    }
}

// ---------------- output proj + camera mean + skip ---------------------------
__global__ void __launch_bounds__(128) k_projout(
        int stage, const float* __restrict__ Wp,
        const float* __restrict__ bp, const float* __restrict__ x) {
    __shared__ __align__(16) float mvec[32][D_];
    int blk = blockIdx.x, tid = threadIdx.x;
    float bp_r = bp[tid];
    float4 wv[32];
#pragma unroll
    for (int c4 = 0; c4 < 32; c4++) {
        wv[c4].x = Wp[(c4*4+0)*D_ + tid];
        wv[c4].y = Wp[(c4*4+1)*D_ + tid];
        wv[c4].z = Wp[(c4*4+2)*D_ + tid];
        wv[c4].w = Wp[(c4*4+3)*D_ + tid];
    }
    for (int tt = 0; tt < 32; tt++) {
        int u = blk*32 + tt;
        int b = u >> 12, p = u & 4095;
        int hh = p >> 6, ww = p & 63;
        int i = hh & 7, j = ww & 7;
        int l = (hh >> 3)*8 + (ww >> 3);
        if (stage == 0) {
            float a = 0.f;
#pragma unroll
            for (int n = 0; n < N_; n++)
                a += g_otok[((b*64+l)*NQ1 + n*64 + i*8 + j)*D_ + tid];
            mvec[tt][tid] = a * (1.0f/6.0f);
        } else {
            mvec[tt][tid] = g_otok[((b*64+l)*64 + i*8 + j)*D_ + tid];
        }
    }
    __syncthreads();
    for (int tt0 = 0; tt0 < 32; tt0 += 4) {
        const float4* x0 = reinterpret_cast<const float4*>(mvec[tt0+0]);
        const float4* x1 = reinterpret_cast<const float4*>(mvec[tt0+1]);
        const float4* x2 = reinterpret_cast<const float4*>(mvec[tt0+2]);
        const float4* x3 = reinterpret_cast<const float4*>(mvec[tt0+3]);
        float a0 = bp_r, a1 = bp_r, a2 = bp_r, a3 = bp_r;
#pragma unroll
        for (int c4 = 0; c4 < 32; c4++) {
            float4 w = wv[c4];
            float4 v0 = x0[c4], v1 = x1[c4], v2 = x2[c4], v3 = x3[c4];
            a0 += v0.x*w.x + v0.y*w.y + v0.z*w.z + v0.w*w.w;
            a1 += v1.x*w.x + v1.y*w.y + v1.z*w.z + v1.w*w.w;
            a2 += v2.x*w.x + v2.y*w.y + v2.z*w.z + v2.w*w.w;
            a3 += v3.x*w.x + v3.y*w.y + v3.z*w.z + v3.w*w.w;
        }
        float accs[4] = {a0, a1, a2, a3};
#pragma unroll
        for (int i2 = 0; i2 < 4; i2++) {
            int u = blk*32 + tt0 + i2;
            int b = u >> 12, p = u & 4095;
            float sk = (stage == 0) ? x[(b*D_+tid)*4096 + p] : g_q1[u*D_ + tid];
            float* dst = (stage == 0) ? g_q1 : g_q2;
            dst[u*D_ + tid] = accs[i2] + sk;
        }
    }
}

// ---------------- MLP --------------------------------------------------------
__global__ void __launch_bounds__(256) k_mlp(
        int which,
        const float* __restrict__ lg, const float* __restrict__ lb,
        const float* __restrict__ Wa, const float* __restrict__ ba,
        const float* __restrict__ Wb, const float* __restrict__ bb) {
    __shared__ __align__(16) float lnx[16][D_];
    __shared__ __align__(16) float gh[16][256];
    float* buf = (which == 0) ? g_q1 : g_q2;
    int blk = blockIdx.x, tid = threadIdx.x;
    int warp = tid >> 5, lane = tid & 31;
    for (int it = 0; it < 2; it++) {
        int tt = it*8 + warp;
        int u = blk*16 + tt;
        float4 v = reinterpret_cast<const float4*>(buf + u*D_)[lane];
        float s = v.x+v.y+v.z+v.w;
        float q = v.x*v.x+v.y*v.y+v.z*v.z+v.w*v.w;
        warpRed2(s, q);
        float mean = s*(1.0f/128.0f);
        float var = fmaxf(q*(1.0f/128.0f) - mean*mean, 0.f);
        float rstd = rsqrtf(var + 1e-5f);
        int c0 = lane*4;
        lnx[tt][c0+0] = (v.x-mean)*rstd*lg[c0+0]+lb[c0+0];
        lnx[tt][c0+1] = (v.y-mean)*rstd*lg[c0+1]+lb[c0+1];
        lnx[tt][c0+2] = (v.z-mean)*rstd*lg[c0+2]+lb[c0+2];
        lnx[tt][c0+3] = (v.w-mean)*rstd*lg[c0+3]+lb[c0+3];
    }
    __syncthreads();
    {
        float4 wa[32];
#pragma unroll
        for (int c4 = 0; c4 < 32; c4++) {
            wa[c4].x = Wa[(c4*4+0)*256 + tid];
            wa[c4].y = Wa[(c4*4+1)*256 + tid];
            wa[c4].z = Wa[(c4*4+2)*256 + tid];
            wa[c4].w = Wa[(c4*4+3)*256 + tid];
        }
        float ba_r = ba[tid];
        for (int tt0 = 0; tt0 < 16; tt0 += 4) {
            const float4* x0 = reinterpret_cast<const float4*>(lnx[tt0+0]);
            const float4* x1 = reinterpret_cast<const float4*>(lnx[tt0+1]);
            const float4* x2 = reinterpret_cast<const float4*>(lnx[tt0+2]);
            const float4* x3 = reinterpret_cast<const float4*>(lnx[tt0+3]);
            float a0 = ba_r, a1 = ba_r, a2 = ba_r, a3 = ba_r;
#pragma unroll
            for (int c4 = 0; c4 < 32; c4++) {
                float4 w = wa[c4];
                float4 v0 = x0[c4], v1 = x1[c4], v2 = x2[c4], v3 = x3[c4];
                a0 += v0.x*w.x + v0.y*w.y + v0.z*w.z + v0.w*w.w;
                a1 += v1.x*w.x + v1.y*w.y + v1.z*w.z + v1.w*w.w;
                a2 += v2.x*w.x + v2.y*w.y + v2.z*w.z + v2.w*w.w;
                a3 += v3.x*w.x + v3.y*w.y + v3.z*w.z + v3.w*w.w;
            }
            gh[tt0+0][tid] = a0 * 0.5f * (1.0f + erff(a0*0.70710678118654752f));
            gh[tt0+1][tid] = a1 * 0.5f * (1.0f + erff(a1*0.70710678118654752f));
            gh[tt0+2][tid] = a2 * 0.5f * (1.0f + erff(a2*0.70710678118654752f));
            gh[tt0+3][tid] = a3 * 0.5f * (1.0f + erff(a3*0.70710678118654752f));
        }
    }
    __syncthreads();
    {
        int o = tid & 127, half = tid >> 7;
        float4 wb[32];
#pragma unroll
        for (int c4 = 0; c4 < 32; c4++) {
            wb[c4].x = Wb[(half*128 + c4*4+0)*D_ + o];
            wb[c4].y = Wb[(half*128 + c4*4+1)*D_ + o];
            wb[c4].z = Wb[(half*128 + c4*4+2)*D_ + o];
            wb[c4].w = Wb[(half*128 + c4*4+3)*D_ + o];
        }
        float accs[16];
        for (int tt0 = 0; tt0 < 16; tt0 += 4) {
            const float4* h0 = reinterpret_cast<const float4*>(&gh[tt0+0][half*128]);
            const float4* h1 = reinterpret_cast<const float4*>(&gh[tt0+1][half*128]);
            const float4* h2 = reinterpret_cast<const float4*>(&gh[tt0+2][half*128]);
            const float4* h3 = reinterpret_cast<const float4*>(&gh[tt0+3][half*128]);
            float a0 = 0.f, a1 = 0.f, a2 = 0.f, a3 = 0.f;
#pragma unroll
            for (int c4 = 0; c4 < 32; c4++) {
                float4 w = wb[c4];
                float4 v0 = h0[c4], v1 = h1[c4], v2 = h2[c4], v3 = h3[c4];
                a0 += v0.x*w.x + v0.y*w.y + v0.z*w.z + v0.w*w.w;
                a1 += v1.x*w.x + v1.y*w.y + v1.z*w.z + v1.w*w.w;
                a2 += v2.x*w.x + v2.y*w.y + v2.z*w.z + v2.w*w.w;
                a3 += v3.x*w.x + v3.y*w.y + v3.z*w.z + v3.w*w.w;
            }
            accs[tt0+0]=a0; accs[tt0+1]=a1; accs[tt0+2]=a2; accs[tt0+3]=a3;
        }
        __syncthreads();
        float* pbuf = &lnx[0][0];
        if (half == 1) {
            for (int tt = 0; tt < 16; tt++) pbuf[tt*D_ + o] = accs[tt];
        }
        __syncthreads();
        if (half == 0) {
            float bb_r = bb[o];
            for (int tt = 0; tt < 16; tt++) {
                int u = blk*16 + tt;
                buf[u*D_ + o] = buf[u*D_ + o] + bb_r + accs[tt] + pbuf[tt*D_ + o];
            }
        }
    }
}

// ---------------- final LN + transpose ---------------------------------------
__global__ void k_final(const float* __restrict__ pg, const float* __restrict__ pb,
                        float* __restrict__ out) {
    int blk = blockIdx.x, tid = threadIdx.x;
    int b = blk / (H_*W_), p = blk % (H_*W_);
    __shared__ float red[4];
    float v = g_q2[blk*D_+tid];
    float mean = blkSum128(v, red)*(1.0f/128.0f);
    float dv = v - mean;
    float var = blkSum128(dv*dv, red)*(1.0f/128.0f);
    out[(b*D_+tid)*(H_*W_) + p] = dv*rsqrtf(var+1e-5f)*pg[tid]+pb[tid];
}

// ---------------------------------------------------------------------------
extern "C" void kernel_launch(void* const* d_in, const int* in_sizes, int n_in,
                              void* d_out, int out_size) {
    (void)in_sizes; (void)n_in; (void)out_size;
    const float* x        = (const float*)d_in[1];
    const float* grid     = (const float*)d_in[2];
    const float* feature  = (const float*)d_in[3];
    const float* I_inv    = (const float*)d_in[4];
    const float* E_inv    = (const float*)d_in[5];
    const float* bn_fl_g  = (const float*)d_in[6];
    const float* bn_fl_b  = (const float*)d_in[7];
    const float* W_fl     = (const float*)d_in[8];
    const float* bn_fp_g  = (const float*)d_in[9];
    const float* bn_fp_b  = (const float*)d_in[10];
    const float* W_fp     = (const float*)d_in[11];
    const float* W_bev    = (const float*)d_in[12];
    const float* b_bev    = (const float*)d_in[13];
    const float* W_img    = (const float*)d_in[14];
    const float* W_cam    = (const float*)d_in[15];
    const float* aln_g    = (const float*)d_in[16];
    const float* aln_b    = (const float*)d_in[17];
    const float* aWqkv    = (const float*)d_in[18];
    const float* abqkv    = (const float*)d_in[19];
    const float* aWp      = (const float*)d_in[20];
    const float* abp      = (const float*)d_in[21];
    const float* pn_g     = (const float*)d_in[22];
    const float* pn_b     = (const float*)d_in[23];
    const float* Wma      = (const float*)d_in[24];
    const float* bma      = (const float*)d_in[25];
    const float* Wmb      = (const float*)d_in[26];
    const float* bmb      = (const float*)d_in[27];
    const float* post_g   = (const float*)d_in[28];
    const float* post_b   = (const float*)d_in[29];
    float* out = (float*)d_out;

    const int GSM = 2*128*136*2 + 512;   // 70144
    cudaFuncSetAttribute(k_keyval, cudaFuncAttributeMaxDynamicSharedMemorySize, 49152);
    cudaFuncSetAttribute(k_gemm, cudaFuncAttributeMaxDynamicSharedMemorySize, GSM);
    cudaFuncSetAttribute(k_attn1, cudaFuncAttributeMaxDynamicSharedMemorySize, NKV*32*2*(int)sizeof(float));
    cudaFuncSetAttribute(k_attn2, cudaFuncAttributeMaxDynamicSharedMemorySize, 102400);

    k_cembed<<<B_*N_, 128>>>(E_inv, W_cam);
    k_keyval<<<B_*N_*88, 128, 49152>>>(feature, I_inv, E_inv, W_img,
                                       bn_fp_g, bn_fp_b, W_fp,
                                       bn_fl_g, bn_fl_b, W_fl);
    k_query<<<B_*N_*H_*W_, 128>>>(grid, x, W_bev, b_bev);
    k_foldw<<<6, 128>>>(aln_g, aln_b, aWqkv, abqkv);

    // stage-1 projections + stage-2 K/V (all independent)
    k_gemm<<<384, 256, GSM>>>(0);   // Q1
    k_gemm<<<264, 256, GSM>>>(1);   // K1
    k_gemm<<<264, 256, GSM>>>(2);   // V1
    k_gemm<<<264, 256, GSM>>>(4);   // K2
    k_gemm<<<264, 256, GSM>>>(5);   // V2

    k_attn1<<<dim3(B_*64, 4), 384, NKV*32*2*sizeof(float)>>>();
    k_projout<<<B_*H_*W_/32, 128>>>(0, aWp, abp, x);
    k_mlp<<<B_*H_*W_/16, 256>>>(0, pn_g, pn_b, Wma, bma, Wmb, bmb);

    k_prenorm<<<B_*H_*W_/8, 256>>>();
    k_gemm<<<64, 256, GSM>>>(3);    // Q2
    k_attn2<<<dim3(B_*64, 4), 256, 102400>>>();
    k_projout<<<B_*H_*W_/32, 128>>>(1, aWp + 128*128, abp + 128, x);
    k_mlp<<<B_*H_*W_/16, 256>>>(1, pn_g + 128, pn_b + 128,
                                Wma + 128*256, bma + 256,
                                Wmb + 256*128, bmb + 128);
    k_final<<<B_*H_*W_, 128>>>(post_g, post_b, out);
}

// round 7
// speedup vs baseline: 4.5921x; 1.6477x over previous
#include <cuda_runtime.h>
#include <cuda_fp16.h>
#include <math.h>
#include <stdint.h>

#define B_   2
#define N_   6
#define H_   64
#define W_   64
#define FH_  32
#define FW_  88
#define PIX  (FH_*FW_)     // 2816
#define D_   128
#define NKV  264
#define NQ1  384

// ---------------- scratch globals (no runtime allocation) -------------------
__device__ float  g_cembed[B_*N_*D_];
__device__ __half g_xq [B_*N_*4096*D_];
__device__ __half g_xk [B_*N_*PIX*D_];
__device__ __half g_xv [B_*N_*PIX*D_];
__device__ __half g_xq1[B_*4096*D_];
__device__ __half g_wfold[6*D_*D_];        // folded weights, [o][c]
__device__ float  g_bfold[6*D_];
__device__ float  g_qp1[B_*N_*4096*D_];
__device__ float  g_kp1[B_*N_*PIX*D_];
__device__ float  g_vp1[B_*N_*PIX*D_];
__device__ float  g_qp2[B_*4096*D_];
__device__ float  g_kp2[B_*N_*PIX*D_];
__device__ float  g_vp2[B_*N_*PIX*D_];
__device__ float  g_otok[B_*64*NQ1*D_];
__device__ float  g_q1[B_*H_*W_*D_];
__device__ float  g_q2[B_*H_*W_*D_];

__device__ __forceinline__ void warpRed2(float& s, float& q) {
#pragma unroll
    for (int o = 16; o; o >>= 1) {
        s += __shfl_xor_sync(0xffffffffu, s, o);
        q += __shfl_xor_sync(0xffffffffu, q, o);
    }
}

__device__ __forceinline__ void st_half4(__half* dst, float a, float b, float c, float d) {
    __half2* p = reinterpret_cast<__half2*>(dst);
    p[0] = __floats2half2_rn(a, b);
    p[1] = __floats2half2_rn(c, d);
}

__device__ __forceinline__ uint32_t packh2(float a, float b) {
    __half2 h = __floats2half2_rn(a, b);
    return *reinterpret_cast<uint32_t*>(&h);
}

__device__ __forceinline__ void mma16816(float* c, const uint32_t* a,
                                         uint32_t b0, uint32_t b1) {
    asm volatile(
        "mma.sync.aligned.m16n8k16.row.col.f32.f16.f16.f32 "
        "{%0,%1,%2,%3}, {%4,%5,%6,%7}, {%8,%9}, {%0,%1,%2,%3};\n"
        : "+f"(c[0]), "+f"(c[1]), "+f"(c[2]), "+f"(c[3])
        : "r"(a[0]), "r"(a[1]), "r"(a[2]), "r"(a[3]), "r"(b0), "r"(b1));
}

// ---------------- camera embedding ------------------------------------------
__global__ void k_cembed(const float* __restrict__ E_inv,
                         const float* __restrict__ W_cam) {
    int bn = blockIdx.x, o = threadIdx.x;
    float acc = 0.f;
#pragma unroll
    for (int i = 0; i < 4; i++) acc += W_cam[o*4+i] * E_inv[bn*16 + i*4 + 3];
    g_cembed[bn*D_ + o] = acc;
}

// ---------------- key/val image features -> LN'd fp16 xhat ------------------
__global__ void __launch_bounds__(128) k_keyval(
        const float* __restrict__ feat,
        const float* __restrict__ I_inv, const float* __restrict__ E_inv,
        const float* __restrict__ W_img,
        const float* __restrict__ fp_g, const float* __restrict__ fp_b,
        const float* __restrict__ W_fp,
        const float* __restrict__ fl_g, const float* __restrict__ fl_b,
        const float* __restrict__ W_fl) {
    extern __shared__ float sh[];
    float* sfp  = sh;            // [128 ch][32 px]
    float* sfl  = sh + 4096;
    float* kbuf = sh + 8192;     // [32 px][128 ch]
    int blk = blockIdx.x, tid = threadIdx.x;
    int bn = blk / 88, p0 = (blk % 88) * 32;
    int warp = tid >> 5, lane = tid & 31;

    const float invs = rsqrtf(1.0f + 1e-5f);
    for (int k = tid; k < 4096; k += 128) {
        int c = k >> 5, pp = k & 31;
        float f = feat[(bn*D_ + c)*PIX + p0 + pp];
        sfp[k] = fmaxf(f * invs * fp_g[c] + fp_b[c], 0.f);
        sfl[k] = fmaxf(f * invs * fl_g[c] + fl_b[c], 0.f);
    }
    for (int it = 0; it < 8; it++) {
        int tt = it*4 + warp;
        int p = p0 + tt, fh = p / FW_, fw = p % FW_;
        float px = (float)fw * (480.0f / 87.0f);
        float py = (float)fh * (224.0f / 31.0f);
        float cam[4];
#pragma unroll
        for (int i = 0; i < 3; i++)
            cam[i] = I_inv[bn*9+i*3+0]*px + I_inv[bn*9+i*3+1]*py + I_inv[bn*9+i*3+2];
        cam[3] = 1.0f;
        float dd[4];
#pragma unroll
        for (int i = 0; i < 4; i++)
            dd[i] = E_inv[bn*16+i*4+0]*cam[0] + E_inv[bn*16+i*4+1]*cam[1]
                  + E_inv[bn*16+i*4+2]*cam[2] + E_inv[bn*16+i*4+3]*cam[3];
        int c0 = lane*4;
        float t[4]; float ssum = 0.f, dum = 0.f;
#pragma unroll
        for (int i = 0; i < 4; i++) {
            int c = c0+i;
            float de = W_img[c*4+0]*dd[0] + W_img[c*4+1]*dd[1]
                     + W_img[c*4+2]*dd[2] + W_img[c*4+3]*dd[3];
            t[i] = de - g_cembed[bn*D_+c];
            ssum += t[i]*t[i];
        }
        warpRed2(ssum, dum);
        float inv = 1.0f / fmaxf(sqrtf(ssum), 1e-12f);
#pragma unroll
        for (int i = 0; i < 4; i++) kbuf[tt*D_ + c0 + i] = t[i]*inv;
    }
    __syncthreads();
    // K conv accumulate into kbuf
    {
        float wreg[128];
        const float4* w4 = reinterpret_cast<const float4*>(W_fp + tid*D_);
#pragma unroll
        for (int c4 = 0; c4 < 32; c4++) {
            float4 w = w4[c4];
            wreg[c4*4+0]=w.x; wreg[c4*4+1]=w.y; wreg[c4*4+2]=w.z; wreg[c4*4+3]=w.w;
        }
        const float4* sx4 = reinterpret_cast<const float4*>(sfp);
#pragma unroll
        for (int pg = 0; pg < 4; pg++) {
            float acc[8];
#pragma unroll
            for (int j = 0; j < 8; j++) acc[j] = 0.f;
            for (int c = 0; c < 128; c++) {
                float w = wreg[c];
                float4 a = sx4[c*8 + pg*2];
                float4 b = sx4[c*8 + pg*2 + 1];
                acc[0] += w*a.x; acc[1] += w*a.y; acc[2] += w*a.z; acc[3] += w*a.w;
                acc[4] += w*b.x; acc[5] += w*b.y; acc[6] += w*b.z; acc[7] += w*b.w;
            }
#pragma unroll
            for (int j = 0; j < 8; j++)
                kbuf[(pg*8+j)*D_ + tid] += acc[j];
        }
    }
    __syncthreads();
    for (int it = 0; it < 8; it++) {
        int tt = it*4 + warp;
        float4 v = reinterpret_cast<const float4*>(&kbuf[tt*D_])[lane];
        float s = v.x+v.y+v.z+v.w;
        float q = v.x*v.x+v.y*v.y+v.z*v.z+v.w*v.w;
        warpRed2(s, q);
        float mean = s*(1.0f/128.0f);
        float var = fmaxf(q*(1.0f/128.0f) - mean*mean, 0.f);
        float rstd = rsqrtf(var + 1e-5f);
        st_half4(&g_xk[(bn*PIX + p0 + tt)*D_ + lane*4],
                 (v.x-mean)*rstd, (v.y-mean)*rstd, (v.z-mean)*rstd, (v.w-mean)*rstd);
    }
    __syncthreads();
    // V conv -> kbuf
    {
        float wreg[128];
        const float4* w4 = reinterpret_cast<const float4*>(W_fl + tid*D_);
#pragma unroll
        for (int c4 = 0; c4 < 32; c4++) {
            float4 w = w4[c4];
            wreg[c4*4+0]=w.x; wreg[c4*4+1]=w.y; wreg[c4*4+2]=w.z; wreg[c4*4+3]=w.w;
        }
        const float4* sx4 = reinterpret_cast<const float4*>(sfl);
#pragma unroll
        for (int pg = 0; pg < 4; pg++) {
            float acc[8];
#pragma unroll
            for (int j = 0; j < 8; j++) acc[j] = 0.f;
            for (int c = 0; c < 128; c++) {
                float w = wreg[c];
                float4 a = sx4[c*8 + pg*2];
                float4 b = sx4[c*8 + pg*2 + 1];
                acc[0] += w*a.x; acc[1] += w*a.y; acc[2] += w*a.z; acc[3] += w*a.w;
                acc[4] += w*b.x; acc[5] += w*b.y; acc[6] += w*b.z; acc[7] += w*b.w;
            }
#pragma unroll
            for (int j = 0; j < 8; j++)
                kbuf[(pg*8+j)*D_ + tid] = acc[j];
        }
    }
    __syncthreads();
    for (int it = 0; it < 8; it++) {
        int tt = it*4 + warp;
        float4 v = reinterpret_cast<const float4*>(&kbuf[tt*D_])[lane];
        float s = v.x+v.y+v.z+v.w;
        float q = v.x*v.x+v.y*v.y+v.z*v.z+v.w*v.w;
        warpRed2(s, q);
        float mean = s*(1.0f/128.0f);
        float var = fmaxf(q*(1.0f/128.0f) - mean*mean, 0.f);
        float rstd = rsqrtf(var + 1e-5f);
        st_half4(&g_xv[(bn*PIX + p0 + tt)*D_ + lane*4],
                 (v.x-mean)*rstd, (v.y-mean)*rstd, (v.z-mean)*rstd, (v.w-mean)*rstd);
    }
}

// ---------------- query -> LN'd fp16 xhat, warp per pixel --------------------
__global__ void __launch_bounds__(256) k_query(
        const float* __restrict__ grid, const float* __restrict__ x,
        const float* __restrict__ W_bev, const float* __restrict__ b_bev) {
    int tid = threadIdx.x, warp = tid >> 5, lane = tid & 31;
    int u = blockIdx.x*8 + warp;
    int bn = u >> 12, p = u & 4095;
    int b = bn / N_;
    int c0 = lane*4;
    float gx = grid[p], gy = grid[4096 + p];
    float t[4]; float ss = 0.f, dum = 0.f;
#pragma unroll
    for (int i = 0; i < 4; i++) {
        int c = c0 + i;
        float we = W_bev[c*2+0]*gx + W_bev[c*2+1]*gy + b_bev[c];
        t[i] = we - g_cembed[bn*D_+c];
        ss += t[i]*t[i];
    }
    warpRed2(ss, dum);
    float inv = 1.0f / fmaxf(sqrtf(ss), 1e-12f);
    float q[4]; float s = 0.f, q2 = 0.f;
#pragma unroll
    for (int i = 0; i < 4; i++) {
        q[i] = t[i]*inv + x[(b*D_ + c0 + i)*4096 + p];
        s += q[i]; q2 += q[i]*q[i];
    }
    warpRed2(s, q2);
    float mean = s*(1.0f/128.0f);
    float var = fmaxf(q2*(1.0f/128.0f) - mean*mean, 0.f);
    float rstd = rsqrtf(var + 1e-5f);
    st_half4(&g_xq[u*D_ + c0],
             (q[0]-mean)*rstd, (q[1]-mean)*rstd, (q[2]-mean)*rstd, (q[3]-mean)*rstd);
}

// ---------------- fold LN gamma/beta into projection weights (parallel) ------
__global__ void __launch_bounds__(256) k_foldw(
        const float* __restrict__ aln_g, const float* __restrict__ aln_b,
        const float* __restrict__ aWqkv, const float* __restrict__ abqkv) {
    __shared__ float sm[16][129];
    __shared__ float bred[16][17];
    int idx = blockIdx.x, tid = threadIdx.x;
    int o0 = blockIdx.y*16;
    const float* W = aWqkv + idx*16384;
    const float* g = aln_g + idx*128;
    const float* bb = aln_b + idx*128;
    for (int k = tid; k < 2048; k += 256) {
        int c = k >> 4, o = k & 15;
        sm[o][c] = g[c] * W[c*128 + o0 + o];
    }
    // bias partials
    {
        int o = tid & 15, cg = tid >> 4;
        float part = 0.f;
#pragma unroll
        for (int cc = 0; cc < 8; cc++) {
            int c = cg*8 + cc;
            part += bb[c] * W[c*128 + o0 + o];
        }
        bred[o][cg] = part;
    }
    __syncthreads();
    for (int k = tid; k < 1024; k += 256) {
        int o = k >> 6, c2 = (k & 63)*2;
        __half2 h = __floats2half2_rn(sm[o][c2], sm[o][c2+1]);
        *reinterpret_cast<__half2*>(&g_wfold[idx*16384 + (o0+o)*128 + c2]) = h;
    }
    if (tid < 16) {
        float a = 0.f;
#pragma unroll
        for (int cg = 0; cg < 16; cg++) a += bred[tid][cg];
        g_bfold[idx*128 + o0 + tid] = a + abqkv[idx*128 + o0 + tid];
    }
}

// ---------------- prenorm q1 -> fp16 xhat ------------------------------------
__global__ void __launch_bounds__(256) k_prenorm() {
    int blk = blockIdx.x, tid = threadIdx.x;
    int warp = tid >> 5, lane = tid & 31;
    int u = blk*8 + warp;
    float4 v = reinterpret_cast<const float4*>(g_q1 + u*D_)[lane];
    float s = v.x+v.y+v.z+v.w;
    float q = v.x*v.x+v.y*v.y+v.z*v.z+v.w*v.w;
    warpRed2(s, q);
    float mean = s*(1.0f/128.0f);
    float var = fmaxf(q*(1.0f/128.0f) - mean*mean, 0.f);
    float rstd = rsqrtf(var + 1e-5f);
    st_half4(&g_xq1[u*D_ + lane*4],
             (v.x-mean)*rstd, (v.y-mean)*rstd, (v.z-mean)*rstd, (v.w-mean)*rstd);
}

// ---------------- HMMA GEMM: C[T][128] = A[T][128] @ Wt^T + bias -------------
__global__ void __launch_bounds__(256) k_gemm(int job) {
    const __half* A; const __half* Wt; const float* bias; float* C;
    switch (job) {
        case 0: A=g_xq;  Wt=g_wfold+0*16384; bias=g_bfold+0*128; C=g_qp1; break;
        case 1: A=g_xk;  Wt=g_wfold+1*16384; bias=g_bfold+1*128; C=g_kp1; break;
        case 2: A=g_xv;  Wt=g_wfold+2*16384; bias=g_bfold+2*128; C=g_vp1; break;
        case 3: A=g_xq1; Wt=g_wfold+3*16384; bias=g_bfold+3*128; C=g_qp2; break;
        case 4: A=g_xk;  Wt=g_wfold+4*16384; bias=g_bfold+4*128; C=g_kp2; break;
        default:A=g_xv;  Wt=g_wfold+5*16384; bias=g_bfold+5*128; C=g_vp2; break;
    }
    extern __shared__ __half shh[];
    __half* As = shh;                 // [128][136]
    __half* Ws = shh + 128*136;       // [128][136]
    float* sbias = reinterpret_cast<float*>(shh + 2*128*136);
    int tid = threadIdx.x;
    int m0 = blockIdx.x * 128;
    {
        int r = tid >> 4, q = tid & 15;
        for (int rr = r; rr < 128; rr += 16) {
            *reinterpret_cast<int4*>(&As[rr*136 + q*8]) =
                *reinterpret_cast<const int4*>(&A[(m0+rr)*128 + q*8]);
            *reinterpret_cast<int4*>(&Ws[rr*136 + q*8]) =
                *reinterpret_cast<const int4*>(&Wt[rr*128 + q*8]);
        }
        if (tid < 128) sbias[tid] = bias[tid];
    }
    __syncthreads();
    int warp = tid >> 5, lane = tid & 31;
    int wm = (warp & 3) * 32;
    int wn = (warp >> 2) * 64;
    int g = lane >> 2, tg = (lane & 3) * 2;
    float acc[2][8][4];
#pragma unroll
    for (int i = 0; i < 2; i++)
#pragma unroll
        for (int j = 0; j < 8; j++)
#pragma unroll
            for (int r = 0; r < 4; r++) acc[i][j][r] = 0.f;
#pragma unroll
    for (int ks = 0; ks < 8; ks++) {
        int k0 = ks*16;
        uint32_t a[2][4];
#pragma unroll
        for (int i = 0; i < 2; i++) {
            int mb = wm + i*16;
            a[i][0] = *reinterpret_cast<const uint32_t*>(&As[(mb+g  )*136 + k0+tg  ]);
            a[i][1] = *reinterpret_cast<const uint32_t*>(&As[(mb+8+g)*136 + k0+tg  ]);
            a[i][2] = *reinterpret_cast<const uint32_t*>(&As[(mb+g  )*136 + k0+8+tg]);
            a[i][3] = *reinterpret_cast<const uint32_t*>(&As[(mb+8+g)*136 + k0+8+tg]);
        }
#pragma unroll
        for (int j = 0; j < 8; j++) {
            uint32_t b0 = *reinterpret_cast<const uint32_t*>(&Ws[(wn+j*8+g)*136 + k0+tg  ]);
            uint32_t b1 = *reinterpret_cast<const uint32_t*>(&Ws[(wn+j*8+g)*136 + k0+8+tg]);
            mma16816(acc[0][j], a[0], b0, b1);
            mma16816(acc[1][j], a[1], b0, b1);
        }
    }
#pragma unroll
    for (int i = 0; i < 2; i++) {
#pragma unroll
        for (int j = 0; j < 8; j++) {
            int m = m0 + wm + i*16 + g;
            int n = wn + j*8 + tg;
            C[m*128 + n]       = acc[i][j][0] + sbias[n];
            C[m*128 + n+1]     = acc[i][j][1] + sbias[n+1];
            C[(m+8)*128 + n]   = acc[i][j][2] + sbias[n];
            C[(m+8)*128 + n+1] = acc[i][j][3] + sbias[n+1];
        }
    }
}

// ---------------- tensor-core flash attention --------------------------------
// grid (B_*64, 4 heads), block = NW*32 threads, warp owns MT*16 q-rows.
template<int MT, int NW>
__global__ void __launch_bounds__(NW*32) k_attn_mma(int stage) {
    const int NQ = MT*16*NW;
    extern __shared__ __half sha[];
    __half* Qs = sha;                  // [NQ][40]
    __half* Ks = Qs + NQ*40;           // [264][40]
    __half* Vt = Ks + 264*40;          // [32][274]
    int bl = blockIdx.x, hh = blockIdx.y, tid = threadIdx.x;
    int b = bl >> 6, l = bl & 63;
    const float scale = 0.17677669529663687f;
    // ---- load Q (fp32 -> fp16, pre-scaled) ----
    for (int idx = tid; idx < NQ*32; idx += NW*32) {
        int row = idx >> 5, ch = idx & 31;
        float qv;
        if (stage == 0) {
            int n = row >> 6, ij = row & 63, i = ij >> 3, j = ij & 7;
            int pix = (b*N_+n)*4096 + ((l>>3)*8 + i)*64 + (l&7)*8 + j;
            qv = g_qp1[pix*D_ + hh*32 + ch];
        } else {
            int i = row >> 3, j = row & 7;
            int pix = b*4096 + ((l>>3)*8 + i)*64 + (l&7)*8 + j;
            qv = g_qp2[pix*D_ + hh*32 + ch];
        }
        Qs[row*40 + ch] = __float2half(qv * scale);
    }
    // ---- load K and V^T ----
    const float* kb = (stage == 0) ? g_kp1 : g_kp2;
    const float* vb = (stage == 0) ? g_vp1 : g_vp2;
    for (int idx = tid; idx < NKV*32; idx += NW*32) {
        int kv = idx >> 5, ch = idx & 31;
        int n = kv/44, f = kv%44, f1 = f/11, f2 = f%11;
        int h, w;
        if (stage == 0) { h = (l>>3)*4 + f1; w = (l&7)*11 + f2; }
        else            { h = f1*8 + (l>>3); w = f2*8 + (l&7); }
        int pix = (b*N_+n)*PIX + h*FW_ + w;
        Ks[kv*40 + ch] = __float2half(kb[pix*D_ + hh*32 + ch]);
        Vt[ch*274 + kv] = __float2half(vb[pix*D_ + hh*32 + ch]);
    }
    // zero Vt padding cols 264..273
    for (int idx = tid; idx < 32*10; idx += NW*32) {
        int ch = idx / 10, c = idx % 10;
        Vt[ch*274 + 264 + c] = __half(0.f);
    }
    __syncthreads();

    int warp = tid >> 5, lane = tid & 31;
    int g = lane >> 2, t4 = lane & 3;
    int row0 = warp * MT * 16;

    // Q A-fragments (chunk-invariant)
    uint32_t af[MT][2][4];
#pragma unroll
    for (int mt = 0; mt < MT; mt++)
#pragma unroll
        for (int ks = 0; ks < 2; ks++) {
            int r = row0 + mt*16, k0 = ks*16;
            af[mt][ks][0] = *reinterpret_cast<const uint32_t*>(&Qs[(r+g  )*40 + k0 + 2*t4    ]);
            af[mt][ks][1] = *reinterpret_cast<const uint32_t*>(&Qs[(r+8+g)*40 + k0 + 2*t4    ]);
            af[mt][ks][2] = *reinterpret_cast<const uint32_t*>(&Qs[(r+g  )*40 + k0 + 8 + 2*t4]);
            af[mt][ks][3] = *reinterpret_cast<const uint32_t*>(&Qs[(r+8+g)*40 + k0 + 8 + 2*t4]);
        }

    float m[MT][2], lsum[MT][2], O[MT][4][4];
#pragma unroll
    for (int mt = 0; mt < MT; mt++) {
        m[mt][0] = -1e30f; m[mt][1] = -1e30f;
        lsum[mt][0] = 0.f; lsum[mt][1] = 0.f;
#pragma unroll
        for (int j = 0; j < 4; j++)
#pragma unroll
            for (int r = 0; r < 4; r++) O[mt][j][r] = 0.f;
    }

    for (int c = 0; c < 17; c++) {
        int kv0 = c*16;
        int nt = (c == 16) ? 1 : 2;
        // B-fragments for S
        uint32_t bf[2][2][2];
#pragma unroll
        for (int n = 0; n < 2; n++) {
            if (n < nt) {
#pragma unroll
                for (int ks = 0; ks < 2; ks++) {
                    bf[n][ks][0] = *reinterpret_cast<const uint32_t*>(&Ks[(kv0+n*8+g)*40 + ks*16 + 2*t4    ]);
                    bf[n][ks][1] = *reinterpret_cast<const uint32_t*>(&Ks[(kv0+n*8+g)*40 + ks*16 + 8 + 2*t4]);
                }
            }
        }
        float S[MT][2][4];
#pragma unroll
        for (int mt = 0; mt < MT; mt++)
#pragma unroll
            for (int n = 0; n < 2; n++)
#pragma unroll
                for (int r = 0; r < 4; r++) S[mt][n][r] = 0.f;
#pragma unroll
        for (int mt = 0; mt < MT; mt++)
#pragma unroll
            for (int n = 0; n < 2; n++) {
                if (n < nt) {
                    mma16816(S[mt][n], af[mt][0], bf[n][0][0], bf[n][0][1]);
                    mma16816(S[mt][n], af[mt][1], bf[n][1][0], bf[n][1][1]);
                }
            }
        // online softmax + PV per m-tile
#pragma unroll
        for (int mt = 0; mt < MT; mt++) {
            float mx0 = fmaxf(S[mt][0][0], S[mt][0][1]);
            float mx8 = fmaxf(S[mt][0][2], S[mt][0][3]);
            if (nt == 2) {
                mx0 = fmaxf(mx0, fmaxf(S[mt][1][0], S[mt][1][1]));
                mx8 = fmaxf(mx8, fmaxf(S[mt][1][2], S[mt][1][3]));
            }
            mx0 = fmaxf(mx0, __shfl_xor_sync(0xffffffffu, mx0, 1));
            mx0 = fmaxf(mx0, __shfl_xor_sync(0xffffffffu, mx0, 2));
            mx8 = fmaxf(mx8, __shfl_xor_sync(0xffffffffu, mx8, 1));
            mx8 = fmaxf(mx8, __shfl_xor_sync(0xffffffffu, mx8, 2));
            float mn0 = fmaxf(m[mt][0], mx0), mn8 = fmaxf(m[mt][1], mx8);
            float cr0 = __expf(m[mt][0] - mn0), cr8 = __expf(m[mt][1] - mn8);
            m[mt][0] = mn0; m[mt][1] = mn8;
            uint32_t pa[4];
            float p00 = __expf(S[mt][0][0] - mn0), p01 = __expf(S[mt][0][1] - mn0);
            float p02 = __expf(S[mt][0][2] - mn8), p03 = __expf(S[mt][0][3] - mn8);
            float rs0 = p00 + p01, rs8 = p02 + p03;
            pa[0] = packh2(p00, p01);
            pa[1] = packh2(p02, p03);
            if (nt == 2) {
                float p10 = __expf(S[mt][1][0] - mn0), p11 = __expf(S[mt][1][1] - mn0);
                float p12 = __expf(S[mt][1][2] - mn8), p13 = __expf(S[mt][1][3] - mn8);
                rs0 += p10 + p11; rs8 += p12 + p13;
                pa[2] = packh2(p10, p11);
                pa[3] = packh2(p12, p13);
            } else { pa[2] = 0u; pa[3] = 0u; }
            rs0 += __shfl_xor_sync(0xffffffffu, rs0, 1);
            rs0 += __shfl_xor_sync(0xffffffffu, rs0, 2);
            rs8 += __shfl_xor_sync(0xffffffffu, rs8, 1);
            rs8 += __shfl_xor_sync(0xffffffffu, rs8, 2);
            lsum[mt][0] = lsum[mt][0]*cr0 + rs0;
            lsum[mt][1] = lsum[mt][1]*cr8 + rs8;
#pragma unroll
            for (int j = 0; j < 4; j++) {
                O[mt][j][0] *= cr0; O[mt][j][1] *= cr0;
                O[mt][j][2] *= cr8; O[mt][j][3] *= cr8;
                uint32_t vb0 = *reinterpret_cast<const uint32_t*>(&Vt[(j*8+g)*274 + kv0 + 2*t4    ]);
                uint32_t vb1 = *reinterpret_cast<const uint32_t*>(&Vt[(j*8+g)*274 + kv0 + 8 + 2*t4]);
                mma16816(O[mt][j], pa, vb0, vb1);
            }
        }
    }
    // epilogue
#pragma unroll
    for (int mt = 0; mt < MT; mt++) {
        float i0 = 1.0f / lsum[mt][0], i8 = 1.0f / lsum[mt][1];
        int rbase = bl*NQ + row0 + mt*16;
#pragma unroll
        for (int j = 0; j < 4; j++) {
            int chn = hh*32 + j*8 + 2*t4;
            g_otok[(rbase+g  )*D_ + chn  ] = O[mt][j][0]*i0;
            g_otok[(rbase+g  )*D_ + chn+1] = O[mt][j][1]*i0;
            g_otok[(rbase+8+g)*D_ + chn  ] = O[mt][j][2]*i8;
            g_otok[(rbase+8+g)*D_ + chn+1] = O[mt][j][3]*i8;
        }
    }
}

// ---------------- output proj + camera mean + skip ---------------------------
__global__ void __launch_bounds__(128) k_projout(
        int stage, const float* __restrict__ Wp,
        const float* __restrict__ bp, const float* __restrict__ x) {
    __shared__ __align__(16) float mvec[32][D_];
    int blk = blockIdx.x, tid = threadIdx.x;
    float bp_r = bp[tid];
    float4 wv[32];
#pragma unroll
    for (int c4 = 0; c4 < 32; c4++) {
        wv[c4].x = Wp[(c4*4+0)*D_ + tid];
        wv[c4].y = Wp[(c4*4+1)*D_ + tid];
        wv[c4].z = Wp[(c4*4+2)*D_ + tid];
        wv[c4].w = Wp[(c4*4+3)*D_ + tid];
    }
    for (int tt = 0; tt < 32; tt++) {
        int u = blk*32 + tt;
        int b = u >> 12, p = u & 4095;
        int hh = p >> 6, ww = p & 63;
        int i = hh & 7, j = ww & 7;
        int l = (hh >> 3)*8 + (ww >> 3);
        if (stage == 0) {
            float a = 0.f;
#pragma unroll
            for (int n = 0; n < N_; n++)
                a += g_otok[((b*64+l)*NQ1 + n*64 + i*8 + j)*D_ + tid];
            mvec[tt][tid] = a * (1.0f/6.0f);
        } else {
            mvec[tt][tid] = g_otok[((b*64+l)*64 + i*8 + j)*D_ + tid];
        }
    }
    __syncthreads();
    for (int tt0 = 0; tt0 < 32; tt0 += 4) {
        const float4* x0 = reinterpret_cast<const float4*>(mvec[tt0+0]);
        const float4* x1 = reinterpret_cast<const float4*>(mvec[tt0+1]);
        const float4* x2 = reinterpret_cast<const float4*>(mvec[tt0+2]);
        const float4* x3 = reinterpret_cast<const float4*>(mvec[tt0+3]);
        float a0 = bp_r, a1 = bp_r, a2 = bp_r, a3 = bp_r;
#pragma unroll
        for (int c4 = 0; c4 < 32; c4++) {
            float4 w = wv[c4];
            float4 v0 = x0[c4], v1 = x1[c4], v2 = x2[c4], v3 = x3[c4];
            a0 += v0.x*w.x + v0.y*w.y + v0.z*w.z + v0.w*w.w;
            a1 += v1.x*w.x + v1.y*w.y + v1.z*w.z + v1.w*w.w;
            a2 += v2.x*w.x + v2.y*w.y + v2.z*w.z + v2.w*w.w;
            a3 += v3.x*w.x + v3.y*w.y + v3.z*w.z + v3.w*w.w;
        }
        float accs[4] = {a0, a1, a2, a3};
#pragma unroll
        for (int i2 = 0; i2 < 4; i2++) {
            int u = blk*32 + tt0 + i2;
            int b = u >> 12, p = u & 4095;
            float sk = (stage == 0) ? x[(b*D_+tid)*4096 + p] : g_q1[u*D_ + tid];
            float* dst = (stage == 0) ? g_q1 : g_q2;
            dst[u*D_ + tid] = accs[i2] + sk;
        }
    }
}

// ---------------- MLP --------------------------------------------------------
__global__ void __launch_bounds__(256) k_mlp(
        int which,
        const float* __restrict__ lg, const float* __restrict__ lb,
        const float* __restrict__ Wa, const float* __restrict__ ba,
        const float* __restrict__ Wb, const float* __restrict__ bb) {
    __shared__ __align__(16) float lnx[16][D_];
    __shared__ __align__(16) float gh[16][256];
    float* buf = (which == 0) ? g_q1 : g_q2;
    int blk = blockIdx.x, tid = threadIdx.x;
    int warp = tid >> 5, lane = tid & 31;
    for (int it = 0; it < 2; it++) {
        int tt = it*8 + warp;
        int u = blk*16 + tt;
        float4 v = reinterpret_cast<const float4*>(buf + u*D_)[lane];
        float s = v.x+v.y+v.z+v.w;
        float q = v.x*v.x+v.y*v.y+v.z*v.z+v.w*v.w;
        warpRed2(s, q);
        float mean = s*(1.0f/128.0f);
        float var = fmaxf(q*(1.0f/128.0f) - mean*mean, 0.f);
        float rstd = rsqrtf(var + 1e-5f);
        int c0 = lane*4;
        lnx[tt][c0+0] = (v.x-mean)*rstd*lg[c0+0]+lb[c0+0];
        lnx[tt][c0+1] = (v.y-mean)*rstd*lg[c0+1]+lb[c0+1];
        lnx[tt][c0+2] = (v.z-mean)*rstd*lg[c0+2]+lb[c0+2];
        lnx[tt][c0+3] = (v.w-mean)*rstd*lg[c0+3]+lb[c0+3];
    }
    __syncthreads();
    {
        float4 wa[32];
#pragma unroll
        for (int c4 = 0; c4 < 32; c4++) {
            wa[c4].x = Wa[(c4*4+0)*256 + tid];
            wa[c4].y = Wa[(c4*4+1)*256 + tid];
            wa[c4].z = Wa[(c4*4+2)*256 + tid];
            wa[c4].w = Wa[(c4*4+3)*256 + tid];
        }
        float ba_r = ba[tid];
        for (int tt0 = 0; tt0 < 16; tt0 += 4) {
            const float4* x0 = reinterpret_cast<const float4*>(lnx[tt0+0]);
            const float4* x1 = reinterpret_cast<const float4*>(lnx[tt0+1]);
            const float4* x2 = reinterpret_cast<const float4*>(lnx[tt0+2]);
            const float4* x3 = reinterpret_cast<const float4*>(lnx[tt0+3]);
            float a0 = ba_r, a1 = ba_r, a2 = ba_r, a3 = ba_r;
#pragma unroll
            for (int c4 = 0; c4 < 32; c4++) {
                float4 w = wa[c4];
                float4 v0 = x0[c4], v1 = x1[c4], v2 = x2[c4], v3 = x3[c4];
                a0 += v0.x*w.x + v0.y*w.y + v0.z*w.z + v0.w*w.w;
                a1 += v1.x*w.x + v1.y*w.y + v1.z*w.z + v1.w*w.w;
                a2 += v2.x*w.x + v2.y*w.y + v2.z*w.z + v2.w*w.w;
                a3 += v3.x*w.x + v3.y*w.y + v3.z*w.z + v3.w*w.w;
            }
            gh[tt0+0][tid] = a0 * 0.5f * (1.0f + erff(a0*0.70710678118654752f));
            gh[tt0+1][tid] = a1 * 0.5f * (1.0f + erff(a1*0.70710678118654752f));
            gh[tt0+2][tid] = a2 * 0.5f * (1.0f + erff(a2*0.70710678118654752f));
            gh[tt0+3][tid] = a3 * 0.5f * (1.0f + erff(a3*0.70710678118654752f));
        }
    }
    __syncthreads();
    {
        int o = tid & 127, half = tid >> 7;
        float4 wb[32];
#pragma unroll
        for (int c4 = 0; c4 < 32; c4++) {
            wb[c4].x = Wb[(half*128 + c4*4+0)*D_ + o];
            wb[c4].y = Wb[(half*128 + c4*4+1)*D_ + o];
            wb[c4].z = Wb[(half*128 + c4*4+2)*D_ + o];
            wb[c4].w = Wb[(half*128 + c4*4+3)*D_ + o];
        }
        float accs[16];
        for (int tt0 = 0; tt0 < 16; tt0 += 4) {
            const float4* h0 = reinterpret_cast<const float4*>(&gh[tt0+0][half*128]);
            const float4* h1 = reinterpret_cast<const float4*>(&gh[tt0+1][half*128]);
            const float4* h2 = reinterpret_cast<const float4*>(&gh[tt0+2][half*128]);
            const float4* h3 = reinterpret_cast<const float4*>(&gh[tt0+3][half*128]);
            float a0 = 0.f, a1 = 0.f, a2 = 0.f, a3 = 0.f;
#pragma unroll
            for (int c4 = 0; c4 < 32; c4++) {
                float4 w = wb[c4];
                float4 v0 = h0[c4], v1 = h1[c4], v2 = h2[c4], v3 = h3[c4];
                a0 += v0.x*w.x + v0.y*w.y + v0.z*w.z + v0.w*w.w;
                a1 += v1.x*w.x + v1.y*w.y + v1.z*w.z + v1.w*w.w;
                a2 += v2.x*w.x + v2.y*w.y + v2.z*w.z + v2.w*w.w;
                a3 += v3.x*w.x + v3.y*w.y + v3.z*w.z + v3.w*w.w;
            }
            accs[tt0+0]=a0; accs[tt0+1]=a1; accs[tt0+2]=a2; accs[tt0+3]=a3;
        }
        __syncthreads();
        float* pbuf = &lnx[0][0];
        if (half == 1) {
            for (int tt = 0; tt < 16; tt++) pbuf[tt*D_ + o] = accs[tt];
        }
        __syncthreads();
        if (half == 0) {
            float bb_r = bb[o];
            for (int tt = 0; tt < 16; tt++) {
                int u = blk*16 + tt;
                buf[u*D_ + o] = buf[u*D_ + o] + bb_r + accs[tt] + pbuf[tt*D_ + o];
            }
        }
    }
}

// ---------------- final LN + transpose, warp per token -----------------------
__global__ void __launch_bounds__(256) k_final(
        const float* __restrict__ pg, const float* __restrict__ pb,
        float* __restrict__ out) {
    int tid = threadIdx.x, warp = tid >> 5, lane = tid & 31;
    int u = blockIdx.x*8 + warp;
    int b = u >> 12, p = u & 4095;
    float4 v = reinterpret_cast<const float4*>(g_q2 + u*D_)[lane];
    float s = v.x+v.y+v.z+v.w;
    float q = v.x*v.x+v.y*v.y+v.z*v.z+v.w*v.w;
    warpRed2(s, q);
    float mean = s*(1.0f/128.0f);
    float var = fmaxf(q*(1.0f/128.0f) - mean*mean, 0.f);
    float rstd = rsqrtf(var + 1e-5f);
    int c0 = lane*4;
    out[(b*D_+c0+0)*4096 + p] = (v.x-mean)*rstd*pg[c0+0]+pb[c0+0];
    out[(b*D_+c0+1)*4096 + p] = (v.y-mean)*rstd*pg[c0+1]+pb[c0+1];
    out[(b*D_+c0+2)*4096 + p] = (v.z-mean)*rstd*pg[c0+2]+pb[c0+2];
    out[(b*D_+c0+3)*4096 + p] = (v.w-mean)*rstd*pg[c0+3]+pb[c0+3];
}

// ---------------------------------------------------------------------------
extern "C" void kernel_launch(void* const* d_in, const int* in_sizes, int n_in,
                              void* d_out, int out_size) {
    (void)in_sizes; (void)n_in; (void)out_size;
    const float* x        = (const float*)d_in[1];
    const float* grid     = (const float*)d_in[2];
    const float* feature  = (const float*)d_in[3];
    const float* I_inv    = (const float*)d_in[4];
    const float* E_inv    = (const float*)d_in[5];
    const float* bn_fl_g  = (const float*)d_in[6];
    const float* bn_fl_b  = (const float*)d_in[7];
    const float* W_fl     = (const float*)d_in[8];
    const float* bn_fp_g  = (const float*)d_in[9];
    const float* bn_fp_b  = (const float*)d_in[10];
    const float* W_fp     = (const float*)d_in[11];
    const float* W_bev    = (const float*)d_in[12];
    const float* b_bev    = (const float*)d_in[13];
    const float* W_img    = (const float*)d_in[14];
    const float* W_cam    = (const float*)d_in[15];
    const float* aln_g    = (const float*)d_in[16];
    const float* aln_b    = (const float*)d_in[17];
    const float* aWqkv    = (const float*)d_in[18];
    const float* abqkv    = (const float*)d_in[19];
    const float* aWp      = (const float*)d_in[20];
    const float* abp      = (const float*)d_in[21];
    const float* pn_g     = (const float*)d_in[22];
    const float* pn_b     = (const float*)d_in[23];
    const float* Wma      = (const float*)d_in[24];
    const float* bma      = (const float*)d_in[25];
    const float* Wmb      = (const float*)d_in[26];
    const float* bmb      = (const float*)d_in[27];
    const float* post_g   = (const float*)d_in[28];
    const float* post_b   = (const float*)d_in[29];
    float* out = (float*)d_out;

    const int GSM = 2*128*136*2 + 512;   // gemm smem
    const int A1SM = (384*40 + 264*40 + 32*274) * 2;   // 69376
    const int A2SM = (64*40 + 264*40 + 32*274) * 2;    // 43776
    cudaFuncSetAttribute(k_keyval, cudaFuncAttributeMaxDynamicSharedMemorySize, 49152);
    cudaFuncSetAttribute(k_gemm, cudaFuncAttributeMaxDynamicSharedMemorySize, GSM);
    cudaFuncSetAttribute(k_attn_mma<3,8>, cudaFuncAttributeMaxDynamicSharedMemorySize, A1SM);
    cudaFuncSetAttribute(k_attn_mma<1,4>, cudaFuncAttributeMaxDynamicSharedMemorySize, A2SM);

    k_cembed<<<B_*N_, 128>>>(E_inv, W_cam);
    k_keyval<<<B_*N_*88, 128, 49152>>>(feature, I_inv, E_inv, W_img,
                                       bn_fp_g, bn_fp_b, W_fp,
                                       bn_fl_g, bn_fl_b, W_fl);
    k_query<<<B_*N_*4096/8, 256>>>(grid, x, W_bev, b_bev);
    k_foldw<<<dim3(6, 8), 256>>>(aln_g, aln_b, aWqkv, abqkv);

    k_gemm<<<384, 256, GSM>>>(0);   // Q1
    k_gemm<<<264, 256, GSM>>>(1);   // K1
    k_gemm<<<264, 256, GSM>>>(2);   // V1
    k_gemm<<<264, 256, GSM>>>(4);   // K2
    k_gemm<<<264, 256, GSM>>>(5);   // V2

    k_attn_mma<3,8><<<dim3(B_*64, 4), 256, A1SM>>>(0);
    k_projout<<<B_*H_*W_/32, 128>>>(0, aWp, abp, x);
    k_mlp<<<B_*H_*W_/16, 256>>>(0, pn_g, pn_b, Wma, bma, Wmb, bmb);

    k_prenorm<<<B_*H_*W_/8, 256>>>();
    k_gemm<<<64, 256, GSM>>>(3);    // Q2
    k_attn_mma<1,4><<<dim3(B_*64, 4), 128, A2SM>>>(1);
    k_projout<<<B_*H_*W_/32, 128>>>(1, aWp + 128*128, abp + 128, x);
    k_mlp<<<B_*H_*W_/16, 256>>>(1, pn_g + 128, pn_b + 128,
                                Wma + 128*256, bma + 256,
                                Wmb + 256*128, bmb + 128);
    k_final<<<B_*H_*W_/8, 256>>>(post_g, post_b, out);
}

// round 9
// speedup vs baseline: 6.0873x; 1.3256x over previous
#include <cuda_runtime.h>
#include <cuda_fp16.h>
#include <math.h>
#include <stdint.h>

#define B_   2
#define N_   6
#define H_   64
#define W_   64
#define FH_  32
#define FW_  88
#define PIX  (FH_*FW_)     // 2816
#define D_   128
#define NKV  264
#define NQ1  384
#define NPX  (B_*N_*PIX)   // 33792
#define NQP  (B_*N_*4096)  // 49152
#define NTK  (B_*4096)     // 8192

// epilogue modes
#define EPI_HALF 0
#define EPI_GELU 1
#define EPI_SKIP0 2
#define EPI_SKIP1 3
#define EPI_RES  4
#define EPI_LN   5

// ---------------- scratch globals (no runtime allocation) -------------------
__device__ float  g_cembed[B_*N_*D_];
__device__ __align__(16) __half g_fph[NPX*D_];
__device__ __align__(16) __half g_flh[NPX*D_];
__device__ __align__(16) float  g_kimg[NPX*D_];
__device__ __align__(16) __half g_xq [NQP*D_];
__device__ __align__(16) __half g_xk [NPX*D_];
__device__ __align__(16) __half g_xv [NPX*D_];
__device__ __align__(16) __half g_xq1[NTK*D_];
__device__ __align__(16) __half g_xm [NTK*D_];
__device__ __align__(16) __half g_wfold[6*D_*D_];
__device__ float  g_bfold[6*D_];
__device__ __align__(16) __half g_wafold[2*256*D_];
__device__ float  g_bafold[2*256];
__device__ __align__(16) __half g_wmbT[2*D_*256];
__device__ __align__(16) __half g_wpT[2*D_*D_];
__device__ __align__(16) __half g_wfpH[D_*D_];
__device__ __align__(16) __half g_wflH[D_*D_];
__device__ __align__(16) __half g_qh1[NQP*D_];
__device__ __align__(16) __half g_kh1[NPX*D_];
__device__ __align__(16) __half g_vh1[NPX*D_];
__device__ __align__(16) __half g_qh2[NTK*D_];
__device__ __align__(16) __half g_kh2[NPX*D_];
__device__ __align__(16) __half g_vh2[NPX*D_];
__device__ __align__(16) __half g_otok[B_*64*NQ1*D_];
__device__ __align__(16) __half g_o2[NTK*D_];
__device__ __align__(16) __half g_mo[NTK*D_];
__device__ __align__(16) __half g_h[NTK*256];
__device__ __align__(16) float  g_q1[NTK*D_];
__device__ __align__(16) float  g_q2[NTK*D_];

__device__ __forceinline__ void warpRed2(float& s, float& q) {
#pragma unroll
    for (int o = 16; o; o >>= 1) {
        s += __shfl_xor_sync(0xffffffffu, s, o);
        q += __shfl_xor_sync(0xffffffffu, q, o);
    }
}

__device__ __forceinline__ void st_half4(__half* dst, float a, float b, float c, float d) {
    __half2* p = reinterpret_cast<__half2*>(dst);
    p[0] = __floats2half2_rn(a, b);
    p[1] = __floats2half2_rn(c, d);
}

__device__ __forceinline__ uint32_t packh2(float a, float b) {
    __half2 h = __floats2half2_rn(a, b);
    return *reinterpret_cast<uint32_t*>(&h);
}

__device__ __forceinline__ float geluf(float h) {
    return h * 0.5f * (1.0f + erff(h * 0.70710678118654752f));
}

__device__ __forceinline__ void mma16816(float* c, const uint32_t* a,
                                         uint32_t b0, uint32_t b1) {
    asm volatile(
        "mma.sync.aligned.m16n8k16.row.col.f32.f16.f16.f32 "
        "{%0,%1,%2,%3}, {%4,%5,%6,%7}, {%8,%9}, {%0,%1,%2,%3};\n"
        : "+f"(c[0]), "+f"(c[1]), "+f"(c[2]), "+f"(c[3])
        : "r"(a[0]), "r"(a[1]), "r"(a[2]), "r"(a[3]), "r"(b0), "r"(b1));
}

// ---------------- camera embedding ------------------------------------------
__global__ void k_cembed(const float* __restrict__ E_inv,
                         const float* __restrict__ W_cam) {
    int bn = blockIdx.x, o = threadIdx.x;
    float acc = 0.f;
#pragma unroll
    for (int i = 0; i < 4; i++) acc += W_cam[o*4+i] * E_inv[bn*16 + i*4 + 3];
    g_cembed[bn*D_ + o] = acc;
}

// ---------------- prep: BN-ReLU fp16 feats + image embedding -----------------
__global__ void __launch_bounds__(128) k_prep(
        const float* __restrict__ feat,
        const float* __restrict__ I_inv, const float* __restrict__ E_inv,
        const float* __restrict__ W_img,
        const float* __restrict__ fp_g, const float* __restrict__ fp_b,
        const float* __restrict__ fl_g, const float* __restrict__ fl_b) {
    extern __shared__ float sh[];
    float* sfp  = sh;                 // [128][33]
    float* sfl  = sh + 128*33;
    float* kimg = sh + 2*128*33;      // [32][128]
    int blk = blockIdx.x, tid = threadIdx.x;
    int bn = blk / 88, p0 = (blk % 88) * 32;
    int warp = tid >> 5, lane = tid & 31;

    const float invs = rsqrtf(1.0f + 1e-5f);
    for (int k = tid; k < 4096; k += 128) {
        int c = k >> 5, pp = k & 31;
        float f = feat[(bn*D_ + c)*PIX + p0 + pp];
        sfp[c*33+pp] = fmaxf(f * invs * fp_g[c] + fp_b[c], 0.f);
        sfl[c*33+pp] = fmaxf(f * invs * fl_g[c] + fl_b[c], 0.f);
    }
    for (int it = 0; it < 8; it++) {
        int tt = it*4 + warp;
        int p = p0 + tt, fh = p / FW_, fw = p % FW_;
        float px = (float)fw * (480.0f / 87.0f);
        float py = (float)fh * (224.0f / 31.0f);
        float cam[4];
#pragma unroll
        for (int i = 0; i < 3; i++)
            cam[i] = I_inv[bn*9+i*3+0]*px + I_inv[bn*9+i*3+1]*py + I_inv[bn*9+i*3+2];
        cam[3] = 1.0f;
        float dd[4];
#pragma unroll
        for (int i = 0; i < 4; i++)
            dd[i] = E_inv[bn*16+i*4+0]*cam[0] + E_inv[bn*16+i*4+1]*cam[1]
                  + E_inv[bn*16+i*4+2]*cam[2] + E_inv[bn*16+i*4+3]*cam[3];
        int c0 = lane*4;
        float t[4]; float ssum = 0.f, dum = 0.f;
#pragma unroll
        for (int i = 0; i < 4; i++) {
            int c = c0+i;
            float de = W_img[c*4+0]*dd[0] + W_img[c*4+1]*dd[1]
                     + W_img[c*4+2]*dd[2] + W_img[c*4+3]*dd[3];
            t[i] = de - g_cembed[bn*D_+c];
            ssum += t[i]*t[i];
        }
        warpRed2(ssum, dum);
        float inv = 1.0f / fmaxf(sqrtf(ssum), 1e-12f);
#pragma unroll
        for (int i = 0; i < 4; i++) kimg[tt*128 + c0 + i] = t[i]*inv;
    }
    __syncthreads();
    for (int pp = 0; pp < 32; pp++) {
        int row = bn*PIX + p0 + pp;
        g_fph[row*D_ + tid] = __float2half(sfp[tid*33 + pp]);
        g_flh[row*D_ + tid] = __float2half(sfl[tid*33 + pp]);
        g_kimg[row*D_ + tid] = kimg[pp*128 + tid];
    }
}

// ---------------- query -> LN'd fp16 xhat, warp per pixel --------------------
__global__ void __launch_bounds__(256) k_query(
        const float* __restrict__ grid, const float* __restrict__ x,
        const float* __restrict__ W_bev, const float* __restrict__ b_bev) {
    int tid = threadIdx.x, warp = tid >> 5, lane = tid & 31;
    int u = blockIdx.x*8 + warp;
    int bn = u >> 12, p = u & 4095;
    int b = bn / N_;
    int c0 = lane*4;
    float gx = grid[p], gy = grid[4096 + p];
    float t[4]; float ss = 0.f, dum = 0.f;
#pragma unroll
    for (int i = 0; i < 4; i++) {
        int c = c0 + i;
        float we = W_bev[c*2+0]*gx + W_bev[c*2+1]*gy + b_bev[c];
        t[i] = we - g_cembed[bn*D_+c];
        ss += t[i]*t[i];
    }
    warpRed2(ss, dum);
    float inv = 1.0f / fmaxf(sqrtf(ss), 1e-12f);
    float q[4]; float s = 0.f, q2 = 0.f;
#pragma unroll
    for (int i = 0; i < 4; i++) {
        q[i] = t[i]*inv + x[(b*D_ + c0 + i)*4096 + p];
        s += q[i]; q2 += q[i]*q[i];
    }
    warpRed2(s, q2);
    float mean = s*(1.0f/128.0f);
    float var = fmaxf(q2*(1.0f/128.0f) - mean*mean, 0.f);
    float rstd = rsqrtf(var + 1e-5f);
    st_half4(&g_xq[u*D_ + c0],
             (q[0]-mean)*rstd, (q[1]-mean)*rstd, (q[2]-mean)*rstd, (q[3]-mean)*rstd);
}

// ---------------- fold attn LN into projection weights -----------------------
__global__ void __launch_bounds__(256) k_foldw(
        const float* __restrict__ aln_g, const float* __restrict__ aln_b,
        const float* __restrict__ aWqkv, const float* __restrict__ abqkv) {
    __shared__ float sm[16][129];
    __shared__ float bred[16][17];
    int idx = blockIdx.x, tid = threadIdx.x;
    int o0 = blockIdx.y*16;
    const float* W = aWqkv + idx*16384;
    const float* g = aln_g + idx*128;
    const float* bb = aln_b + idx*128;
    for (int k = tid; k < 2048; k += 256) {
        int c = k >> 4, o = k & 15;
        sm[o][c] = g[c] * W[c*128 + o0 + o];
    }
    {
        int o = tid & 15, cg = tid >> 4;
        float part = 0.f;
#pragma unroll
        for (int cc = 0; cc < 8; cc++) {
            int c = cg*8 + cc;
            part += bb[c] * W[c*128 + o0 + o];
        }
        bred[o][cg] = part;
    }
    __syncthreads();
    for (int k = tid; k < 1024; k += 256) {
        int o = k >> 6, c2 = (k & 63)*2;
        __half2 h = __floats2half2_rn(sm[o][c2], sm[o][c2+1]);
        *reinterpret_cast<__half2*>(&g_wfold[idx*16384 + (o0+o)*128 + c2]) = h;
    }
    if (tid < 16) {
        float a = 0.f;
#pragma unroll
        for (int cg = 0; cg < 16; cg++) a += bred[tid][cg];
        g_bfold[idx*128 + o0 + tid] = a + abqkv[idx*128 + o0 + tid];
    }
}

// ---------------- fold MLP LN into Wa (128 -> 256) ---------------------------
__global__ void __launch_bounds__(256) k_foldwa(
        const float* __restrict__ pn_g, const float* __restrict__ pn_b,
        const float* __restrict__ Wma, const float* __restrict__ bma) {
    __shared__ float sm[16][129];
    __shared__ float bred[16][17];
    int s = blockIdx.x, tid = threadIdx.x;
    int o0 = blockIdx.y*16;
    const float* W = Wma + s*128*256;
    const float* g = pn_g + s*128;
    const float* bb = pn_b + s*128;
    for (int k = tid; k < 2048; k += 256) {
        int c = k >> 4, o = k & 15;
        sm[o][c] = g[c] * W[c*256 + o0 + o];
    }
    {
        int o = tid & 15, cg = tid >> 4;
        float part = 0.f;
#pragma unroll
        for (int cc = 0; cc < 8; cc++) {
            int c = cg*8 + cc;
            part += bb[c] * W[c*256 + o0 + o];
        }
        bred[o][cg] = part;
    }
    __syncthreads();
    for (int k = tid; k < 1024; k += 256) {
        int o = k >> 6, c2 = (k & 63)*2;
        __half2 h = __floats2half2_rn(sm[o][c2], sm[o][c2+1]);
        *reinterpret_cast<__half2*>(&g_wafold[s*32768 + (o0+o)*128 + c2]) = h;
    }
    if (tid < 16) {
        float a = 0.f;
#pragma unroll
        for (int cg = 0; cg < 16; cg++) a += bred[tid][cg];
        g_bafold[s*256 + o0 + tid] = a + bma[s*256 + o0 + tid];
    }
}

// ---------------- transpose fp32 [R][C] -> fp16 [C][R] (dst by selector) -----
__global__ void __launch_bounds__(256) k_tr_h(int sel, const float* __restrict__ src,
                                              int R, int C) {
    __half* dst = (sel == 0) ? g_wpT
                : (sel == 1) ? (g_wpT + 16384)
                : (sel == 2) ? g_wmbT : (g_wmbT + 32768);
    __shared__ float t[32][33];
    int c0 = blockIdx.x*32, r0 = blockIdx.y*32;
    int cx = threadIdx.x & 31, ry = threadIdx.x >> 5;
    for (int rr = ry; rr < 32; rr += 8)
        t[rr][cx] = src[(r0+rr)*C + c0 + cx];
    __syncthreads();
    for (int cc = ry; cc < 32; cc += 8)
        dst[(c0+cc)*R + r0 + cx] = __float2half(t[cx][cc]);
}

// ---------------- fp32 -> fp16 copy (dst by selector) ------------------------
__global__ void k_cvt_h(int sel, const float* __restrict__ src) {
    __half* dst = sel ? g_wflH : g_wfpH;
    int i = blockIdx.x*256 + threadIdx.x;
    dst[i] = __float2half(src[i]);
}

// ---------------- prenorm: fp32 buf -> fp16 xhat (selector) ------------------
__global__ void __launch_bounds__(256) k_prenorm(int which) {
    const float* src = (which == 2) ? g_q2 : g_q1;
    __half* dst = (which == 1) ? g_xq1 : g_xm;
    int tid = threadIdx.x, warp = tid >> 5, lane = tid & 31;
    int u = blockIdx.x*8 + warp;
    float4 v = reinterpret_cast<const float4*>(src + u*D_)[lane];
    float s = v.x+v.y+v.z+v.w;
    float q = v.x*v.x+v.y*v.y+v.z*v.z+v.w*v.w;
    warpRed2(s, q);
    float mean = s*(1.0f/128.0f);
    float var = fmaxf(q*(1.0f/128.0f) - mean*mean, 0.f);
    float rstd = rsqrtf(var + 1e-5f);
    st_half4(&dst[u*D_ + lane*4],
             (v.x-mean)*rstd, (v.y-mean)*rstd, (v.z-mean)*rstd, (v.w-mean)*rstd);
}

// ---------------- device-side job table for the unified GEMM -----------------
__device__ __forceinline__ void gemm_job(
        int job, const float* extb, const float* extaux,
        const __half*& A, const __half*& B, const float*& bias, void*& out,
        const float*& aux, int& epi, float& scale, int& ldC) {
    const float QS = 0.17677669529663687f;
    scale = 1.f; ldC = 128; aux = nullptr; bias = nullptr;
    switch (job) {
    case 0:  A=g_fph; B=g_wfpH; out=g_xk; aux=g_kimg; epi=EPI_LN; break;
    case 1:  A=g_flh; B=g_wflH; out=g_xv; epi=EPI_LN; break;
    case 2:  A=g_xq;  B=g_wfold;          bias=g_bfold;     out=g_qh1; epi=EPI_HALF; scale=QS; break;
    case 3:  A=g_xk;  B=g_wfold+16384;    bias=g_bfold+128; out=g_kh1; epi=EPI_HALF; break;
    case 4:  A=g_xv;  B=g_wfold+2*16384;  bias=g_bfold+256; out=g_vh1; epi=EPI_HALF; break;
    case 5:  A=g_xk;  B=g_wfold+4*16384;  bias=g_bfold+512; out=g_kh2; epi=EPI_HALF; break;
    case 6:  A=g_xv;  B=g_wfold+5*16384;  bias=g_bfold+640; out=g_vh2; epi=EPI_HALF; break;
    case 7:  A=g_mo;  B=g_wpT;  bias=extb; out=g_q1; aux=extaux; epi=EPI_SKIP0; break;
    case 8:  A=g_xm;  B=g_wafold;         bias=g_bafold;     out=g_h;     epi=EPI_GELU; ldC=256; break;
    case 9:  A=g_xm;  B=g_wafold+16384;   bias=g_bafold+128; out=g_h+128; epi=EPI_GELU; ldC=256; break;
    case 10: A=g_h;   B=g_wmbT; bias=extb; out=g_q1; aux=g_q1; epi=EPI_RES; break;
    case 11: A=g_xq1; B=g_wfold+3*16384;  bias=g_bfold+384; out=g_qh2; epi=EPI_HALF; scale=QS; break;
    case 12: A=g_o2;  B=g_wpT+16384; bias=extb; out=g_q2; aux=g_q1; epi=EPI_SKIP1; break;
    case 13: A=g_xm;  B=g_wafold+32768;        bias=g_bafold+256; out=g_h;     epi=EPI_GELU; ldC=256; break;
    case 14: A=g_xm;  B=g_wafold+32768+16384;  bias=g_bafold+384; out=g_h+128; epi=EPI_GELU; ldC=256; break;
    default: A=g_h;   B=g_wmbT+32768; bias=extb; out=g_q2; aux=g_q2; epi=EPI_RES; break;
    }
}

// ---------------- unified HMMA GEMM with fused epilogues ---------------------
// C[M][128] = A[M][KT*128] @ B[128][KT*128]^T (+ epilogue). 256 thr, M-tile 128.
template<int KT>
__global__ void __launch_bounds__(256) k_gemm_ep(
        int job, const float* __restrict__ extb, const float* __restrict__ extaux) {
    const __half* A; const __half* Bw; const float* bias; void* outp;
    const float* aux; int epi; float scale; int ldC;
    gemm_job(job, extb, extaux, A, Bw, bias, outp, aux, epi, scale, ldC);

    extern __shared__ __half shh[];
    __half* As = shh;                 // [128][136]
    __half* Bs = shh + 128*136;
    int tid = threadIdx.x;
    int m0 = blockIdx.x * 128;
    const int KD = KT*128;
    int warp = tid >> 5, lane = tid & 31;
    int wm = (warp & 3) * 32, wn = (warp >> 2) * 64;
    int g = lane >> 2, tg = (lane & 3) * 2;
    float acc[2][8][4];
#pragma unroll
    for (int i = 0; i < 2; i++)
#pragma unroll
        for (int j = 0; j < 8; j++)
#pragma unroll
            for (int r = 0; r < 4; r++) acc[i][j][r] = 0.f;

    for (int kc = 0; kc < KT; kc++) {
        int r = tid >> 4, q = tid & 15;
        for (int rr = r; rr < 128; rr += 16) {
            *reinterpret_cast<int4*>(&As[rr*136 + q*8]) =
                *reinterpret_cast<const int4*>(&A[(m0+rr)*KD + kc*128 + q*8]);
            *reinterpret_cast<int4*>(&Bs[rr*136 + q*8]) =
                *reinterpret_cast<const int4*>(&Bw[rr*KD + kc*128 + q*8]);
        }
        __syncthreads();
#pragma unroll
        for (int ks = 0; ks < 8; ks++) {
            int k0 = ks*16;
            uint32_t a[2][4];
#pragma unroll
            for (int i = 0; i < 2; i++) {
                int mb = wm + i*16;
                a[i][0] = *reinterpret_cast<const uint32_t*>(&As[(mb+g  )*136 + k0+tg  ]);
                a[i][1] = *reinterpret_cast<const uint32_t*>(&As[(mb+8+g)*136 + k0+tg  ]);
                a[i][2] = *reinterpret_cast<const uint32_t*>(&As[(mb+g  )*136 + k0+8+tg]);
                a[i][3] = *reinterpret_cast<const uint32_t*>(&As[(mb+8+g)*136 + k0+8+tg]);
            }
#pragma unroll
            for (int j = 0; j < 8; j++) {
                uint32_t b0 = *reinterpret_cast<const uint32_t*>(&Bs[(wn+j*8+g)*136 + k0+tg  ]);
                uint32_t b1 = *reinterpret_cast<const uint32_t*>(&Bs[(wn+j*8+g)*136 + k0+8+tg]);
                mma16816(acc[0][j], a[0], b0, b1);
                mma16816(acc[1][j], a[1], b0, b1);
            }
        }
        __syncthreads();
    }

    if (epi == EPI_LN) {
        if (aux) {
#pragma unroll
            for (int i = 0; i < 2; i++)
#pragma unroll
            for (int j = 0; j < 8; j++) {
                int r0 = m0 + wm + i*16 + g, r1 = r0 + 8;
                int n = wn + j*8 + tg;
                acc[i][j][0] += aux[r0*D_ + n];
                acc[i][j][1] += aux[r0*D_ + n+1];
                acc[i][j][2] += aux[r1*D_ + n];
                acc[i][j][3] += aux[r1*D_ + n+1];
            }
        }
        float sum[2][2] = {{0,0},{0,0}}, sq[2][2] = {{0,0},{0,0}};
#pragma unroll
        for (int i = 0; i < 2; i++)
#pragma unroll
        for (int j = 0; j < 8; j++) {
            float a0 = acc[i][j][0], a1 = acc[i][j][1];
            float a2 = acc[i][j][2], a3 = acc[i][j][3];
            sum[i][0] += a0 + a1; sq[i][0] += a0*a0 + a1*a1;
            sum[i][1] += a2 + a3; sq[i][1] += a2*a2 + a3*a3;
        }
#pragma unroll
        for (int o = 1; o <= 2; o <<= 1) {
#pragma unroll
            for (int i = 0; i < 2; i++)
#pragma unroll
            for (int rh = 0; rh < 2; rh++) {
                sum[i][rh] += __shfl_xor_sync(0xffffffffu, sum[i][rh], o);
                sq[i][rh]  += __shfl_xor_sync(0xffffffffu, sq[i][rh], o);
            }
        }
        float* sred = reinterpret_cast<float*>(shh);   // [128][4]
        if ((lane & 3) == 0) {
#pragma unroll
            for (int i = 0; i < 2; i++)
#pragma unroll
            for (int rh = 0; rh < 2; rh++) {
                int row = wm + i*16 + rh*8 + g;
                sred[row*4 + (wn >> 6)*2 + 0] = sum[i][rh];
                sred[row*4 + (wn >> 6)*2 + 1] = sq[i][rh];
            }
        }
        __syncthreads();
        __half* O = reinterpret_cast<__half*>(outp);
#pragma unroll
        for (int i = 0; i < 2; i++)
#pragma unroll
        for (int rh = 0; rh < 2; rh++) {
            int row = wm + i*16 + rh*8 + g;
            float s = sred[row*4+0] + sred[row*4+2];
            float qq = sred[row*4+1] + sred[row*4+3];
            float mean = s*(1.0f/128.0f);
            float var = fmaxf(qq*(1.0f/128.0f) - mean*mean, 0.f);
            float rstd = rsqrtf(var + 1e-5f);
#pragma unroll
            for (int j = 0; j < 8; j++) {
                int n = wn + j*8 + tg;
                float v0 = (acc[i][j][rh*2+0]-mean)*rstd;
                float v1 = (acc[i][j][rh*2+1]-mean)*rstd;
                *reinterpret_cast<uint32_t*>(&O[(m0+row)*D_ + n]) = packh2(v0, v1);
            }
        }
    } else if (epi <= EPI_GELU) {
        __half* O = reinterpret_cast<__half*>(outp);
#pragma unroll
        for (int i = 0; i < 2; i++)
#pragma unroll
        for (int j = 0; j < 8; j++) {
            int n = wn + j*8 + tg;
            float b0 = bias[n], b1 = bias[n+1];
            int r0 = m0 + wm + i*16 + g, r1 = r0 + 8;
            float v0 = acc[i][j][0]+b0, v1 = acc[i][j][1]+b1;
            float v2 = acc[i][j][2]+b0, v3 = acc[i][j][3]+b1;
            if (epi == EPI_GELU) {
                v0 = geluf(v0); v1 = geluf(v1); v2 = geluf(v2); v3 = geluf(v3);
            } else {
                v0 *= scale; v1 *= scale; v2 *= scale; v3 *= scale;
            }
            *reinterpret_cast<uint32_t*>(&O[r0*ldC + n]) = packh2(v0, v1);
            *reinterpret_cast<uint32_t*>(&O[r1*ldC + n]) = packh2(v2, v3);
        }
    } else {
        float* O = reinterpret_cast<float*>(outp);
#pragma unroll
        for (int i = 0; i < 2; i++)
#pragma unroll
        for (int j = 0; j < 8; j++) {
            int n = wn + j*8 + tg;
            float b0 = bias[n], b1 = bias[n+1];
            int r0 = m0 + wm + i*16 + g, r1 = r0 + 8;
            float v[4] = {acc[i][j][0]+b0, acc[i][j][1]+b1,
                          acc[i][j][2]+b0, acc[i][j][3]+b1};
            int rows[2] = {r0, r1};
#pragma unroll
            for (int rh = 0; rh < 2; rh++) {
#pragma unroll
                for (int d = 0; d < 2; d++) {
                    int row = rows[rh], nn = n + d;
                    float sk;
                    if (epi == EPI_SKIP0) {
                        int b = row >> 12, p = row & 4095;
                        sk = aux[(b*D_ + nn)*4096 + p];
                    } else {
                        sk = aux[row*D_ + nn];
                    }
                    O[row*D_ + nn] = v[rh*2+d] + sk;
                }
            }
        }
    }
}

// ---------------- tensor-core flash attention (fp16 in / fp16 out) -----------
template<int MT, int NW>
__global__ void __launch_bounds__(NW*32) k_attn_mma(int stage) {
    const int NQ = MT*16*NW;
    extern __shared__ __half sha[];
    __half* Qs = sha;                  // [NQ][40]
    __half* Ks = Qs + NQ*40;           // [264][40]
    __half* Vt = Ks + 264*40;          // [32][274]
    int bl = blockIdx.x, hh = blockIdx.y, tid = threadIdx.x;
    int b = bl >> 6, l = bl & 63;
    const __half* qsrc; const __half* ksrc; const __half* vsrc;
    if (stage == 0) { qsrc = g_qh1; ksrc = g_kh1; vsrc = g_vh1; }
    else            { qsrc = g_qh2; ksrc = g_kh2; vsrc = g_vh2; }
    for (int idx = tid; idx < NQ*16; idx += NW*32) {
        int row = idx >> 4, c2 = idx & 15;
        int pix;
        if (stage == 0) {
            int n = row >> 6, ij = row & 63;
            pix = (b*N_+n)*4096 + ((l>>3)*8 + (ij>>3))*64 + (l&7)*8 + (ij&7);
        } else {
            pix = b*4096 + ((l>>3)*8 + (row>>3))*64 + (l&7)*8 + (row&7);
        }
        *reinterpret_cast<uint32_t*>(&Qs[row*40 + 2*c2]) =
            *reinterpret_cast<const uint32_t*>(&qsrc[pix*D_ + hh*32 + 2*c2]);
    }
    for (int idx = tid; idx < NKV*16; idx += NW*32) {
        int kv = idx >> 4, c2 = idx & 15;
        int n = kv/44, f = kv%44, f1 = f/11, f2 = f%11;
        int h, w;
        if (stage == 0) { h = (l>>3)*4 + f1; w = (l&7)*11 + f2; }
        else            { h = f1*8 + (l>>3); w = f2*8 + (l&7); }
        int pix = (b*N_+n)*PIX + h*FW_ + w;
        *reinterpret_cast<uint32_t*>(&Ks[kv*40 + 2*c2]) =
            *reinterpret_cast<const uint32_t*>(&ksrc[pix*D_ + hh*32 + 2*c2]);
    }
    for (int idx = tid; idx < NKV*32; idx += NW*32) {
        int kv = idx >> 5, ch = idx & 31;
        int n = kv/44, f = kv%44, f1 = f/11, f2 = f%11;
        int h, w;
        if (stage == 0) { h = (l>>3)*4 + f1; w = (l&7)*11 + f2; }
        else            { h = f1*8 + (l>>3); w = f2*8 + (l&7); }
        int pix = (b*N_+n)*PIX + h*FW_ + w;
        Vt[ch*274 + kv] = vsrc[pix*D_ + hh*32 + ch];
    }
    for (int idx = tid; idx < 32*10; idx += NW*32) {
        int ch = idx / 10, c = idx % 10;
        Vt[ch*274 + 264 + c] = __half(0.f);
    }
    __syncthreads();

    int warp = tid >> 5, lane = tid & 31;
    int g = lane >> 2, t4 = lane & 3;
    int row0 = warp * MT * 16;

    uint32_t af[MT][2][4];
#pragma unroll
    for (int mt = 0; mt < MT; mt++)
#pragma unroll
        for (int ks = 0; ks < 2; ks++) {
            int r = row0 + mt*16, k0 = ks*16;
            af[mt][ks][0] = *reinterpret_cast<const uint32_t*>(&Qs[(r+g  )*40 + k0 + 2*t4    ]);
            af[mt][ks][1] = *reinterpret_cast<const uint32_t*>(&Qs[(r+8+g)*40 + k0 + 2*t4    ]);
            af[mt][ks][2] = *reinterpret_cast<const uint32_t*>(&Qs[(r+g  )*40 + k0 + 8 + 2*t4]);
            af[mt][ks][3] = *reinterpret_cast<const uint32_t*>(&Qs[(r+8+g)*40 + k0 + 8 + 2*t4]);
        }

    float m[MT][2], lsum[MT][2], O[MT][4][4];
#pragma unroll
    for (int mt = 0; mt < MT; mt++) {
        m[mt][0] = -1e30f; m[mt][1] = -1e30f;
        lsum[mt][0] = 0.f; lsum[mt][1] = 0.f;
#pragma unroll
        for (int j = 0; j < 4; j++)
#pragma unroll
            for (int r = 0; r < 4; r++) O[mt][j][r] = 0.f;
    }

    for (int c = 0; c < 17; c++) {
        int kv0 = c*16;
        int nt = (c == 16) ? 1 : 2;
        uint32_t bf[2][2][2];
#pragma unroll
        for (int n = 0; n < 2; n++) {
            if (n < nt) {
#pragma unroll
                for (int ks = 0; ks < 2; ks++) {
                    bf[n][ks][0] = *reinterpret_cast<const uint32_t*>(&Ks[(kv0+n*8+g)*40 + ks*16 + 2*t4    ]);
                    bf[n][ks][1] = *reinterpret_cast<const uint32_t*>(&Ks[(kv0+n*8+g)*40 + ks*16 + 8 + 2*t4]);
                }
            }
        }
        float S[MT][2][4];
#pragma unroll
        for (int mt = 0; mt < MT; mt++)
#pragma unroll
            for (int n = 0; n < 2; n++)
#pragma unroll
                for (int r = 0; r < 4; r++) S[mt][n][r] = 0.f;
#pragma unroll
        for (int mt = 0; mt < MT; mt++)
#pragma unroll
            for (int n = 0; n < 2; n++) {
                if (n < nt) {
                    mma16816(S[mt][n], af[mt][0], bf[n][0][0], bf[n][0][1]);
                    mma16816(S[mt][n], af[mt][1], bf[n][1][0], bf[n][1][1]);
                }
            }
#pragma unroll
        for (int mt = 0; mt < MT; mt++) {
            float mx0 = fmaxf(S[mt][0][0], S[mt][0][1]);
            float mx8 = fmaxf(S[mt][0][2], S[mt][0][3]);
            if (nt == 2) {
                mx0 = fmaxf(mx0, fmaxf(S[mt][1][0], S[mt][1][1]));
                mx8 = fmaxf(mx8, fmaxf(S[mt][1][2], S[mt][1][3]));
            }
            mx0 = fmaxf(mx0, __shfl_xor_sync(0xffffffffu, mx0, 1));
            mx0 = fmaxf(mx0, __shfl_xor_sync(0xffffffffu, mx0, 2));
            mx8 = fmaxf(mx8, __shfl_xor_sync(0xffffffffu, mx8, 1));
            mx8 = fmaxf(mx8, __shfl_xor_sync(0xffffffffu, mx8, 2));
            float mn0 = fmaxf(m[mt][0], mx0), mn8 = fmaxf(m[mt][1], mx8);
            float cr0 = __expf(m[mt][0] - mn0), cr8 = __expf(m[mt][1] - mn8);
            m[mt][0] = mn0; m[mt][1] = mn8;
            uint32_t pa[4];
            float p00 = __expf(S[mt][0][0] - mn0), p01 = __expf(S[mt][0][1] - mn0);
            float p02 = __expf(S[mt][0][2] - mn8), p03 = __expf(S[mt][0][3] - mn8);
            float rs0 = p00 + p01, rs8 = p02 + p03;
            pa[0] = packh2(p00, p01);
            pa[1] = packh2(p02, p03);
            if (nt == 2) {
                float p10 = __expf(S[mt][1][0] - mn0), p11 = __expf(S[mt][1][1] - mn0);
                float p12 = __expf(S[mt][1][2] - mn8), p13 = __expf(S[mt][1][3] - mn8);
                rs0 += p10 + p11; rs8 += p12 + p13;
                pa[2] = packh2(p10, p11);
                pa[3] = packh2(p12, p13);
            } else { pa[2] = 0u; pa[3] = 0u; }
            rs0 += __shfl_xor_sync(0xffffffffu, rs0, 1);
            rs0 += __shfl_xor_sync(0xffffffffu, rs0, 2);
            rs8 += __shfl_xor_sync(0xffffffffu, rs8, 1);
            rs8 += __shfl_xor_sync(0xffffffffu, rs8, 2);
            lsum[mt][0] = lsum[mt][0]*cr0 + rs0;
            lsum[mt][1] = lsum[mt][1]*cr8 + rs8;
#pragma unroll
            for (int j = 0; j < 4; j++) {
                O[mt][j][0] *= cr0; O[mt][j][1] *= cr0;
                O[mt][j][2] *= cr8; O[mt][j][3] *= cr8;
                uint32_t vb0 = *reinterpret_cast<const uint32_t*>(&Vt[(j*8+g)*274 + kv0 + 2*t4    ]);
                uint32_t vb1 = *reinterpret_cast<const uint32_t*>(&Vt[(j*8+g)*274 + kv0 + 8 + 2*t4]);
                mma16816(O[mt][j], pa, vb0, vb1);
            }
        }
    }
#pragma unroll
    for (int mt = 0; mt < MT; mt++) {
        float i0 = 1.0f / lsum[mt][0], i8 = 1.0f / lsum[mt][1];
        int r0 = row0 + mt*16 + g;
        int r1 = r0 + 8;
        int out0, out1;
        if (stage == 0) {
            out0 = bl*NQ + r0;
            out1 = bl*NQ + r1;
        } else {
            out0 = b*4096 + ((l>>3)*8 + (r0>>3))*64 + (l&7)*8 + (r0&7);
            out1 = b*4096 + ((l>>3)*8 + (r1>>3))*64 + (l&7)*8 + (r1&7);
        }
        __half* Od = (stage == 0) ? g_otok : g_o2;
#pragma unroll
        for (int j = 0; j < 4; j++) {
            int chn = hh*32 + j*8 + 2*t4;
            *reinterpret_cast<uint32_t*>(&Od[out0*D_ + chn]) = packh2(O[mt][j][0]*i0, O[mt][j][1]*i0);
            *reinterpret_cast<uint32_t*>(&Od[out1*D_ + chn]) = packh2(O[mt][j][2]*i8, O[mt][j][3]*i8);
        }
    }
}

// ---------------- camera mean of stage-1 attention output --------------------
__global__ void __launch_bounds__(256) k_mean() {
    int tid = threadIdx.x;
    int u = blockIdx.x*4 + (tid >> 6);
    int c2 = tid & 63;
    int b = u >> 12, p = u & 4095;
    int hh_ = p >> 6, ww = p & 63;
    int l = ((hh_ >> 3) << 3) + (ww >> 3);
    int base = ((b*64 + l)*NQ1 + (hh_&7)*8 + (ww&7))*D_ + c2*2;
    float sx = 0.f, sy = 0.f;
#pragma unroll
    for (int n = 0; n < 6; n++) {
        __half2 h = *reinterpret_cast<const __half2*>(&g_otok[base + n*64*D_]);
        float2 f = __half22float2(h);
        sx += f.x; sy += f.y;
    }
    *reinterpret_cast<__half2*>(&g_mo[u*D_ + c2*2]) =
        __floats2half2_rn(sx*(1.0f/6.0f), sy*(1.0f/6.0f));
}

// ---------------- final LN + transpose, warp per token -----------------------
__global__ void __launch_bounds__(256) k_final(
        const float* __restrict__ pg, const float* __restrict__ pb,
        float* __restrict__ out) {
    int tid = threadIdx.x, warp = tid >> 5, lane = tid & 31;
    int u = blockIdx.x*8 + warp;
    int b = u >> 12, p = u & 4095;
    float4 v = reinterpret_cast<const float4*>(g_q2 + u*D_)[lane];
    float s = v.x+v.y+v.z+v.w;
    float q = v.x*v.x+v.y*v.y+v.z*v.z+v.w*v.w;
    warpRed2(s, q);
    float mean = s*(1.0f/128.0f);
    float var = fmaxf(q*(1.0f/128.0f) - mean*mean, 0.f);
    float rstd = rsqrtf(var + 1e-5f);
    int c0 = lane*4;
    out[(b*D_+c0+0)*4096 + p] = (v.x-mean)*rstd*pg[c0+0]+pb[c0+0];
    out[(b*D_+c0+1)*4096 + p] = (v.y-mean)*rstd*pg[c0+1]+pb[c0+1];
    out[(b*D_+c0+2)*4096 + p] = (v.z-mean)*rstd*pg[c0+2]+pb[c0+2];
    out[(b*D_+c0+3)*4096 + p] = (v.w-mean)*rstd*pg[c0+3]+pb[c0+3];
}

// ---------------------------------------------------------------------------
extern "C" void kernel_launch(void* const* d_in, const int* in_sizes, int n_in,
                              void* d_out, int out_size) {
    (void)in_sizes; (void)n_in; (void)out_size;
    const float* x        = (const float*)d_in[1];
    const float* grid     = (const float*)d_in[2];
    const float* feature  = (const float*)d_in[3];
    const float* I_inv    = (const float*)d_in[4];
    const float* E_inv    = (const float*)d_in[5];
    const float* bn_fl_g  = (const float*)d_in[6];
    const float* bn_fl_b  = (const float*)d_in[7];
    const float* W_fl     = (const float*)d_in[8];
    const float* bn_fp_g  = (const float*)d_in[9];
    const float* bn_fp_b  = (const float*)d_in[10];
    const float* W_fp     = (const float*)d_in[11];
    const float* W_bev    = (const float*)d_in[12];
    const float* b_bev    = (const float*)d_in[13];
    const float* W_img    = (const float*)d_in[14];
    const float* W_cam    = (const float*)d_in[15];
    const float* aln_g    = (const float*)d_in[16];
    const float* aln_b    = (const float*)d_in[17];
    const float* aWqkv    = (const float*)d_in[18];
    const float* abqkv    = (const float*)d_in[19];
    const float* aWp      = (const float*)d_in[20];
    const float* abp      = (const float*)d_in[21];
    const float* pn_g     = (const float*)d_in[22];
    const float* pn_b     = (const float*)d_in[23];
    const float* Wma      = (const float*)d_in[24];
    const float* bma      = (const float*)d_in[25];
    const float* Wmb      = (const float*)d_in[26];
    const float* bmb      = (const float*)d_in[27];
    const float* post_g   = (const float*)d_in[28];
    const float* post_b   = (const float*)d_in[29];
    float* out = (float*)d_out;

    const int GSM = 2*128*136*2;             // 69632
    const int PSM = 2*128*33*4 + 32*128*4;   // 50176
    const int A1SM = (384*40 + 264*40 + 32*274) * 2;
    const int A2SM = (64*40 + 264*40 + 32*274) * 2;
    cudaFuncSetAttribute(k_prep, cudaFuncAttributeMaxDynamicSharedMemorySize, PSM);
    cudaFuncSetAttribute(k_gemm_ep<1>, cudaFuncAttributeMaxDynamicSharedMemorySize, GSM);
    cudaFuncSetAttribute(k_gemm_ep<2>, cudaFuncAttributeMaxDynamicSharedMemorySize, GSM);
    cudaFuncSetAttribute(k_attn_mma<3,8>, cudaFuncAttributeMaxDynamicSharedMemorySize, A1SM);
    cudaFuncSetAttribute(k_attn_mma<1,4>, cudaFuncAttributeMaxDynamicSharedMemorySize, A2SM);

    // prep + weight prep
    k_cembed<<<B_*N_, 128>>>(E_inv, W_cam);
    k_prep<<<B_*N_*88, 128, PSM>>>(feature, I_inv, E_inv, W_img,
                                   bn_fp_g, bn_fp_b, bn_fl_g, bn_fl_b);
    k_query<<<NQP/8, 256>>>(grid, x, W_bev, b_bev);
    k_foldw<<<dim3(6, 8), 256>>>(aln_g, aln_b, aWqkv, abqkv);
    k_foldwa<<<dim3(2, 16), 256>>>(pn_g, pn_b, Wma, bma);
    k_tr_h<<<dim3(4, 4), 256>>>(0, aWp, 128, 128);
    k_tr_h<<<dim3(4, 4), 256>>>(1, aWp + 16384, 128, 128);
    k_tr_h<<<dim3(4, 8), 256>>>(2, Wmb, 256, 128);
    k_tr_h<<<dim3(4, 8), 256>>>(3, Wmb + 32768, 256, 128);
    k_cvt_h<<<64, 256>>>(0, W_fp);
    k_cvt_h<<<64, 256>>>(1, W_fl);

    // conv GEMMs with LN epilogue -> xk/xv
    k_gemm_ep<1><<<NPX/128, 256, GSM>>>(0, nullptr, nullptr);
    k_gemm_ep<1><<<NPX/128, 256, GSM>>>(1, nullptr, nullptr);

    // projections (fp16 out; Q pre-scaled)
    k_gemm_ep<1><<<NQP/128, 256, GSM>>>(2, nullptr, nullptr);   // Q1
    k_gemm_ep<1><<<NPX/128, 256, GSM>>>(3, nullptr, nullptr);   // K1
    k_gemm_ep<1><<<NPX/128, 256, GSM>>>(4, nullptr, nullptr);   // V1
    k_gemm_ep<1><<<NPX/128, 256, GSM>>>(5, nullptr, nullptr);   // K2
    k_gemm_ep<1><<<NPX/128, 256, GSM>>>(6, nullptr, nullptr);   // V2

    // stage 1
    k_attn_mma<3,8><<<dim3(B_*64, 4), 256, A1SM>>>(0);
    k_mean<<<NTK/4, 256>>>();
    k_gemm_ep<1><<<NTK/128, 256, GSM>>>(7, abp, x);             // proj + skip
    k_prenorm<<<NTK/8, 256>>>(0);
    k_gemm_ep<1><<<NTK/128, 256, GSM>>>(8, nullptr, nullptr);   // gelu a
    k_gemm_ep<1><<<NTK/128, 256, GSM>>>(9, nullptr, nullptr);   // gelu b
    k_gemm_ep<2><<<NTK/128, 256, GSM>>>(10, bmb, nullptr);      // residual

    // stage 2
    k_prenorm<<<NTK/8, 256>>>(1);
    k_gemm_ep<1><<<NTK/128, 256, GSM>>>(11, nullptr, nullptr);  // Q2
    k_attn_mma<1,4><<<dim3(B_*64, 4), 128, A2SM>>>(1);
    k_gemm_ep<1><<<NTK/128, 256, GSM>>>(12, abp + 128, nullptr);// proj + skip
    k_prenorm<<<NTK/8, 256>>>(2);
    k_gemm_ep<1><<<NTK/128, 256, GSM>>>(13, nullptr, nullptr);  // gelu a
    k_gemm_ep<1><<<NTK/128, 256, GSM>>>(14, nullptr, nullptr);  // gelu b
    k_gemm_ep<2><<<NTK/128, 256, GSM>>>(15, bmb + 128, nullptr);// residual

    k_final<<<NTK/8, 256>>>(post_g, post_b, out);
}

// round 11
// speedup vs baseline: 6.3502x; 1.0432x over previous
#include <cuda_runtime.h>
#include <cuda_fp16.h>
#include <math.h>
#include <stdint.h>

#define B_   2
#define N_   6
#define FH_  32
#define FW_  88
#define PIX  (FH_*FW_)     // 2816
#define D_   128
#define NKV  264
#define NQ1  384
#define NPX  (B_*N_*PIX)   // 33792
#define NQP  (B_*N_*4096)  // 49152
#define NTK  (B_*4096)     // 8192

// epilogue modes
#define EPI_HALF  0
#define EPI_GELU  1
#define EPI_LN    2
#define EPI_SKLN0 3
#define EPI_SKLN1 4
#define EPI_RESLN 5
#define EPI_FIN   6

// ---------------- scratch globals (no runtime allocation) -------------------
__device__ __align__(16) __half g_fph[NPX*D_];
__device__ __align__(16) __half g_flh[NPX*D_];
__device__ __align__(16) float  g_kimg[NPX*D_];
__device__ __align__(16) __half g_xq [NQP*D_];
__device__ __align__(16) __half g_xk [NPX*D_];
__device__ __align__(16) __half g_xv [NPX*D_];
__device__ __align__(16) __half g_xq1[NTK*D_];
__device__ __align__(16) __half g_xm [NTK*D_];
__device__ __align__(16) __half g_wfold[6*D_*D_];
__device__ float  g_bfold[6*D_];
__device__ __align__(16) __half g_wafold[2*256*D_];
__device__ float  g_bafold[2*256];
__device__ __align__(16) __half g_wmbT[2*D_*256];
__device__ __align__(16) __half g_wpT[2*D_*D_];
__device__ __align__(16) __half g_wfpH[D_*D_];
__device__ __align__(16) __half g_wflH[D_*D_];
__device__ __align__(16) __half g_qh1[NQP*D_];
__device__ __align__(16) __half g_kh1[NPX*D_];
__device__ __align__(16) __half g_vh1[NPX*D_];
__device__ __align__(16) __half g_qh2[NTK*D_];
__device__ __align__(16) __half g_kh2[NPX*D_];
__device__ __align__(16) __half g_vh2[NPX*D_];
__device__ __align__(16) __half g_otok[B_*64*NQ1*D_];
__device__ __align__(16) __half g_o2[NTK*D_];
__device__ __align__(16) __half g_h[NTK*256];
__device__ __align__(16) float  g_q1[NTK*D_];
__device__ __align__(16) float  g_q2[NTK*D_];

__device__ __forceinline__ void warpRed2(float& s, float& q) {
#pragma unroll
    for (int o = 16; o; o >>= 1) {
        s += __shfl_xor_sync(0xffffffffu, s, o);
        q += __shfl_xor_sync(0xffffffffu, q, o);
    }
}

__device__ __forceinline__ void st_half4(__half* dst, float a, float b, float c, float d) {
    __half2* p = reinterpret_cast<__half2*>(dst);
    p[0] = __floats2half2_rn(a, b);
    p[1] = __floats2half2_rn(c, d);
}

__device__ __forceinline__ uint32_t packh2(float a, float b) {
    __half2 h = __floats2half2_rn(a, b);
    return *reinterpret_cast<uint32_t*>(&h);
}

__device__ __forceinline__ float geluf(float h) {
    return h * 0.5f * (1.0f + erff(h * 0.70710678118654752f));
}

__device__ __forceinline__ void mma16816(float* c, const uint32_t* a,
                                         uint32_t b0, uint32_t b1) {
    asm volatile(
        "mma.sync.aligned.m16n8k16.row.col.f32.f16.f16.f32 "
        "{%0,%1,%2,%3}, {%4,%5,%6,%7}, {%8,%9}, {%0,%1,%2,%3};\n"
        : "+f"(c[0]), "+f"(c[1]), "+f"(c[2]), "+f"(c[3])
        : "r"(a[0]), "r"(a[1]), "r"(a[2]), "r"(a[3]), "r"(b0), "r"(b1));
}

// ---------------- merged weight prep (one launch, block-range dispatch) ------
__global__ void __launch_bounds__(256) k_wprep(
        const float* __restrict__ aln_g, const float* __restrict__ aln_b,
        const float* __restrict__ aWqkv, const float* __restrict__ abqkv,
        const float* __restrict__ pn_g, const float* __restrict__ pn_b,
        const float* __restrict__ Wma, const float* __restrict__ bma,
        const float* __restrict__ aWp, const float* __restrict__ Wmb,
        const float* __restrict__ W_fp, const float* __restrict__ W_fl) {
    __shared__ float sm[16][129];
    __shared__ float bred[16][17];
    int blk = blockIdx.x, tid = threadIdx.x;
    if (blk < 48) {
        // fold attn LN into QKV weights
        int idx = blk >> 3, o0 = (blk & 7) * 16;
        const float* W = aWqkv + idx*16384;
        const float* g = aln_g + idx*128;
        const float* bb = aln_b + idx*128;
        for (int k = tid; k < 2048; k += 256) {
            int c = k >> 4, o = k & 15;
            sm[o][c] = g[c] * W[c*128 + o0 + o];
        }
        {
            int o = tid & 15, cg = tid >> 4;
            float part = 0.f;
#pragma unroll
            for (int cc = 0; cc < 8; cc++) {
                int c = cg*8 + cc;
                part += bb[c] * W[c*128 + o0 + o];
            }
            bred[o][cg] = part;
        }
        __syncthreads();
        for (int k = tid; k < 1024; k += 256) {
            int o = k >> 6, c2 = (k & 63)*2;
            *reinterpret_cast<__half2*>(&g_wfold[idx*16384 + (o0+o)*128 + c2]) =
                __floats2half2_rn(sm[o][c2], sm[o][c2+1]);
        }
        if (tid < 16) {
            float a = 0.f;
#pragma unroll
            for (int cg = 0; cg < 16; cg++) a += bred[tid][cg];
            g_bfold[idx*128 + o0 + tid] = a + abqkv[idx*128 + o0 + tid];
        }
    } else if (blk < 80) {
        // fold MLP LN into Wa
        int t = blk - 48;
        int s = t >> 4, o0 = (t & 15) * 16;
        const float* W = Wma + s*128*256;
        const float* g = pn_g + s*128;
        const float* bb = pn_b + s*128;
        for (int k = tid; k < 2048; k += 256) {
            int c = k >> 4, o = k & 15;
            sm[o][c] = g[c] * W[c*256 + o0 + o];
        }
        {
            int o = tid & 15, cg = tid >> 4;
            float part = 0.f;
#pragma unroll
            for (int cc = 0; cc < 8; cc++) {
                int c = cg*8 + cc;
                part += bb[c] * W[c*256 + o0 + o];
            }
            bred[o][cg] = part;
        }
        __syncthreads();
        for (int k = tid; k < 1024; k += 256) {
            int o = k >> 6, c2 = (k & 63)*2;
            *reinterpret_cast<__half2*>(&g_wafold[s*32768 + (o0+o)*128 + c2]) =
                __floats2half2_rn(sm[o][c2], sm[o][c2+1]);
        }
        if (tid < 16) {
            float a = 0.f;
#pragma unroll
            for (int cg = 0; cg < 16; cg++) a += bred[tid][cg];
            g_bafold[s*256 + o0 + tid] = a + bma[s*256 + o0 + tid];
        }
    } else if (blk < 176) {
        // transpose fp32 [R][C] -> fp16 [C][R]
        int t = blk - 80;
        const float* src; __half* dst; int R, C, bx, by;
        if (t < 16)      { src = aWp;          dst = g_wpT;          R=128; C=128; bx=t&3;      by=t>>2; }
        else if (t < 32) { src = aWp+16384;    dst = g_wpT+16384;    R=128; C=128; bx=(t-16)&3; by=(t-16)>>2; }
        else if (t < 64) { src = Wmb;          dst = g_wmbT;         R=256; C=128; bx=(t-32)&3; by=(t-32)>>2; }
        else             { src = Wmb+32768;    dst = g_wmbT+32768;   R=256; C=128; bx=(t-64)&3; by=(t-64)>>2; }
        float (*tb)[33] = reinterpret_cast<float(*)[33]>(&sm[0][0]);
        int c0 = bx*32, r0 = by*32;
        int cx = tid & 31, ry = tid >> 5;
        for (int rr = ry; rr < 32; rr += 8)
            tb[rr][cx] = src[(r0+rr)*C + c0 + cx];
        __syncthreads();
        for (int cc = ry; cc < 32; cc += 8)
            dst[(c0+cc)*R + r0 + cx] = __float2half(tb[cx][cc]);
    } else {
        // fp32 -> fp16 conv weights
        int t = blk - 176;
        const float* src = (t < 64) ? W_fp : W_fl;
        __half* dst = (t < 64) ? g_wfpH : g_wflH;
        int i = (t & 63)*256 + tid;
        dst[i] = __float2half(src[i]);
    }
}

// ---------------- prep: BN-ReLU fp16 feats + image embedding -----------------
__global__ void __launch_bounds__(128) k_prep(
        const float* __restrict__ feat,
        const float* __restrict__ I_inv, const float* __restrict__ E_inv,
        const float* __restrict__ W_img, const float* __restrict__ W_cam,
        const float* __restrict__ fp_g, const float* __restrict__ fp_b,
        const float* __restrict__ fl_g, const float* __restrict__ fl_b) {
    extern __shared__ float sh[];
    float* sfp  = sh;                 // [128][33]
    float* sfl  = sh + 128*33;
    float* kimg = sh + 2*128*33;      // [32][128]
    int blk = blockIdx.x, tid = threadIdx.x;
    int bn = blk / 88, p0 = (blk % 88) * 32;
    int warp = tid >> 5, lane = tid & 31;

    const float invs = rsqrtf(1.0f + 1e-5f);
    for (int k = tid; k < 4096; k += 128) {
        int c = k >> 5, pp = k & 31;
        float f = feat[(bn*D_ + c)*PIX + p0 + pp];
        sfp[c*33+pp] = fmaxf(f * invs * fp_g[c] + fp_b[c], 0.f);
        sfl[c*33+pp] = fmaxf(f * invs * fl_g[c] + fl_b[c], 0.f);
    }
    float e3[4];
#pragma unroll
    for (int i = 0; i < 4; i++) e3[i] = E_inv[bn*16 + i*4 + 3];
    for (int it = 0; it < 8; it++) {
        int tt = it*4 + warp;
        int p = p0 + tt, fh = p / FW_, fw = p % FW_;
        float px = (float)fw * (480.0f / 87.0f);
        float py = (float)fh * (224.0f / 31.0f);
        float cam[4];
#pragma unroll
        for (int i = 0; i < 3; i++)
            cam[i] = I_inv[bn*9+i*3+0]*px + I_inv[bn*9+i*3+1]*py + I_inv[bn*9+i*3+2];
        cam[3] = 1.0f;
        float dd[4];
#pragma unroll
        for (int i = 0; i < 4; i++)
            dd[i] = E_inv[bn*16+i*4+0]*cam[0] + E_inv[bn*16+i*4+1]*cam[1]
                  + E_inv[bn*16+i*4+2]*cam[2] + E_inv[bn*16+i*4+3]*cam[3];
        int c0 = lane*4;
        float t[4]; float ssum = 0.f, dum = 0.f;
#pragma unroll
        for (int i = 0; i < 4; i++) {
            int c = c0+i;
            float de = W_img[c*4+0]*dd[0] + W_img[c*4+1]*dd[1]
                     + W_img[c*4+2]*dd[2] + W_img[c*4+3]*dd[3];
            float ce = W_cam[c*4+0]*e3[0] + W_cam[c*4+1]*e3[1]
                     + W_cam[c*4+2]*e3[2] + W_cam[c*4+3]*e3[3];
            t[i] = de - ce;
            ssum += t[i]*t[i];
        }
        warpRed2(ssum, dum);
        float inv = 1.0f / fmaxf(sqrtf(ssum), 1e-12f);
#pragma unroll
        for (int i = 0; i < 4; i++) kimg[tt*128 + c0 + i] = t[i]*inv;
    }
    __syncthreads();
    for (int pp = 0; pp < 32; pp++) {
        int row = bn*PIX + p0 + pp;
        g_fph[row*D_ + tid] = __float2half(sfp[tid*33 + pp]);
        g_flh[row*D_ + tid] = __float2half(sfl[tid*33 + pp]);
        g_kimg[row*D_ + tid] = kimg[pp*128 + tid];
    }
}

// ---------------- query -> LN'd fp16 xhat, warp per pixel --------------------
__global__ void __launch_bounds__(256) k_query(
        const float* __restrict__ grid, const float* __restrict__ x,
        const float* __restrict__ W_bev, const float* __restrict__ b_bev,
        const float* __restrict__ E_inv, const float* __restrict__ W_cam) {
    int tid = threadIdx.x, warp = tid >> 5, lane = tid & 31;
    int u = blockIdx.x*8 + warp;
    int bn = u >> 12, p = u & 4095;
    int b = bn / N_;
    int c0 = lane*4;
    float e3[4];
#pragma unroll
    for (int i = 0; i < 4; i++) e3[i] = E_inv[bn*16 + i*4 + 3];
    float gx = grid[p], gy = grid[4096 + p];
    float t[4]; float ss = 0.f, dum = 0.f;
#pragma unroll
    for (int i = 0; i < 4; i++) {
        int c = c0 + i;
        float we = W_bev[c*2+0]*gx + W_bev[c*2+1]*gy + b_bev[c];
        float ce = W_cam[c*4+0]*e3[0] + W_cam[c*4+1]*e3[1]
                 + W_cam[c*4+2]*e3[2] + W_cam[c*4+3]*e3[3];
        t[i] = we - ce;
        ss += t[i]*t[i];
    }
    warpRed2(ss, dum);
    float inv = 1.0f / fmaxf(sqrtf(ss), 1e-12f);
    float q[4]; float s = 0.f, q2 = 0.f;
#pragma unroll
    for (int i = 0; i < 4; i++) {
        q[i] = t[i]*inv + x[(b*D_ + c0 + i)*4096 + p];
        s += q[i]; q2 += q[i]*q[i];
    }
    warpRed2(s, q2);
    float mean = s*(1.0f/128.0f);
    float var = fmaxf(q2*(1.0f/128.0f) - mean*mean, 0.f);
    float rstd = rsqrtf(var + 1e-5f);
    st_half4(&g_xq[u*D_ + c0],
             (q[0]-mean)*rstd, (q[1]-mean)*rstd, (q[2]-mean)*rstd, (q[3]-mean)*rstd);
}

// ---------------- device-side job table for the unified GEMM -----------------
__device__ __forceinline__ void gemm_job(
        int job, const float* extb,
        const __half*& A, const __half*& B, const float*& bias,
        __half*& oh, float*& of, const float*& aux,
        int& epi, float& scale, int& ldC) {
    const float QS = 0.17677669529663687f;
    scale = 1.f; ldC = 128; aux = nullptr; bias = nullptr; oh = nullptr; of = nullptr;
    switch (job) {
    case 0:  A=g_fph; B=g_wfpH; oh=g_xk; aux=g_kimg; epi=EPI_LN; break;
    case 1:  A=g_flh; B=g_wflH; oh=g_xv; epi=EPI_LN; break;
    case 2:  A=g_xq;  B=g_wfold;          bias=g_bfold;     oh=g_qh1; epi=EPI_HALF; scale=QS; break;
    case 3:  A=g_xk;  B=g_wfold+16384;    bias=g_bfold+128; oh=g_kh1; epi=EPI_HALF; break;
    case 4:  A=g_xv;  B=g_wfold+2*16384;  bias=g_bfold+256; oh=g_vh1; epi=EPI_HALF; break;
    case 5:  A=g_xk;  B=g_wfold+4*16384;  bias=g_bfold+512; oh=g_kh2; epi=EPI_HALF; break;
    case 6:  A=g_xv;  B=g_wfold+5*16384;  bias=g_bfold+640; oh=g_vh2; epi=EPI_HALF; break;
    case 7:  A=nullptr; B=g_wpT; bias=extb; of=g_q1; oh=g_xm; epi=EPI_SKLN0; break;  // aux=x via extaux
    case 8:  A=g_xm;  B=g_wafold;         bias=g_bafold;     oh=g_h;     epi=EPI_GELU; ldC=256; break;
    case 9:  A=g_xm;  B=g_wafold+16384;   bias=g_bafold+128; oh=g_h+128; epi=EPI_GELU; ldC=256; break;
    case 10: A=g_h;   B=g_wmbT; bias=extb; of=g_q1; oh=g_xq1; aux=g_q1; epi=EPI_RESLN; break;
    case 11: A=g_xq1; B=g_wfold+3*16384;  bias=g_bfold+384; oh=g_qh2; epi=EPI_HALF; scale=QS; break;
    case 12: A=g_o2;  B=g_wpT+16384; bias=extb; of=g_q2; oh=g_xm; aux=g_q1; epi=EPI_SKLN1; break;
    case 13: A=g_xm;  B=g_wafold+32768;        bias=g_bafold+256; oh=g_h;     epi=EPI_GELU; ldC=256; break;
    case 14: A=g_xm;  B=g_wafold+32768+16384;  bias=g_bafold+384; oh=g_h+128; epi=EPI_GELU; ldC=256; break;
    default: A=g_h;   B=g_wmbT+32768; bias=extb; aux=g_q2; epi=EPI_FIN; break;
    }
}

// ---------------- unified HMMA GEMM with fused epilogues ---------------------
// C[M][128] = A[M][KT*128] @ B[128][KT*128]^T (+ epilogue). 256 thr, M-tile 128.
template<int KT>
__global__ void __launch_bounds__(256) k_gemm_ep(
        int jobsel, const float* __restrict__ extb,
        const float* __restrict__ extg, const float* __restrict__ extbt,
        const float* __restrict__ extaux, float* __restrict__ extout) {
    int job, tile;
    if (jobsel < 100)       { job = jobsel; tile = blockIdx.x; }
    else if (jobsel == 100) { job = blockIdx.x / 264; tile = blockIdx.x % 264; }
    else if (jobsel == 101) {
        int bx = blockIdx.x;
        if (bx < 384) { job = 2; tile = bx; }
        else { int r = bx - 384; job = 3 + r/264; tile = r % 264; }
    }
    else if (jobsel == 102) { job = 8 + (blockIdx.x >> 6); tile = blockIdx.x & 63; }
    else                    { job = 13 + (blockIdx.x >> 6); tile = blockIdx.x & 63; }

    const __half* A; const __half* Bw; const float* bias;
    __half* oh; float* of; const float* aux; int epi; float scale; int ldC;
    gemm_job(job, extb, A, Bw, bias, oh, of, aux, epi, scale, ldC);
    if (epi == EPI_SKLN0) aux = extaux;

    extern __shared__ __half shh[];
    __half* As = shh;                 // [128][136]
    __half* Bs = shh + 128*136;
    int tid = threadIdx.x;
    int m0 = tile * 128;
    const int KD = KT*128;
    int warp = tid >> 5, lane = tid & 31;
    int wm = (warp & 3) * 32, wn = (warp >> 2) * 64;
    int g = lane >> 2, tg = (lane & 3) * 2;
    float acc[2][8][4];
#pragma unroll
    for (int i = 0; i < 2; i++)
#pragma unroll
        for (int j = 0; j < 8; j++)
#pragma unroll
            for (int r = 0; r < 4; r++) acc[i][j][r] = 0.f;

    for (int kc = 0; kc < KT; kc++) {
        int r = tid >> 4, q = tid & 15;
        if (job == 7) {
            // A-row = mean over 6 cameras of g_otok
            for (int rr = r; rr < 128; rr += 16) {
                int row = m0 + rr;
                int b = row >> 12, p = row & 4095;
                int hh_ = p >> 6, ww = p & 63;
                int l = ((hh_ >> 3) << 3) + (ww >> 3);
                const __half* src = g_otok + ((b*64 + l)*NQ1 + (hh_&7)*8 + (ww&7))*D_ + q*8;
                float s[8];
#pragma unroll
                for (int t = 0; t < 8; t++) s[t] = 0.f;
#pragma unroll
                for (int n = 0; n < 6; n++) {
                    const __half2* pp = reinterpret_cast<const __half2*>(src + n*64*D_);
#pragma unroll
                    for (int t = 0; t < 4; t++) {
                        float2 f = __half22float2(pp[t]);
                        s[t*2] += f.x; s[t*2+1] += f.y;
                    }
                }
                __half2 o[4];
#pragma unroll
                for (int t = 0; t < 4; t++)
                    o[t] = __floats2half2_rn(s[t*2]*(1.f/6.f), s[t*2+1]*(1.f/6.f));
                *reinterpret_cast<int4*>(&As[rr*136 + q*8]) = *reinterpret_cast<int4*>(o);
                *reinterpret_cast<int4*>(&Bs[rr*136 + q*8]) =
                    *reinterpret_cast<const int4*>(&Bw[rr*KD + q*8]);
            }
        } else {
            for (int rr = r; rr < 128; rr += 16) {
                *reinterpret_cast<int4*>(&As[rr*136 + q*8]) =
                    *reinterpret_cast<const int4*>(&A[(m0+rr)*KD + kc*128 + q*8]);
                *reinterpret_cast<int4*>(&Bs[rr*136 + q*8]) =
                    *reinterpret_cast<const int4*>(&Bw[rr*KD + kc*128 + q*8]);
            }
        }
        __syncthreads();
#pragma unroll
        for (int ks = 0; ks < 8; ks++) {
            int k0 = ks*16;
            uint32_t a[2][4];
#pragma unroll
            for (int i = 0; i < 2; i++) {
                int mb = wm + i*16;
                a[i][0] = *reinterpret_cast<const uint32_t*>(&As[(mb+g  )*136 + k0+tg  ]);
                a[i][1] = *reinterpret_cast<const uint32_t*>(&As[(mb+8+g)*136 + k0+tg  ]);
                a[i][2] = *reinterpret_cast<const uint32_t*>(&As[(mb+g  )*136 + k0+8+tg]);
                a[i][3] = *reinterpret_cast<const uint32_t*>(&As[(mb+8+g)*136 + k0+8+tg]);
            }
#pragma unroll
            for (int j = 0; j < 8; j++) {
                uint32_t b0 = *reinterpret_cast<const uint32_t*>(&Bs[(wn+j*8+g)*136 + k0+tg  ]);
                uint32_t b1 = *reinterpret_cast<const uint32_t*>(&Bs[(wn+j*8+g)*136 + k0+8+tg]);
                mma16816(acc[0][j], a[0], b0, b1);
                mma16816(acc[1][j], a[1], b0, b1);
            }
        }
        __syncthreads();
    }

    if (epi <= EPI_GELU) {
#pragma unroll
        for (int i = 0; i < 2; i++)
#pragma unroll
        for (int j = 0; j < 8; j++) {
            int n = wn + j*8 + tg;
            float b0 = bias[n], b1 = bias[n+1];
            int r0 = m0 + wm + i*16 + g, r1 = r0 + 8;
            float v0 = acc[i][j][0]+b0, v1 = acc[i][j][1]+b1;
            float v2 = acc[i][j][2]+b0, v3 = acc[i][j][3]+b1;
            if (epi == EPI_GELU) {
                v0 = geluf(v0); v1 = geluf(v1); v2 = geluf(v2); v3 = geluf(v3);
            } else {
                v0 *= scale; v1 *= scale; v2 *= scale; v3 *= scale;
            }
            *reinterpret_cast<uint32_t*>(&oh[r0*ldC + n]) = packh2(v0, v1);
            *reinterpret_cast<uint32_t*>(&oh[r1*ldC + n]) = packh2(v2, v3);
        }
    } else {
        // LN family: fold bias + aux, optional fp32 store, then LN
#pragma unroll
        for (int i = 0; i < 2; i++)
#pragma unroll
        for (int j = 0; j < 8; j++) {
            int n = wn + j*8 + tg;
            int r0 = m0 + wm + i*16 + g, r1 = r0 + 8;
            if (bias) {
                float b0 = bias[n], b1 = bias[n+1];
                acc[i][j][0] += b0; acc[i][j][1] += b1;
                acc[i][j][2] += b0; acc[i][j][3] += b1;
            }
            if (aux) {
                if (epi == EPI_SKLN0) {
                    int ba = r0 >> 12, pa = r0 & 4095;
                    int bb_ = r1 >> 12, pb = r1 & 4095;
                    acc[i][j][0] += aux[(ba*D_ + n  )*4096 + pa];
                    acc[i][j][1] += aux[(ba*D_ + n+1)*4096 + pa];
                    acc[i][j][2] += aux[(bb_*D_ + n  )*4096 + pb];
                    acc[i][j][3] += aux[(bb_*D_ + n+1)*4096 + pb];
                } else {
                    acc[i][j][0] += aux[r0*D_ + n];
                    acc[i][j][1] += aux[r0*D_ + n+1];
                    acc[i][j][2] += aux[r1*D_ + n];
                    acc[i][j][3] += aux[r1*D_ + n+1];
                }
            }
            if (of) {
                of[r0*D_ + n]   = acc[i][j][0];
                of[r0*D_ + n+1] = acc[i][j][1];
                of[r1*D_ + n]   = acc[i][j][2];
                of[r1*D_ + n+1] = acc[i][j][3];
            }
        }
        float sum[2][2] = {{0,0},{0,0}}, sq[2][2] = {{0,0},{0,0}};
#pragma unroll
        for (int i = 0; i < 2; i++)
#pragma unroll
        for (int j = 0; j < 8; j++) {
            float a0 = acc[i][j][0], a1 = acc[i][j][1];
            float a2 = acc[i][j][2], a3 = acc[i][j][3];
            sum[i][0] += a0 + a1; sq[i][0] += a0*a0 + a1*a1;
            sum[i][1] += a2 + a3; sq[i][1] += a2*a2 + a3*a3;
        }
#pragma unroll
        for (int o = 1; o <= 2; o <<= 1) {
#pragma unroll
            for (int i = 0; i < 2; i++)
#pragma unroll
            for (int rh = 0; rh < 2; rh++) {
                sum[i][rh] += __shfl_xor_sync(0xffffffffu, sum[i][rh], o);
                sq[i][rh]  += __shfl_xor_sync(0xffffffffu, sq[i][rh], o);
            }
        }
        float* sred = reinterpret_cast<float*>(shh);   // [128][4]
        if ((lane & 3) == 0) {
#pragma unroll
            for (int i = 0; i < 2; i++)
#pragma unroll
            for (int rh = 0; rh < 2; rh++) {
                int row = wm + i*16 + rh*8 + g;
                sred[row*4 + (wn >> 6)*2 + 0] = sum[i][rh];
                sred[row*4 + (wn >> 6)*2 + 1] = sq[i][rh];
            }
        }
        __syncthreads();
#pragma unroll
        for (int i = 0; i < 2; i++)
#pragma unroll
        for (int rh = 0; rh < 2; rh++) {
            int row = wm + i*16 + rh*8 + g;
            float s = sred[row*4+0] + sred[row*4+2];
            float qq = sred[row*4+1] + sred[row*4+3];
            float mean = s*(1.0f/128.0f);
            float var = fmaxf(qq*(1.0f/128.0f) - mean*mean, 0.f);
            float rstd = rsqrtf(var + 1e-5f);
            if (epi == EPI_FIN) {
                int grow = m0 + row;
                int b = grow >> 12, p = grow & 4095;
#pragma unroll
                for (int j = 0; j < 8; j++) {
                    int n = wn + j*8 + tg;
                    extout[(b*D_ + n  )*4096 + p] =
                        (acc[i][j][rh*2+0]-mean)*rstd*extg[n]   + extbt[n];
                    extout[(b*D_ + n+1)*4096 + p] =
                        (acc[i][j][rh*2+1]-mean)*rstd*extg[n+1] + extbt[n+1];
                }
            } else {
#pragma unroll
                for (int j = 0; j < 8; j++) {
                    int n = wn + j*8 + tg;
                    float v0 = (acc[i][j][rh*2+0]-mean)*rstd;
                    float v1 = (acc[i][j][rh*2+1]-mean)*rstd;
                    *reinterpret_cast<uint32_t*>(&oh[(m0+row)*D_ + n]) = packh2(v0, v1);
                }
            }
        }
    }
}

// ---------------- tensor-core flash attention (fp16 in / fp16 out) -----------
template<int MT, int NW>
__global__ void __launch_bounds__(NW*32) k_attn_mma(int stage) {
    const int NQ = MT*16*NW;
    extern __shared__ __half sha[];
    __half* Qs = sha;                  // [NQ][40]
    __half* Ks = Qs + NQ*40;           // [264][40]
    __half* Vt = Ks + 264*40;          // [32][274]
    int bl = blockIdx.x, hh = blockIdx.y, tid = threadIdx.x;
    int b = bl >> 6, l = bl & 63;
    const __half* qsrc; const __half* ksrc; const __half* vsrc;
    if (stage == 0) { qsrc = g_qh1; ksrc = g_kh1; vsrc = g_vh1; }
    else            { qsrc = g_qh2; ksrc = g_kh2; vsrc = g_vh2; }
    for (int idx = tid; idx < NQ*16; idx += NW*32) {
        int row = idx >> 4, c2 = idx & 15;
        int pix;
        if (stage == 0) {
            int n = row >> 6, ij = row & 63;
            pix = (b*N_+n)*4096 + ((l>>3)*8 + (ij>>3))*64 + (l&7)*8 + (ij&7);
        } else {
            pix = b*4096 + ((l>>3)*8 + (row>>3))*64 + (l&7)*8 + (row&7);
        }
        *reinterpret_cast<uint32_t*>(&Qs[row*40 + 2*c2]) =
            *reinterpret_cast<const uint32_t*>(&qsrc[pix*D_ + hh*32 + 2*c2]);
    }
    for (int idx = tid; idx < NKV*16; idx += NW*32) {
        int kv = idx >> 4, c2 = idx & 15;
        int n = kv/44, f = kv%44, f1 = f/11, f2 = f%11;
        int h, w;
        if (stage == 0) { h = (l>>3)*4 + f1; w = (l&7)*11 + f2; }
        else            { h = f1*8 + (l>>3); w = f2*8 + (l&7); }
        int pix = (b*N_+n)*PIX + h*FW_ + w;
        *reinterpret_cast<uint32_t*>(&Ks[kv*40 + 2*c2]) =
            *reinterpret_cast<const uint32_t*>(&ksrc[pix*D_ + hh*32 + 2*c2]);
    }
    for (int idx = tid; idx < NKV*32; idx += NW*32) {
        int kv = idx >> 5, ch = idx & 31;
        int n = kv/44, f = kv%44, f1 = f/11, f2 = f%11;
        int h, w;
        if (stage == 0) { h = (l>>3)*4 + f1; w = (l&7)*11 + f2; }
        else            { h = f1*8 + (l>>3); w = f2*8 + (l&7); }
        int pix = (b*N_+n)*PIX + h*FW_ + w;
        Vt[ch*274 + kv] = vsrc[pix*D_ + hh*32 + ch];
    }
    for (int idx = tid; idx < 32*10; idx += NW*32) {
        int ch = idx / 10, c = idx % 10;
        Vt[ch*274 + 264 + c] = __half(0.f);
    }
    __syncthreads();

    int warp = tid >> 5, lane = tid & 31;
    int g = lane >> 2, t4 = lane & 3;
    int row0 = warp * MT * 16;

    uint32_t af[MT][2][4];
#pragma unroll
    for (int mt = 0; mt < MT; mt++)
#pragma unroll
        for (int ks = 0; ks < 2; ks++) {
            int r = row0 + mt*16, k0 = ks*16;
            af[mt][ks][0] = *reinterpret_cast<const uint32_t*>(&Qs[(r+g  )*40 + k0 + 2*t4    ]);
            af[mt][ks][1] = *reinterpret_cast<const uint32_t*>(&Qs[(r+8+g)*40 + k0 + 2*t4    ]);
            af[mt][ks][2] = *reinterpret_cast<const uint32_t*>(&Qs[(r+g  )*40 + k0 + 8 + 2*t4]);
            af[mt][ks][3] = *reinterpret_cast<const uint32_t*>(&Qs[(r+8+g)*40 + k0 + 8 + 2*t4]);
        }

    float m[MT][2], lsum[MT][2], O[MT][4][4];
#pragma unroll
    for (int mt = 0; mt < MT; mt++) {
        m[mt][0] = -1e30f; m[mt][1] = -1e30f;
        lsum[mt][0] = 0.f; lsum[mt][1] = 0.f;
#pragma unroll
        for (int j = 0; j < 4; j++)
#pragma unroll
            for (int r = 0; r < 4; r++) O[mt][j][r] = 0.f;
    }

    for (int c = 0; c < 17; c++) {
        int kv0 = c*16;
        int nt = (c == 16) ? 1 : 2;
        uint32_t bf[2][2][2];
#pragma unroll
        for (int n = 0; n < 2; n++) {
            if (n < nt) {
#pragma unroll
                for (int ks = 0; ks < 2; ks++) {
                    bf[n][ks][0] = *reinterpret_cast<const uint32_t*>(&Ks[(kv0+n*8+g)*40 + ks*16 + 2*t4    ]);
                    bf[n][ks][1] = *reinterpret_cast<const uint32_t*>(&Ks[(kv0+n*8+g)*40 + ks*16 + 8 + 2*t4]);
                }
            }
        }
        float S[MT][2][4];
#pragma unroll
        for (int mt = 0; mt < MT; mt++)
#pragma unroll
            for (int n = 0; n < 2; n++)
#pragma unroll
                for (int r = 0; r < 4; r++) S[mt][n][r] = 0.f;
#pragma unroll
        for (int mt = 0; mt < MT; mt++)
#pragma unroll
            for (int n = 0; n < 2; n++) {
                if (n < nt) {
                    mma16816(S[mt][n], af[mt][0], bf[n][0][0], bf[n][0][1]);
                    mma16816(S[mt][n], af[mt][1], bf[n][1][0], bf[n][1][1]);
                }
            }
#pragma unroll
        for (int mt = 0; mt < MT; mt++) {
            float mx0 = fmaxf(S[mt][0][0], S[mt][0][1]);
            float mx8 = fmaxf(S[mt][0][2], S[mt][0][3]);
            if (nt == 2) {
                mx0 = fmaxf(mx0, fmaxf(S[mt][1][0], S[mt][1][1]));
                mx8 = fmaxf(mx8, fmaxf(S[mt][1][2], S[mt][1][3]));
            }
            mx0 = fmaxf(mx0, __shfl_xor_sync(0xffffffffu, mx0, 1));
            mx0 = fmaxf(mx0, __shfl_xor_sync(0xffffffffu, mx0, 2));
            mx8 = fmaxf(mx8, __shfl_xor_sync(0xffffffffu, mx8, 1));
            mx8 = fmaxf(mx8, __shfl_xor_sync(0xffffffffu, mx8, 2));
            float mn0 = fmaxf(m[mt][0], mx0), mn8 = fmaxf(m[mt][1], mx8);
            float cr0 = __expf(m[mt][0] - mn0), cr8 = __expf(m[mt][1] - mn8);
            m[mt][0] = mn0; m[mt][1] = mn8;
            uint32_t pa[4];
            float p00 = __expf(S[mt][0][0] - mn0), p01 = __expf(S[mt][0][1] - mn0);
            float p02 = __expf(S[mt][0][2] - mn8), p03 = __expf(S[mt][0][3] - mn8);
            float rs0 = p00 + p01, rs8 = p02 + p03;
            pa[0] = packh2(p00, p01);
            pa[1] = packh2(p02, p03);
            if (nt == 2) {
                float p10 = __expf(S[mt][1][0] - mn0), p11 = __expf(S[mt][1][1] - mn0);
                float p12 = __expf(S[mt][1][2] - mn8), p13 = __expf(S[mt][1][3] - mn8);
                rs0 += p10 + p11; rs8 += p12 + p13;
                pa[2] = packh2(p10, p11);
                pa[3] = packh2(p12, p13);
            } else { pa[2] = 0u; pa[3] = 0u; }
            rs0 += __shfl_xor_sync(0xffffffffu, rs0, 1);
            rs0 += __shfl_xor_sync(0xffffffffu, rs0, 2);
            rs8 += __shfl_xor_sync(0xffffffffu, rs8, 1);
            rs8 += __shfl_xor_sync(0xffffffffu, rs8, 2);
            lsum[mt][0] = lsum[mt][0]*cr0 + rs0;
            lsum[mt][1] = lsum[mt][1]*cr8 + rs8;
#pragma unroll
            for (int j = 0; j < 4; j++) {
                O[mt][j][0] *= cr0; O[mt][j][1] *= cr0;
                O[mt][j][2] *= cr8; O[mt][j][3] *= cr8;
                uint32_t vb0 = *reinterpret_cast<const uint32_t*>(&Vt[(j*8+g)*274 + kv0 + 2*t4    ]);
                uint32_t vb1 = *reinterpret_cast<const uint32_t*>(&Vt[(j*8+g)*274 + kv0 + 8 + 2*t4]);
                mma16816(O[mt][j], pa, vb0, vb1);
            }
        }
    }
#pragma unroll
    for (int mt = 0; mt < MT; mt++) {
        float i0 = 1.0f / lsum[mt][0], i8 = 1.0f / lsum[mt][1];
        int r0 = row0 + mt*16 + g;
        int r1 = r0 + 8;
        int out0, out1;
        if (stage == 0) {
            out0 = bl*NQ + r0;
            out1 = bl*NQ + r1;
        } else {
            out0 = b*4096 + ((l>>3)*8 + (r0>>3))*64 + (l&7)*8 + (r0&7);
            out1 = b*4096 + ((l>>3)*8 + (r1>>3))*64 + (l&7)*8 + (r1&7);
        }
        __half* Od = (stage == 0) ? g_otok : g_o2;
#pragma unroll
        for (int j = 0; j < 4; j++) {
            int chn = hh*32 + j*8 + 2*t4;
            *reinterpret_cast<uint32_t*>(&Od[out0*D_ + chn]) = packh2(O[mt][j][0]*i0, O[mt][j][1]*i0);
            *reinterpret_cast<uint32_t*>(&Od[out1*D_ + chn]) = packh2(O[mt][j][2]*i8, O[mt][j][3]*i8);
        }
    }
}

// ---------------------------------------------------------------------------
extern "C" void kernel_launch(void* const* d_in, const int* in_sizes, int n_in,
                              void* d_out, int out_size) {
    (void)in_sizes; (void)n_in; (void)out_size;
    const float* x        = (const float*)d_in[1];
    const float* grid     = (const float*)d_in[2];
    const float* feature  = (const float*)d_in[3];
    const float* I_inv    = (const float*)d_in[4];
    const float* E_inv    = (const float*)d_in[5];
    const float* bn_fl_g  = (const float*)d_in[6];
    const float* bn_fl_b  = (const float*)d_in[7];
    const float* W_fl     = (const float*)d_in[8];
    const float* bn_fp_g  = (const float*)d_in[9];
    const float* bn_fp_b  = (const float*)d_in[10];
    const float* W_fp     = (const float*)d_in[11];
    const float* W_bev    = (const float*)d_in[12];
    const float* b_bev    = (const float*)d_in[13];
    const float* W_img    = (const float*)d_in[14];
    const float* W_cam    = (const float*)d_in[15];
    const float* aln_g    = (const float*)d_in[16];
    const float* aln_b    = (const float*)d_in[17];
    const float* aWqkv    = (const float*)d_in[18];
    const float* abqkv    = (const float*)d_in[19];
    const float* aWp      = (const float*)d_in[20];
    const float* abp      = (const float*)d_in[21];
    const float* pn_g     = (const float*)d_in[22];
    const float* pn_b     = (const float*)d_in[23];
    const float* Wma      = (const float*)d_in[24];
    const float* bma      = (const float*)d_in[25];
    const float* Wmb      = (const float*)d_in[26];
    const float* bmb      = (const float*)d_in[27];
    const float* post_g   = (const float*)d_in[28];
    const float* post_b   = (const float*)d_in[29];
    float* out = (float*)d_out;

    const int GSM = 2*128*136*2;             // 69632
    const int PSM = 2*128*33*4 + 32*128*4;   // 50176
    const int A1SM = (384*40 + 264*40 + 32*274) * 2;
    const int A2SM = (64*40 + 264*40 + 32*274) * 2;
    cudaFuncSetAttribute(k_prep, cudaFuncAttributeMaxDynamicSharedMemorySize, PSM);
    cudaFuncSetAttribute(k_gemm_ep<1>, cudaFuncAttributeMaxDynamicSharedMemorySize, GSM);
    cudaFuncSetAttribute(k_gemm_ep<2>, cudaFuncAttributeMaxDynamicSharedMemorySize, GSM);
    cudaFuncSetAttribute(k_attn_mma<3,8>, cudaFuncAttributeMaxDynamicSharedMemorySize, A1SM);
    cudaFuncSetAttribute(k_attn_mma<1,4>, cudaFuncAttributeMaxDynamicSharedMemorySize, A2SM);

    // prep (weights + activations)
    k_wprep<<<304, 256>>>(aln_g, aln_b, aWqkv, abqkv, pn_g, pn_b, Wma, bma,
                          aWp, Wmb, W_fp, W_fl);
    k_prep<<<B_*N_*88, 128, PSM>>>(feature, I_inv, E_inv, W_img, W_cam,
                                   bn_fp_g, bn_fp_b, bn_fl_g, bn_fl_b);
    k_query<<<NQP/8, 256>>>(grid, x, W_bev, b_bev, E_inv, W_cam);

    // conv GEMMs (jobs 0,1) then all 5 QKV projections (jobs 2..6)
    k_gemm_ep<1><<<528, 256, GSM>>>(100, nullptr, nullptr, nullptr, nullptr, nullptr);
    k_gemm_ep<1><<<1440, 256, GSM>>>(101, nullptr, nullptr, nullptr, nullptr, nullptr);

    // stage 1
    k_attn_mma<3,8><<<dim3(B_*64, 4), 256, A1SM>>>(0);
    k_gemm_ep<1><<<64, 256, GSM>>>(7, abp, nullptr, nullptr, x, nullptr);       // mean+proj+skip+LN
    k_gemm_ep<1><<<128, 256, GSM>>>(102, nullptr, nullptr, nullptr, nullptr, nullptr);  // gelu a,b
    k_gemm_ep<2><<<64, 256, GSM>>>(10, bmb, nullptr, nullptr, nullptr, nullptr);        // res+LN -> xq1

    // stage 2
    k_gemm_ep<1><<<64, 256, GSM>>>(11, nullptr, nullptr, nullptr, nullptr, nullptr);    // Q2
    k_attn_mma<1,4><<<dim3(B_*64, 4), 128, A2SM>>>(1);
    k_gemm_ep<1><<<64, 256, GSM>>>(12, abp + 128, nullptr, nullptr, nullptr, nullptr);  // proj+skip+LN
    k_gemm_ep<1><<<128, 256, GSM>>>(103, nullptr, nullptr, nullptr, nullptr, nullptr);  // gelu a,b
    k_gemm_ep<2><<<64, 256, GSM>>>(15, bmb + 128, post_g, post_b, nullptr, out);        // res+finalLN
}

// round 12
// speedup vs baseline: 7.1511x; 1.1261x over previous
#include <cuda_runtime.h>
#include <cuda_fp16.h>
#include <math.h>
#include <stdint.h>

#define B_   2
#define N_   6
#define FH_  32
#define FW_  88
#define PIX  (FH_*FW_)     // 2816
#define D_   128
#define NKV  264
#define NQ1  384
#define NPX  (B_*N_*PIX)   // 33792
#define NQP  (B_*N_*4096)  // 49152
#define NTK  (B_*4096)     // 8192

// epilogue modes
#define EPI_HALF  0
#define EPI_GELU  1
#define EPI_LN    2
#define EPI_SKLN0 3
#define EPI_SKLN1 4
#define EPI_RESLN 5
#define EPI_FIN   6

// ---------------- scratch globals (no runtime allocation) -------------------
__device__ __align__(16) __half g_fph[NPX*D_];
__device__ __align__(16) __half g_flh[NPX*D_];
__device__ __align__(16) __half g_kimgh[NPX*D_];
__device__ __align__(16) __half g_xq [NQP*D_];
__device__ __align__(16) __half g_xk [NPX*D_];
__device__ __align__(16) __half g_xv [NPX*D_];
__device__ __align__(16) __half g_xq1[NTK*D_];
__device__ __align__(16) __half g_xm [NTK*D_];
__device__ __align__(16) __half g_wfold[6*D_*D_];
__device__ float  g_bfold[6*D_];
__device__ __align__(16) __half g_wafold[2*256*D_];
__device__ float  g_bafold[2*256];
__device__ __align__(16) __half g_wmbT[2*D_*256];
__device__ __align__(16) __half g_wpT[2*D_*D_];
__device__ __align__(16) __half g_wfpH[D_*D_];
__device__ __align__(16) __half g_wflH[D_*D_];
__device__ __align__(16) __half g_qh1[NQP*D_];
__device__ __align__(16) __half g_kh1[NPX*D_];
__device__ __align__(16) __half g_vh1[NPX*D_];
__device__ __align__(16) __half g_qh2[NTK*D_];
__device__ __align__(16) __half g_kh2[NPX*D_];
__device__ __align__(16) __half g_vh2[NPX*D_];
__device__ __align__(16) __half g_otok[B_*64*NQ1*D_];
__device__ __align__(16) __half g_o2[NTK*D_];
__device__ __align__(16) __half g_h[NTK*256];
__device__ __align__(16) float  g_q1[NTK*D_];
__device__ __align__(16) float  g_q2[NTK*D_];

__device__ __forceinline__ void warpRed2(float& s, float& q) {
#pragma unroll
    for (int o = 16; o; o >>= 1) {
        s += __shfl_xor_sync(0xffffffffu, s, o);
        q += __shfl_xor_sync(0xffffffffu, q, o);
    }
}

__device__ __forceinline__ void st_half4(__half* dst, float a, float b, float c, float d) {
    __half2* p = reinterpret_cast<__half2*>(dst);
    p[0] = __floats2half2_rn(a, b);
    p[1] = __floats2half2_rn(c, d);
}

__device__ __forceinline__ uint32_t packh2(float a, float b) {
    __half2 h = __floats2half2_rn(a, b);
    return *reinterpret_cast<uint32_t*>(&h);
}

__device__ __forceinline__ float geluf(float h) {
    return h * 0.5f * (1.0f + erff(h * 0.70710678118654752f));
}

__device__ __forceinline__ void mma16816(float* c, const uint32_t* a,
                                         uint32_t b0, uint32_t b1) {
    asm volatile(
        "mma.sync.aligned.m16n8k16.row.col.f32.f16.f16.f32 "
        "{%0,%1,%2,%3}, {%4,%5,%6,%7}, {%8,%9}, {%0,%1,%2,%3};\n"
        : "+f"(c[0]), "+f"(c[1]), "+f"(c[2]), "+f"(c[3])
        : "r"(a[0]), "r"(a[1]), "r"(a[2]), "r"(a[3]), "r"(b0), "r"(b1));
}

__device__ __forceinline__ void cpa16(void* smem, const void* gmem) {
    uint32_t sa = (uint32_t)__cvta_generic_to_shared(smem);
    asm volatile("cp.async.cg.shared.global [%0], [%1], 16;\n" :: "r"(sa), "l"(gmem));
}

// ---------------- merged weight prep (one launch, block-range dispatch) ------
__global__ void __launch_bounds__(256) k_wprep(
        const float* __restrict__ aln_g, const float* __restrict__ aln_b,
        const float* __restrict__ aWqkv, const float* __restrict__ abqkv,
        const float* __restrict__ pn_g, const float* __restrict__ pn_b,
        const float* __restrict__ Wma, const float* __restrict__ bma,
        const float* __restrict__ aWp, const float* __restrict__ Wmb,
        const float* __restrict__ W_fp, const float* __restrict__ W_fl) {
    __shared__ float sm[16][129];
    __shared__ float bred[16][17];
    int blk = blockIdx.x, tid = threadIdx.x;
    if (blk < 48) {
        int idx = blk >> 3, o0 = (blk & 7) * 16;
        const float* W = aWqkv + idx*16384;
        const float* g = aln_g + idx*128;
        const float* bb = aln_b + idx*128;
        for (int k = tid; k < 2048; k += 256) {
            int c = k >> 4, o = k & 15;
            sm[o][c] = g[c] * W[c*128 + o0 + o];
        }
        {
            int o = tid & 15, cg = tid >> 4;
            float part = 0.f;
#pragma unroll
            for (int cc = 0; cc < 8; cc++) {
                int c = cg*8 + cc;
                part += bb[c] * W[c*128 + o0 + o];
            }
            bred[o][cg] = part;
        }
        __syncthreads();
        for (int k = tid; k < 1024; k += 256) {
            int o = k >> 6, c2 = (k & 63)*2;
            *reinterpret_cast<__half2*>(&g_wfold[idx*16384 + (o0+o)*128 + c2]) =
                __floats2half2_rn(sm[o][c2], sm[o][c2+1]);
        }
        if (tid < 16) {
            float a = 0.f;
#pragma unroll
            for (int cg = 0; cg < 16; cg++) a += bred[tid][cg];
            g_bfold[idx*128 + o0 + tid] = a + abqkv[idx*128 + o0 + tid];
        }
    } else if (blk < 80) {
        int t = blk - 48;
        int s = t >> 4, o0 = (t & 15) * 16;
        const float* W = Wma + s*128*256;
        const float* g = pn_g + s*128;
        const float* bb = pn_b + s*128;
        for (int k = tid; k < 2048; k += 256) {
            int c = k >> 4, o = k & 15;
            sm[o][c] = g[c] * W[c*256 + o0 + o];
        }
        {
            int o = tid & 15, cg = tid >> 4;
            float part = 0.f;
#pragma unroll
            for (int cc = 0; cc < 8; cc++) {
                int c = cg*8 + cc;
                part += bb[c] * W[c*256 + o0 + o];
            }
            bred[o][cg] = part;
        }
        __syncthreads();
        for (int k = tid; k < 1024; k += 256) {
            int o = k >> 6, c2 = (k & 63)*2;
            *reinterpret_cast<__half2*>(&g_wafold[s*32768 + (o0+o)*128 + c2]) =
                __floats2half2_rn(sm[o][c2], sm[o][c2+1]);
        }
        if (tid < 16) {
            float a = 0.f;
#pragma unroll
            for (int cg = 0; cg < 16; cg++) a += bred[tid][cg];
            g_bafold[s*256 + o0 + tid] = a + bma[s*256 + o0 + tid];
        }
    } else if (blk < 176) {
        int t = blk - 80;
        const float* src; __half* dst; int R, C, bx, by;
        if (t < 16)      { src = aWp;          dst = g_wpT;          R=128; C=128; bx=t&3;      by=t>>2; }
        else if (t < 32) { src = aWp+16384;    dst = g_wpT+16384;    R=128; C=128; bx=(t-16)&3; by=(t-16)>>2; }
        else if (t < 64) { src = Wmb;          dst = g_wmbT;         R=256; C=128; bx=(t-32)&3; by=(t-32)>>2; }
        else             { src = Wmb+32768;    dst = g_wmbT+32768;   R=256; C=128; bx=(t-64)&3; by=(t-64)>>2; }
        float (*tb)[33] = reinterpret_cast<float(*)[33]>(&sm[0][0]);
        int c0 = bx*32, r0 = by*32;
        int cx = tid & 31, ry = tid >> 5;
        for (int rr = ry; rr < 32; rr += 8)
            tb[rr][cx] = src[(r0+rr)*C + c0 + cx];
        __syncthreads();
        for (int cc = ry; cc < 32; cc += 8)
            dst[(c0+cc)*R + r0 + cx] = __float2half(tb[cx][cc]);
    } else {
        int t = blk - 176;
        const float* src = (t < 64) ? W_fp : W_fl;
        __half* dst = (t < 64) ? g_wfpH : g_wflH;
        int i = (t & 63)*256 + tid;
        dst[i] = __float2half(src[i]);
    }
}

// ---------------- prep: BN-ReLU fp16 feats + image embedding -----------------
__global__ void __launch_bounds__(128) k_prep(
        const float* __restrict__ feat,
        const float* __restrict__ I_inv, const float* __restrict__ E_inv,
        const float* __restrict__ W_img, const float* __restrict__ W_cam,
        const float* __restrict__ fp_g, const float* __restrict__ fp_b,
        const float* __restrict__ fl_g, const float* __restrict__ fl_b) {
    extern __shared__ float sh[];
    float* sfp  = sh;                 // [128][33]
    float* sfl  = sh + 128*33;
    float* kimg = sh + 2*128*33;      // [32][128]
    int blk = blockIdx.x, tid = threadIdx.x;
    int bn = blk / 88, p0 = (blk % 88) * 32;
    int warp = tid >> 5, lane = tid & 31;

    const float invs = rsqrtf(1.0f + 1e-5f);
    for (int k = tid; k < 4096; k += 128) {
        int c = k >> 5, pp = k & 31;
        float f = feat[(bn*D_ + c)*PIX + p0 + pp];
        sfp[c*33+pp] = fmaxf(f * invs * fp_g[c] + fp_b[c], 0.f);
        sfl[c*33+pp] = fmaxf(f * invs * fl_g[c] + fl_b[c], 0.f);
    }
    float e3[4];
#pragma unroll
    for (int i = 0; i < 4; i++) e3[i] = E_inv[bn*16 + i*4 + 3];
    for (int it = 0; it < 8; it++) {
        int tt = it*4 + warp;
        int p = p0 + tt, fh = p / FW_, fw = p % FW_;
        float px = (float)fw * (480.0f / 87.0f);
        float py = (float)fh * (224.0f / 31.0f);
        float cam[4];
#pragma unroll
        for (int i = 0; i < 3; i++)
            cam[i] = I_inv[bn*9+i*3+0]*px + I_inv[bn*9+i*3+1]*py + I_inv[bn*9+i*3+2];
        cam[3] = 1.0f;
        float dd[4];
#pragma unroll
        for (int i = 0; i < 4; i++)
            dd[i] = E_inv[bn*16+i*4+0]*cam[0] + E_inv[bn*16+i*4+1]*cam[1]
                  + E_inv[bn*16+i*4+2]*cam[2] + E_inv[bn*16+i*4+3]*cam[3];
        int c0 = lane*4;
        float t[4]; float ssum = 0.f, dum = 0.f;
#pragma unroll
        for (int i = 0; i < 4; i++) {
            int c = c0+i;
            float de = W_img[c*4+0]*dd[0] + W_img[c*4+1]*dd[1]
                     + W_img[c*4+2]*dd[2] + W_img[c*4+3]*dd[3];
            float ce = W_cam[c*4+0]*e3[0] + W_cam[c*4+1]*e3[1]
                     + W_cam[c*4+2]*e3[2] + W_cam[c*4+3]*e3[3];
            t[i] = de - ce;
            ssum += t[i]*t[i];
        }
        warpRed2(ssum, dum);
        float inv = 1.0f / fmaxf(sqrtf(ssum), 1e-12f);
#pragma unroll
        for (int i = 0; i < 4; i++) kimg[tt*128 + c0 + i] = t[i]*inv;
    }
    __syncthreads();
    for (int pp = 0; pp < 32; pp++) {
        int row = bn*PIX + p0 + pp;
        g_fph[row*D_ + tid] = __float2half(sfp[tid*33 + pp]);
        g_flh[row*D_ + tid] = __float2half(sfl[tid*33 + pp]);
        g_kimgh[row*D_ + tid] = __float2half(kimg[pp*128 + tid]);
    }
}

// ---------------- query -> LN'd fp16 xhat, warp per pixel --------------------
__global__ void __launch_bounds__(256) k_query(
        const float* __restrict__ grid, const float* __restrict__ x,
        const float* __restrict__ W_bev, const float* __restrict__ b_bev,
        const float* __restrict__ E_inv, const float* __restrict__ W_cam) {
    int tid = threadIdx.x, warp = tid >> 5, lane = tid & 31;
    int u = blockIdx.x*8 + warp;
    int bn = u >> 12, p = u & 4095;
    int b = bn / N_;
    int c0 = lane*4;
    float e3[4];
#pragma unroll
    for (int i = 0; i < 4; i++) e3[i] = E_inv[bn*16 + i*4 + 3];
    float gx = grid[p], gy = grid[4096 + p];
    float t[4]; float ss = 0.f, dum = 0.f;
#pragma unroll
    for (int i = 0; i < 4; i++) {
        int c = c0 + i;
        float we = W_bev[c*2+0]*gx + W_bev[c*2+1]*gy + b_bev[c];
        float ce = W_cam[c*4+0]*e3[0] + W_cam[c*4+1]*e3[1]
                 + W_cam[c*4+2]*e3[2] + W_cam[c*4+3]*e3[3];
        t[i] = we - ce;
        ss += t[i]*t[i];
    }
    warpRed2(ss, dum);
    float inv = 1.0f / fmaxf(sqrtf(ss), 1e-12f);
    float q[4]; float s = 0.f, q2 = 0.f;
#pragma unroll
    for (int i = 0; i < 4; i++) {
        q[i] = t[i]*inv + x[(b*D_ + c0 + i)*4096 + p];
        s += q[i]; q2 += q[i]*q[i];
    }
    warpRed2(s, q2);
    float mean = s*(1.0f/128.0f);
    float var = fmaxf(q2*(1.0f/128.0f) - mean*mean, 0.f);
    float rstd = rsqrtf(var + 1e-5f);
    st_half4(&g_xq[u*D_ + c0],
             (q[0]-mean)*rstd, (q[1]-mean)*rstd, (q[2]-mean)*rstd, (q[3]-mean)*rstd);
}

// ---------------- device-side job table for the unified GEMM -----------------
__device__ __forceinline__ void gemm_job(
        int job, const float* extb,
        const __half*& A, const __half*& B, const float*& bias,
        __half*& oh, float*& of, const float*& aux, const __half*& auxh,
        int& epi, float& scale, int& ldC) {
    const float QS = 0.17677669529663687f;
    scale = 1.f; ldC = 128; aux = nullptr; auxh = nullptr;
    bias = nullptr; oh = nullptr; of = nullptr;
    switch (job) {
    case 0:  A=g_fph; B=g_wfpH; oh=g_xk; auxh=g_kimgh; epi=EPI_LN; break;
    case 1:  A=g_flh; B=g_wflH; oh=g_xv; epi=EPI_LN; break;
    case 2:  A=g_xq;  B=g_wfold;          bias=g_bfold;     oh=g_qh1; epi=EPI_HALF; scale=QS; break;
    case 3:  A=g_xk;  B=g_wfold+16384;    bias=g_bfold+128; oh=g_kh1; epi=EPI_HALF; break;
    case 4:  A=g_xv;  B=g_wfold+2*16384;  bias=g_bfold+256; oh=g_vh1; epi=EPI_HALF; break;
    case 5:  A=g_xk;  B=g_wfold+4*16384;  bias=g_bfold+512; oh=g_kh2; epi=EPI_HALF; break;
    case 6:  A=g_xv;  B=g_wfold+5*16384;  bias=g_bfold+640; oh=g_vh2; epi=EPI_HALF; break;
    case 7:  A=nullptr; B=g_wpT; bias=extb; of=g_q1; oh=g_xm; epi=EPI_SKLN0; break;
    case 8:  A=g_xm;  B=g_wafold;         bias=g_bafold;     oh=g_h;     epi=EPI_GELU; ldC=256; break;
    case 9:  A=g_xm;  B=g_wafold+16384;   bias=g_bafold+128; oh=g_h+128; epi=EPI_GELU; ldC=256; break;
    case 10: A=g_h;   B=g_wmbT; bias=extb; of=g_q1; oh=g_xq1; aux=g_q1; epi=EPI_RESLN; break;
    case 11: A=g_xq1; B=g_wfold+3*16384;  bias=g_bfold+384; oh=g_qh2; epi=EPI_HALF; scale=QS; break;
    case 12: A=g_o2;  B=g_wpT+16384; bias=extb; of=g_q2; oh=g_xm; aux=g_q1; epi=EPI_SKLN1; break;
    case 13: A=g_xm;  B=g_wafold+32768;        bias=g_bafold+256; oh=g_h;     epi=EPI_GELU; ldC=256; break;
    case 14: A=g_xm;  B=g_wafold+32768+16384;  bias=g_bafold+384; oh=g_h+128; epi=EPI_GELU; ldC=256; break;
    default: A=g_h;   B=g_wmbT+32768; bias=extb; aux=g_q2; epi=EPI_FIN; break;
    }
}

// ---------------- unified HMMA GEMM with fused epilogues ---------------------
// C[64][128] per block = A[64][KT*128] @ B[128][KT*128]^T (+ epilogue).
// 256 thr, 8 warps as 2(m) x 4(n); warp tile 32x32.
template<int KT>
__global__ void __launch_bounds__(256, 3) k_gemm_ep(
        int jobsel, const float* __restrict__ extb,
        const float* __restrict__ extg, const float* __restrict__ extbt,
        const float* __restrict__ extaux, float* __restrict__ extout) {
    int job, tile;
    if (jobsel < 100)       { job = jobsel; tile = blockIdx.x; }
    else if (jobsel == 100) { job = blockIdx.x / 528; tile = blockIdx.x % 528; }
    else if (jobsel == 101) {
        int bx = blockIdx.x;
        if (bx < 768) { job = 2; tile = bx; }
        else { int r = bx - 768; job = 3 + r/528; tile = r % 528; }
    }
    else if (jobsel == 102) { job = 8 + (blockIdx.x >> 7); tile = blockIdx.x & 127; }
    else                    { job = 13 + (blockIdx.x >> 7); tile = blockIdx.x & 127; }

    const __half* A; const __half* Bw; const float* bias;
    __half* oh; float* of; const float* aux; const __half* auxh;
    int epi; float scale; int ldC;
    gemm_job(job, extb, A, Bw, bias, oh, of, aux, auxh, epi, scale, ldC);
    if (epi == EPI_SKLN0) aux = extaux;

    extern __shared__ __half shh[];
    __half* As = shh;                 // [64][136]
    __half* Bs = shh + 64*136;        // [128][136]
    int tid = threadIdx.x;
    int m0 = tile * 64;
    const int KD = KT*128;
    int warp = tid >> 5, lane = tid & 31;
    int wm = (warp & 1) * 32, wn = (warp >> 1) * 32;
    int g = lane >> 2, tg = (lane & 3) * 2;
    float acc[2][4][4];
#pragma unroll
    for (int i = 0; i < 2; i++)
#pragma unroll
        for (int j = 0; j < 4; j++)
#pragma unroll
            for (int r = 0; r < 4; r++) acc[i][j][r] = 0.f;

    for (int kc = 0; kc < KT; kc++) {
        int r = tid >> 4, q = tid & 15;
        if (job == 7) {
            // A-row = mean over 6 cameras of g_otok (computed, not cp.async)
            for (int rr = r; rr < 64; rr += 16) {
                int row = m0 + rr;
                int b = row >> 12, p = row & 4095;
                int hh_ = p >> 6, ww = p & 63;
                int l = ((hh_ >> 3) << 3) + (ww >> 3);
                const __half* src = g_otok + ((b*64 + l)*NQ1 + (hh_&7)*8 + (ww&7))*D_ + q*8;
                float s[8];
#pragma unroll
                for (int t = 0; t < 8; t++) s[t] = 0.f;
#pragma unroll
                for (int n = 0; n < 6; n++) {
                    const __half2* pp = reinterpret_cast<const __half2*>(src + n*64*D_);
#pragma unroll
                    for (int t = 0; t < 4; t++) {
                        float2 f = __half22float2(pp[t]);
                        s[t*2] += f.x; s[t*2+1] += f.y;
                    }
                }
                __half2 o[4];
#pragma unroll
                for (int t = 0; t < 4; t++)
                    o[t] = __floats2half2_rn(s[t*2]*(1.f/6.f), s[t*2+1]*(1.f/6.f));
                *reinterpret_cast<int4*>(&As[rr*136 + q*8]) = *reinterpret_cast<int4*>(o);
            }
#pragma unroll
            for (int rr = r; rr < 128; rr += 16)
                cpa16(&Bs[rr*136 + q*8], &Bw[rr*KD + q*8]);
        } else {
#pragma unroll
            for (int rr = r; rr < 64; rr += 16)
                cpa16(&As[rr*136 + q*8], &A[(m0+rr)*KD + kc*128 + q*8]);
#pragma unroll
            for (int rr = r; rr < 128; rr += 16)
                cpa16(&Bs[rr*136 + q*8], &Bw[rr*KD + kc*128 + q*8]);
        }
        asm volatile("cp.async.commit_group;\n");
        asm volatile("cp.async.wait_group 0;\n");
        __syncthreads();
#pragma unroll
        for (int ks = 0; ks < 8; ks++) {
            int k0 = ks*16;
            uint32_t a[2][4];
#pragma unroll
            for (int i = 0; i < 2; i++) {
                int mb = wm + i*16;
                a[i][0] = *reinterpret_cast<const uint32_t*>(&As[(mb+g  )*136 + k0+tg  ]);
                a[i][1] = *reinterpret_cast<const uint32_t*>(&As[(mb+8+g)*136 + k0+tg  ]);
                a[i][2] = *reinterpret_cast<const uint32_t*>(&As[(mb+g  )*136 + k0+8+tg]);
                a[i][3] = *reinterpret_cast<const uint32_t*>(&As[(mb+8+g)*136 + k0+8+tg]);
            }
#pragma unroll
            for (int j = 0; j < 4; j++) {
                uint32_t b0 = *reinterpret_cast<const uint32_t*>(&Bs[(wn+j*8+g)*136 + k0+tg  ]);
                uint32_t b1 = *reinterpret_cast<const uint32_t*>(&Bs[(wn+j*8+g)*136 + k0+8+tg]);
                mma16816(acc[0][j], a[0], b0, b1);
                mma16816(acc[1][j], a[1], b0, b1);
            }
        }
        __syncthreads();
    }

    if (epi <= EPI_GELU) {
#pragma unroll
        for (int i = 0; i < 2; i++)
#pragma unroll
        for (int j = 0; j < 4; j++) {
            int n = wn + j*8 + tg;
            float b0 = bias[n], b1 = bias[n+1];
            int r0 = m0 + wm + i*16 + g, r1 = r0 + 8;
            float v0 = acc[i][j][0]+b0, v1 = acc[i][j][1]+b1;
            float v2 = acc[i][j][2]+b0, v3 = acc[i][j][3]+b1;
            if (epi == EPI_GELU) {
                v0 = geluf(v0); v1 = geluf(v1); v2 = geluf(v2); v3 = geluf(v3);
            } else {
                v0 *= scale; v1 *= scale; v2 *= scale; v3 *= scale;
            }
            *reinterpret_cast<uint32_t*>(&oh[r0*ldC + n]) = packh2(v0, v1);
            *reinterpret_cast<uint32_t*>(&oh[r1*ldC + n]) = packh2(v2, v3);
        }
    } else {
        // LN family: fold bias + aux, optional fp32 store, then LN
#pragma unroll
        for (int i = 0; i < 2; i++)
#pragma unroll
        for (int j = 0; j < 4; j++) {
            int n = wn + j*8 + tg;
            int r0 = m0 + wm + i*16 + g, r1 = r0 + 8;
            if (bias) {
                float b0 = bias[n], b1 = bias[n+1];
                acc[i][j][0] += b0; acc[i][j][1] += b1;
                acc[i][j][2] += b0; acc[i][j][3] += b1;
            }
            if (auxh) {
                acc[i][j][0] += __half2float(auxh[r0*D_ + n]);
                acc[i][j][1] += __half2float(auxh[r0*D_ + n+1]);
                acc[i][j][2] += __half2float(auxh[r1*D_ + n]);
                acc[i][j][3] += __half2float(auxh[r1*D_ + n+1]);
            }
            if (aux) {
                if (epi == EPI_SKLN0) {
                    int ba = r0 >> 12, pa = r0 & 4095;
                    int bb_ = r1 >> 12, pb = r1 & 4095;
                    acc[i][j][0] += aux[(ba*D_ + n  )*4096 + pa];
                    acc[i][j][1] += aux[(ba*D_ + n+1)*4096 + pa];
                    acc[i][j][2] += aux[(bb_*D_ + n  )*4096 + pb];
                    acc[i][j][3] += aux[(bb_*D_ + n+1)*4096 + pb];
                } else {
                    acc[i][j][0] += aux[r0*D_ + n];
                    acc[i][j][1] += aux[r0*D_ + n+1];
                    acc[i][j][2] += aux[r1*D_ + n];
                    acc[i][j][3] += aux[r1*D_ + n+1];
                }
            }
            if (of) {
                of[r0*D_ + n]   = acc[i][j][0];
                of[r0*D_ + n+1] = acc[i][j][1];
                of[r1*D_ + n]   = acc[i][j][2];
                of[r1*D_ + n+1] = acc[i][j][3];
            }
        }
        float sum[2][2] = {{0,0},{0,0}}, sq[2][2] = {{0,0},{0,0}};
#pragma unroll
        for (int i = 0; i < 2; i++)
#pragma unroll
        for (int j = 0; j < 4; j++) {
            float a0 = acc[i][j][0], a1 = acc[i][j][1];
            float a2 = acc[i][j][2], a3 = acc[i][j][3];
            sum[i][0] += a0 + a1; sq[i][0] += a0*a0 + a1*a1;
            sum[i][1] += a2 + a3; sq[i][1] += a2*a2 + a3*a3;
        }
#pragma unroll
        for (int o = 1; o <= 2; o <<= 1) {
#pragma unroll
            for (int i = 0; i < 2; i++)
#pragma unroll
            for (int rh = 0; rh < 2; rh++) {
                sum[i][rh] += __shfl_xor_sync(0xffffffffu, sum[i][rh], o);
                sq[i][rh]  += __shfl_xor_sync(0xffffffffu, sq[i][rh], o);
            }
        }
        float* sred = reinterpret_cast<float*>(shh);   // [64][8]
        if ((lane & 3) == 0) {
#pragma unroll
            for (int i = 0; i < 2; i++)
#pragma unroll
            for (int rh = 0; rh < 2; rh++) {
                int row = wm + i*16 + rh*8 + g;
                sred[row*8 + (warp >> 1)*2 + 0] = sum[i][rh];
                sred[row*8 + (warp >> 1)*2 + 1] = sq[i][rh];
            }
        }
        __syncthreads();
#pragma unroll
        for (int i = 0; i < 2; i++)
#pragma unroll
        for (int rh = 0; rh < 2; rh++) {
            int row = wm + i*16 + rh*8 + g;
            float s = sred[row*8+0] + sred[row*8+2] + sred[row*8+4] + sred[row*8+6];
            float qq = sred[row*8+1] + sred[row*8+3] + sred[row*8+5] + sred[row*8+7];
            float mean = s*(1.0f/128.0f);
            float var = fmaxf(qq*(1.0f/128.0f) - mean*mean, 0.f);
            float rstd = rsqrtf(var + 1e-5f);
            if (epi == EPI_FIN) {
                int grow = m0 + row;
                int b = grow >> 12, p = grow & 4095;
#pragma unroll
                for (int j = 0; j < 4; j++) {
                    int n = wn + j*8 + tg;
                    extout[(b*D_ + n  )*4096 + p] =
                        (acc[i][j][rh*2+0]-mean)*rstd*extg[n]   + extbt[n];
                    extout[(b*D_ + n+1)*4096 + p] =
                        (acc[i][j][rh*2+1]-mean)*rstd*extg[n+1] + extbt[n+1];
                }
            } else {
#pragma unroll
                for (int j = 0; j < 4; j++) {
                    int n = wn + j*8 + tg;
                    float v0 = (acc[i][j][rh*2+0]-mean)*rstd;
                    float v1 = (acc[i][j][rh*2+1]-mean)*rstd;
                    *reinterpret_cast<uint32_t*>(&oh[(m0+row)*D_ + n]) = packh2(v0, v1);
                }
            }
        }
    }
}

// ---------------- tensor-core flash attention (fp16 in / fp16 out) -----------
template<int MT, int NW>
__global__ void __launch_bounds__(NW*32) k_attn_mma(int stage) {
    const int NQ = MT*16*NW;
    extern __shared__ __half sha[];
    __half* Qs = sha;                  // [NQ][40]
    __half* Ks = Qs + NQ*40;           // [264][40]
    __half* Vt = Ks + 264*40;          // [32][274]
    int bl = blockIdx.x, hh = blockIdx.y, tid = threadIdx.x;
    int b = bl >> 6, l = bl & 63;
    const __half* qsrc; const __half* ksrc; const __half* vsrc;
    if (stage == 0) { qsrc = g_qh1; ksrc = g_kh1; vsrc = g_vh1; }
    else            { qsrc = g_qh2; ksrc = g_kh2; vsrc = g_vh2; }
    for (int idx = tid; idx < NQ*16; idx += NW*32) {
        int row = idx >> 4, c2 = idx & 15;
        int pix;
        if (stage == 0) {
            int n = row >> 6, ij = row & 63;
            pix = (b*N_+n)*4096 + ((l>>3)*8 + (ij>>3))*64 + (l&7)*8 + (ij&7);
        } else {
            pix = b*4096 + ((l>>3)*8 + (row>>3))*64 + (l&7)*8 + (row&7);
        }
        *reinterpret_cast<uint32_t*>(&Qs[row*40 + 2*c2]) =
            *reinterpret_cast<const uint32_t*>(&qsrc[pix*D_ + hh*32 + 2*c2]);
    }
    for (int idx = tid; idx < NKV*16; idx += NW*32) {
        int kv = idx >> 4, c2 = idx & 15;
        int n = kv/44, f = kv%44, f1 = f/11, f2 = f%11;
        int h, w;
        if (stage == 0) { h = (l>>3)*4 + f1; w = (l&7)*11 + f2; }
        else            { h = f1*8 + (l>>3); w = f2*8 + (l&7); }
        int pix = (b*N_+n)*PIX + h*FW_ + w;
        *reinterpret_cast<uint32_t*>(&Ks[kv*40 + 2*c2]) =
            *reinterpret_cast<const uint32_t*>(&ksrc[pix*D_ + hh*32 + 2*c2]);
    }
    for (int idx = tid; idx < NKV*32; idx += NW*32) {
        int kv = idx >> 5, ch = idx & 31;
        int n = kv/44, f = kv%44, f1 = f/11, f2 = f%11;
        int h, w;
        if (stage == 0) { h = (l>>3)*4 + f1; w = (l&7)*11 + f2; }
        else            { h = f1*8 + (l>>3); w = f2*8 + (l&7); }
        int pix = (b*N_+n)*PIX + h*FW_ + w;
        Vt[ch*274 + kv] = vsrc[pix*D_ + hh*32 + ch];
    }
    for (int idx = tid; idx < 32*10; idx += NW*32) {
        int ch = idx / 10, c = idx % 10;
        Vt[ch*274 + 264 + c] = __half(0.f);
    }
    __syncthreads();

    int warp = tid >> 5, lane = tid & 31;
    int g = lane >> 2, t4 = lane & 3;
    int row0 = warp * MT * 16;

    uint32_t af[MT][2][4];
#pragma unroll
    for (int mt = 0; mt < MT; mt++)
#pragma unroll
        for (int ks = 0; ks < 2; ks++) {
            int r = row0 + mt*16, k0 = ks*16;
            af[mt][ks][0] = *reinterpret_cast<const uint32_t*>(&Qs[(r+g  )*40 + k0 + 2*t4    ]);
            af[mt][ks][1] = *reinterpret_cast<const uint32_t*>(&Qs[(r+8+g)*40 + k0 + 2*t4    ]);
            af[mt][ks][2] = *reinterpret_cast<const uint32_t*>(&Qs[(r+g  )*40 + k0 + 8 + 2*t4]);
            af[mt][ks][3] = *reinterpret_cast<const uint32_t*>(&Qs[(r+8+g)*40 + k0 + 8 + 2*t4]);
        }

    float m[MT][2], lsum[MT][2], O[MT][4][4];
#pragma unroll
    for (int mt = 0; mt < MT; mt++) {
        m[mt][0] = -1e30f; m[mt][1] = -1e30f;
        lsum[mt][0] = 0.f; lsum[mt][1] = 0.f;
#pragma unroll
        for (int j = 0; j < 4; j++)
#pragma unroll
            for (int r = 0; r < 4; r++) O[mt][j][r] = 0.f;
    }

    for (int c = 0; c < 17; c++) {
        int kv0 = c*16;
        int nt = (c == 16) ? 1 : 2;
        uint32_t bf[2][2][2];
#pragma unroll
        for (int n = 0; n < 2; n++) {
            if (n < nt) {
#pragma unroll
                for (int ks = 0; ks < 2; ks++) {
                    bf[n][ks][0] = *reinterpret_cast<const uint32_t*>(&Ks[(kv0+n*8+g)*40 + ks*16 + 2*t4    ]);
                    bf[n][ks][1] = *reinterpret_cast<const uint32_t*>(&Ks[(kv0+n*8+g)*40 + ks*16 + 8 + 2*t4]);
                }
            }
        }
        float S[MT][2][4];
#pragma unroll
        for (int mt = 0; mt < MT; mt++)
#pragma unroll
            for (int n = 0; n < 2; n++)
#pragma unroll
                for (int r = 0; r < 4; r++) S[mt][n][r] = 0.f;
#pragma unroll
        for (int mt = 0; mt < MT; mt++)
#pragma unroll
            for (int n = 0; n < 2; n++) {
                if (n < nt) {
                    mma16816(S[mt][n], af[mt][0], bf[n][0][0], bf[n][0][1]);
                    mma16816(S[mt][n], af[mt][1], bf[n][1][0], bf[n][1][1]);
                }
            }
#pragma unroll
        for (int mt = 0; mt < MT; mt++) {
            float mx0 = fmaxf(S[mt][0][0], S[mt][0][1]);
            float mx8 = fmaxf(S[mt][0][2], S[mt][0][3]);
            if (nt == 2) {
                mx0 = fmaxf(mx0, fmaxf(S[mt][1][0], S[mt][1][1]));
                mx8 = fmaxf(mx8, fmaxf(S[mt][1][2], S[mt][1][3]));
            }
            mx0 = fmaxf(mx0, __shfl_xor_sync(0xffffffffu, mx0, 1));
            mx0 = fmaxf(mx0, __shfl_xor_sync(0xffffffffu, mx0, 2));
            mx8 = fmaxf(mx8, __shfl_xor_sync(0xffffffffu, mx8, 1));
            mx8 = fmaxf(mx8, __shfl_xor_sync(0xffffffffu, mx8, 2));
            float mn0 = fmaxf(m[mt][0], mx0), mn8 = fmaxf(m[mt][1], mx8);
            float cr0 = __expf(m[mt][0] - mn0), cr8 = __expf(m[mt][1] - mn8);
            m[mt][0] = mn0; m[mt][1] = mn8;
            uint32_t pa[4];
            float p00 = __expf(S[mt][0][0] - mn0), p01 = __expf(S[mt][0][1] - mn0);
            float p02 = __expf(S[mt][0][2] - mn8), p03 = __expf(S[mt][0][3] - mn8);
            float rs0 = p00 + p01, rs8 = p02 + p03;
            pa[0] = packh2(p00, p01);
            pa[1] = packh2(p02, p03);
            if (nt == 2) {
                float p10 = __expf(S[mt][1][0] - mn0), p11 = __expf(S[mt][1][1] - mn0);
                float p12 = __expf(S[mt][1][2] - mn8), p13 = __expf(S[mt][1][3] - mn8);
                rs0 += p10 + p11; rs8 += p12 + p13;
                pa[2] = packh2(p10, p11);
                pa[3] = packh2(p12, p13);
            } else { pa[2] = 0u; pa[3] = 0u; }
            rs0 += __shfl_xor_sync(0xffffffffu, rs0, 1);
            rs0 += __shfl_xor_sync(0xffffffffu, rs0, 2);
            rs8 += __shfl_xor_sync(0xffffffffu, rs8, 1);
            rs8 += __shfl_xor_sync(0xffffffffu, rs8, 2);
            lsum[mt][0] = lsum[mt][0]*cr0 + rs0;
            lsum[mt][1] = lsum[mt][1]*cr8 + rs8;
#pragma unroll
            for (int j = 0; j < 4; j++) {
                O[mt][j][0] *= cr0; O[mt][j][1] *= cr0;
                O[mt][j][2] *= cr8; O[mt][j][3] *= cr8;
                uint32_t vb0 = *reinterpret_cast<const uint32_t*>(&Vt[(j*8+g)*274 + kv0 + 2*t4    ]);
                uint32_t vb1 = *reinterpret_cast<const uint32_t*>(&Vt[(j*8+g)*274 + kv0 + 8 + 2*t4]);
                mma16816(O[mt][j], pa, vb0, vb1);
            }
        }
    }
#pragma unroll
    for (int mt = 0; mt < MT; mt++) {
        float i0 = 1.0f / lsum[mt][0], i8 = 1.0f / lsum[mt][1];
        int r0 = row0 + mt*16 + g;
        int r1 = r0 + 8;
        int out0, out1;
        if (stage == 0) {
            out0 = bl*NQ + r0;
            out1 = bl*NQ + r1;
        } else {
            out0 = b*4096 + ((l>>3)*8 + (r0>>3))*64 + (l&7)*8 + (r0&7);
            out1 = b*4096 + ((l>>3)*8 + (r1>>3))*64 + (l&7)*8 + (r1&7);
        }
        __half* Od = (stage == 0) ? g_otok : g_o2;
#pragma unroll
        for (int j = 0; j < 4; j++) {
            int chn = hh*32 + j*8 + 2*t4;
            *reinterpret_cast<uint32_t*>(&Od[out0*D_ + chn]) = packh2(O[mt][j][0]*i0, O[mt][j][1]*i0);
            *reinterpret_cast<uint32_t*>(&Od[out1*D_ + chn]) = packh2(O[mt][j][2]*i8, O[mt][j][3]*i8);
        }
    }
}

// ---------------------------------------------------------------------------
extern "C" void kernel_launch(void* const* d_in, const int* in_sizes, int n_in,
                              void* d_out, int out_size) {
    (void)in_sizes; (void)n_in; (void)out_size;
    const float* x        = (const float*)d_in[1];
    const float* grid     = (const float*)d_in[2];
    const float* feature  = (const float*)d_in[3];
    const float* I_inv    = (const float*)d_in[4];
    const float* E_inv    = (const float*)d_in[5];
    const float* bn_fl_g  = (const float*)d_in[6];
    const float* bn_fl_b  = (const float*)d_in[7];
    const float* W_fl     = (const float*)d_in[8];
    const float* bn_fp_g  = (const float*)d_in[9];
    const float* bn_fp_b  = (const float*)d_in[10];
    const float* W_fp     = (const float*)d_in[11];
    const float* W_bev    = (const float*)d_in[12];
    const float* b_bev    = (const float*)d_in[13];
    const float* W_img    = (const float*)d_in[14];
    const float* W_cam    = (const float*)d_in[15];
    const float* aln_g    = (const float*)d_in[16];
    const float* aln_b    = (const float*)d_in[17];
    const float* aWqkv    = (const float*)d_in[18];
    const float* abqkv    = (const float*)d_in[19];
    const float* aWp      = (const float*)d_in[20];
    const float* abp      = (const float*)d_in[21];
    const float* pn_g     = (const float*)d_in[22];
    const float* pn_b     = (const float*)d_in[23];
    const float* Wma      = (const float*)d_in[24];
    const float* bma      = (const float*)d_in[25];
    const float* Wmb      = (const float*)d_in[26];
    const float* bmb      = (const float*)d_in[27];
    const float* post_g   = (const float*)d_in[28];
    const float* post_b   = (const float*)d_in[29];
    float* out = (float*)d_out;

    const int GSM = (64*136 + 128*136) * 2;  // 52224
    const int PSM = 2*128*33*4 + 32*128*4;   // 50176
    const int A1SM = (384*40 + 264*40 + 32*274) * 2;
    const int A2SM = (64*40 + 264*40 + 32*274) * 2;
    cudaFuncSetAttribute(k_prep, cudaFuncAttributeMaxDynamicSharedMemorySize, PSM);
    cudaFuncSetAttribute(k_gemm_ep<1>, cudaFuncAttributeMaxDynamicSharedMemorySize, GSM);
    cudaFuncSetAttribute(k_gemm_ep<2>, cudaFuncAttributeMaxDynamicSharedMemorySize, GSM);
    cudaFuncSetAttribute(k_attn_mma<3,8>, cudaFuncAttributeMaxDynamicSharedMemorySize, A1SM);
    cudaFuncSetAttribute(k_attn_mma<1,4>, cudaFuncAttributeMaxDynamicSharedMemorySize, A2SM);

    // prep (weights + activations)
    k_wprep<<<304, 256>>>(aln_g, aln_b, aWqkv, abqkv, pn_g, pn_b, Wma, bma,
                          aWp, Wmb, W_fp, W_fl);
    k_prep<<<B_*N_*88, 128, PSM>>>(feature, I_inv, E_inv, W_img, W_cam,
                                   bn_fp_g, bn_fp_b, bn_fl_g, bn_fl_b);
    k_query<<<NQP/8, 256>>>(grid, x, W_bev, b_bev, E_inv, W_cam);

    // conv GEMMs (jobs 0,1) then all 5 QKV projections (jobs 2..6)
    k_gemm_ep<1><<<1056, 256, GSM>>>(100, nullptr, nullptr, nullptr, nullptr, nullptr);
    k_gemm_ep<1><<<2880, 256, GSM>>>(101, nullptr, nullptr, nullptr, nullptr, nullptr);

    // stage 1
    k_attn_mma<3,8><<<dim3(B_*64, 4), 256, A1SM>>>(0);
    k_gemm_ep<1><<<128, 256, GSM>>>(7, abp, nullptr, nullptr, x, nullptr);      // mean+proj+skip+LN
    k_gemm_ep<1><<<256, 256, GSM>>>(102, nullptr, nullptr, nullptr, nullptr, nullptr);  // gelu a,b
    k_gemm_ep<2><<<128, 256, GSM>>>(10, bmb, nullptr, nullptr, nullptr, nullptr);       // res+LN -> xq1

    // stage 2
    k_gemm_ep<1><<<128, 256, GSM>>>(11, nullptr, nullptr, nullptr, nullptr, nullptr);   // Q2
    k_attn_mma<1,4><<<dim3(B_*64, 4), 128, A2SM>>>(1);
    k_gemm_ep<1><<<128, 256, GSM>>>(12, abp + 128, nullptr, nullptr, nullptr, nullptr); // proj+skip+LN
    k_gemm_ep<1><<<256, 256, GSM>>>(103, nullptr, nullptr, nullptr, nullptr, nullptr);  // gelu a,b
    k_gemm_ep<2><<<128, 256, GSM>>>(15, bmb + 128, post_g, post_b, nullptr, out);       // res+finalLN
}